// round 7
// baseline (speedup 1.0000x reference)
#include <cuda_runtime.h>
#include <cstdint>

#define NB 4
#define NX 64
#define NY 64
#define NZ 40
#define C  32
#define KM 16
#define KZM 16
#define KYM 32

// ================= compile-time trig ======
constexpr double D_PI = 3.141592653589793238462643383279502884;

constexpr double tsin_(double x) {
    double x2 = x * x, t = x, s = x;
    for (int n = 1; n <= 13; n++) { t *= -x2 / ((2.0*n) * (2.0*n + 1.0)); s += t; }
    return s;
}
constexpr double tcos_(double x) {
    double x2 = x * x, t = 1.0, s = 1.0;
    for (int n = 1; n <= 13; n++) { t *= -x2 / ((2.0*n - 1.0) * (2.0*n)); s += t; }
    return s;
}
constexpr double ang_(int m, int N) {
    int mm = m % N;
    if (mm > N / 2) mm -= N;
    return 2.0 * D_PI * mm / N;
}

struct FXT { float c[16][64]; float s[16][64]; };
constexpr FXT mkFX() {
    FXT t{};
    for (int k = 0; k < 16; k++)
        for (int n = 0; n < 64; n++) {
            double a = ang_(k * n, 64);
            t.c[k][n] = (float)tcos_(a);
            t.s[k][n] = (float)(-tsin_(a));
        }
    return t;
}
__device__ constexpr FXT FX = mkFX();

struct FZT { float c[16][40]; float s[16][40]; };
constexpr FZT mkFZ() {
    FZT t{};
    for (int k = 0; k < 16; k++) {
        int f = (k < 8) ? k : k + 5;
        for (int n = 0; n < 40; n++) {
            double a = ang_(f * n, 40);
            t.c[k][n] = (float)tcos_(a);
            t.s[k][n] = (float)(-tsin_(a));
        }
    }
    return t;
}
__device__ constexpr FZT FZ = mkFZ();

struct FYT { float c[32][64]; float s[32][64]; };
constexpr FYT mkFY() {
    FYT t{};
    for (int k = 0; k < 32; k++) {
        int f = (k < 16) ? k : k + 1;
        for (int n = 0; n < 64; n++) {
            double a = ang_(f * n, 64);
            t.c[k][n] = (float)tcos_(a);
            t.s[k][n] = (float)(-tsin_(a));
        }
    }
    return t;
}
__device__ constexpr FYT FY = mkFY();

struct IXT { float c[16][64]; float s[16][64]; };
constexpr IXT mkIX() {
    IXT t{};
    for (int k = 0; k < 16; k++)
        for (int n = 0; n < 64; n++) {
            double a = ang_(k * n, 64);
            t.c[k][n] = (float)(tcos_(a) / 64.0);
            t.s[k][n] = (float)(tsin_(a) / 64.0);
        }
    return t;
}
__device__ constexpr IXT IX = mkIX();

struct IZT { float c[16][40]; float s[16][40]; };
constexpr IZT mkIZ() {
    IZT t{};
    for (int k = 0; k < 16; k++) {
        int f = (k < 8) ? k : k + 5;
        double w = (f == 0 || f == 20) ? 1.0 : 2.0;
        for (int n = 0; n < 40; n++) {
            double a = ang_(f * n, 40);
            t.c[k][n] = (float)(tcos_(a) * w / 40.0);
            t.s[k][n] = (float)(tsin_(a) * w / 40.0);
        }
    }
    return t;
}
__device__ constexpr IZT IZ = mkIZ();

struct IYT { float c[32][64]; float s[32][64]; };
constexpr IYT mkIY() {
    IYT t{};
    for (int k = 0; k < 32; k++) {
        int f = (k < 16) ? k : k + 1;
        double w = (f == 0 || f == 32) ? 1.0 : 2.0;
        for (int n = 0; n < 64; n++) {
            double a = ang_(f * n, 64);
            t.c[k][n] = (float)(tcos_(a) * w / 64.0);
            t.s[k][n] = (float)(tsin_(a) * w / 64.0);
        }
    }
    return t;
}
__device__ constexpr IYT IY = mkIY();

// ================= scratch =================
__device__ float2 g_Qx[(size_t)NB*KM*NY*NZ*C];    // [b][kx][y][z][i]
__device__ float2 g_P1[(size_t)NB*NX*NY*KZM*C];   // [b][x][y][kz][i]
__device__ float2 g_F [(size_t)512*160*C];        // [mode][row][c]
__device__ float2 g_R [(size_t)NB*64*NZ*KM*C];    // [b][u][pos][k][o]
__device__ float  g_acc[(size_t)NB*NX*NY*NZ*C];   // [b][x][y][z][o]

// ================= 1x1 conv (init acc) =================
__global__ void __launch_bounds__(640) k_conv(const float* __restrict__ x,
                                              const float* __restrict__ w,
                                              const float* __restrict__ bias) {
    __shared__ float xs[NZ*C];
    __shared__ float Wt[C*C];
    __shared__ float bs[C];
    int y = blockIdx.x, xx = blockIdx.y, b = blockIdx.z;
    int tid = threadIdx.x;
    const float* xr = x + (((size_t)(b*NX+xx)*NY + y) * NZ) * C;
    for (int t = tid; t < NZ*C; t += 640) xs[t] = xr[t];
    for (int t = tid; t < C*C;  t += 640) Wt[t] = w[(t % C) * C + (t / C)];
    if (tid < C) bs[tid] = bias[tid];
    __syncthreads();
    int o = tid & 31, zz = tid >> 5;
    float* ar = g_acc + (((size_t)(b*NX+xx)*NY + y) * NZ) * C;
    for (int rep = 0; rep < 2; rep++) {
        int z = zz + rep * 20;
        float v = bs[o];
        #pragma unroll
        for (int i = 0; i < C; i++) v += xs[z*C + i] * Wt[i*C + o];
        ar[z*C + o] = v;
    }
}

// ================= forward x DFT (all 16 modes) ============================
__global__ void __launch_bounds__(256) k_fftx16(const float* __restrict__ x) {
    int w = threadIdx.x >> 5, i = threadIdx.x & 31;
    int z = blockIdx.x * 8 + w;
    int y = blockIdx.y, b = blockIdx.z;
    const float* px = x + (((size_t)b*NX*NY + y)*NZ + z)*C + i;
    float2 acc[16];
    #pragma unroll
    for (int k = 0; k < 16; k++) acc[k] = make_float2(0.f, 0.f);
    #pragma unroll
    for (int xx = 0; xx < NX; xx++) {
        float v = px[(size_t)xx*NY*NZ*C];
        #pragma unroll
        for (int k = 0; k < 16; k++) {
            acc[k].x = fmaf(v, FX.c[k][xx], acc[k].x);
            acc[k].y = fmaf(v, FX.s[k][xx], acc[k].y);
        }
    }
    #pragma unroll
    for (int k = 0; k < 16; k++)
        g_Qx[((((size_t)b*KM + k)*NY + y)*NZ + z)*C + i] = acc[k];
}

// ================= forward z rDFT (16 modes) ================================
__global__ void __launch_bounds__(256) k_rfftz(const float* __restrict__ x) {
    int w = threadIdx.x >> 5, i = threadIdx.x & 31;
    int y = blockIdx.x * 8 + w;
    int xx = blockIdx.y, b = blockIdx.z;
    const float* px = x + (((size_t)(b*NX+xx)*NY + y) * NZ) * C + i;
    float2 acc[16];
    #pragma unroll
    for (int k = 0; k < 16; k++) acc[k] = make_float2(0.f, 0.f);
    #pragma unroll
    for (int z = 0; z < NZ; z++) {
        float v = px[(size_t)z*C];
        #pragma unroll
        for (int k = 0; k < 16; k++) {
            acc[k].x = fmaf(v, FZ.c[k][z], acc[k].x);
            acc[k].y = fmaf(v, FZ.s[k][z], acc[k].y);
        }
    }
    float2* q = g_P1 + (((size_t)(b*NX+xx)*NY + y) * KZM) * C + i;
    #pragma unroll
    for (int k = 0; k < 16; k++) q[(size_t)k*C] = acc[k];
}

// ================= xz: z DFT of Qx (all 16 kz modes) ========================
__global__ void __launch_bounds__(256) k_zfftQ16() {
    int w = threadIdx.x >> 5, i = threadIdx.x & 31;
    int y = blockIdx.x * 8 + w;
    int kx = blockIdx.y, b = blockIdx.z;
    const float2* q = g_Qx + (((size_t)(b*KM+kx)*NY + y) * NZ) * C + i;
    float2 acc[16];
    #pragma unroll
    for (int k = 0; k < 16; k++) acc[k] = make_float2(0.f, 0.f);
    #pragma unroll
    for (int z = 0; z < NZ; z++) {
        float2 a = q[(size_t)z*C];
        #pragma unroll
        for (int k = 0; k < 16; k++) {
            float cc = FZ.c[k][z], ss = FZ.s[k][z];
            acc[k].x = fmaf(a.x, cc, acc[k].x);
            acc[k].x = fmaf(a.y, -ss, acc[k].x);
            acc[k].y = fmaf(a.x, ss, acc[k].y);
            acc[k].y = fmaf(a.y, cc, acc[k].y);
        }
    }
    #pragma unroll
    for (int k = 0; k < 16; k++) {
        int m = kx*KZM + k;
        g_F[((size_t)m*(NB*NY) + b*NY + y)*C + i] = acc[k];
    }
}

// ================= xy: y DFT (real axis, 16 of 32 modes from M0) ============
template<int M0>
__global__ void __launch_bounds__(256) k_yfftQ16() {
    int w = threadIdx.x >> 5, i = threadIdx.x & 31;
    int z = blockIdx.x * 8 + w;
    int kx = blockIdx.y, b = blockIdx.z;
    const float2* q = g_Qx + (((size_t)(b*KM+kx)*NY) * NZ + z) * C + i;
    float2 acc[16];
    #pragma unroll
    for (int k = 0; k < 16; k++) acc[k] = make_float2(0.f, 0.f);
    #pragma unroll
    for (int y = 0; y < NY; y++) {
        float2 a = q[(size_t)y*NZ*C];
        #pragma unroll
        for (int k = 0; k < 16; k++) {
            float cc = FY.c[M0+k][y], ss = FY.s[M0+k][y];
            acc[k].x = fmaf(a.x, cc, acc[k].x);
            acc[k].x = fmaf(a.y, -ss, acc[k].x);
            acc[k].y = fmaf(a.x, ss, acc[k].y);
            acc[k].y = fmaf(a.y, cc, acc[k].y);
        }
    }
    #pragma unroll
    for (int k = 0; k < 16; k++) {
        int m = kx*KYM + M0 + k;
        g_F[((size_t)m*(NB*NZ) + b*NZ + z)*C + i] = acc[k];
    }
}

// ================= yz: y DFT of P1 (all 16 complex modes) ===================
__global__ void __launch_bounds__(256) k_yfftP16() {
    int w = threadIdx.x >> 5, i = threadIdx.x & 31;
    int kz = blockIdx.x * 8 + w;
    int xx = blockIdx.y, b = blockIdx.z;
    const float2* p = g_P1 + (((size_t)(b*NX+xx)*NY) * KZM + kz) * C + i;
    float2 acc[16];
    #pragma unroll
    for (int k = 0; k < 16; k++) acc[k] = make_float2(0.f, 0.f);
    #pragma unroll
    for (int y = 0; y < NY; y++) {
        float2 a = p[(size_t)y*KZM*C];
        #pragma unroll
        for (int k = 0; k < 16; k++) {
            float cc = FX.c[k][y], ss = FX.s[k][y];
            acc[k].x = fmaf(a.x, cc, acc[k].x);
            acc[k].x = fmaf(a.y, -ss, acc[k].x);
            acc[k].y = fmaf(a.x, ss, acc[k].y);
            acc[k].y = fmaf(a.y, cc, acc[k].y);
        }
    }
    #pragma unroll
    for (int k = 0; k < 16; k++) {
        int m = k*KZM + kz;
        g_F[((size_t)m*(NB*NX) + b*NX + xx)*C + i] = acc[k];
    }
}

// ================= per-mode complex 32x32 mix: weights-in-regs + shfl =======
// grid (modes, rows/32), block 256 (8 warps x 4 rows)
template<int D>
__global__ void __launch_bounds__(256) k_mix2(const float* __restrict__ fw,
                                              const float* __restrict__ fw2,
                                              int rows) {
    int m = blockIdx.x, chunk = blockIdx.y;
    int o = threadIdx.x & 31, w = threadIdx.x >> 5;
    int mpx = 2 * D;
    int kx = m / mpx, km = m % mpx;
    const float* W = (km < D) ? fw : fw2;
    int kk = (km < D) ? km : km - D;
    float wre[32], wim[32];
    #pragma unroll
    for (int i = 0; i < 32; i++) {
        size_t base = ((((size_t)i*C + o)*KM + kx)*D + kk) * 2;
        wre[i] = W[base]; wim[i] = W[base + 1];
    }
    int row0 = chunk * 32 + w * 4;
    float2* Fp = g_F + (size_t)m*rows*C;
    float2 f[4], acc[4];
    #pragma unroll
    for (int r = 0; r < 4; r++) {
        f[r] = Fp[(size_t)(row0 + r)*C + o];
        acc[r] = make_float2(0.f, 0.f);
    }
    #pragma unroll
    for (int i = 0; i < 32; i++) {
        #pragma unroll
        for (int r = 0; r < 4; r++) {
            float ar = __shfl_sync(0xffffffffu, f[r].x, i);
            float ai = __shfl_sync(0xffffffffu, f[r].y, i);
            acc[r].x = fmaf(ar, wre[i], acc[r].x);
            acc[r].x = fmaf(ai, -wim[i], acc[r].x);
            acc[r].y = fmaf(ar, wim[i], acc[r].y);
            acc[r].y = fmaf(ai, wre[i], acc[r].y);
        }
    }
    #pragma unroll
    for (int r = 0; r < 4; r++)
        Fp[(size_t)(row0 + r)*C + o] = acc[r];
}

// ================= inverse over z (16 modes -> 40 z) ========================
template<int Z0>
__device__ __forceinline__ void invZ_body(int b, int kc, int u, int o) {
    float2 acc[8];
    #pragma unroll
    for (int j = 0; j < 8; j++) acc[j] = make_float2(0.f, 0.f);
    #pragma unroll
    for (int kz = 0; kz < KZM; kz++) {
        float2 g = g_F[((size_t)(kc*KZM + kz)*(NB*64) + b*64 + u)*C + o];
        #pragma unroll
        for (int j = 0; j < 8; j++) {
            float cc = IZ.c[kz][Z0+j], ss = IZ.s[kz][Z0+j];
            acc[j].x = fmaf(g.x, cc, acc[j].x);
            acc[j].x = fmaf(g.y, -ss, acc[j].x);
            acc[j].y = fmaf(g.x, ss, acc[j].y);
            acc[j].y = fmaf(g.y, cc, acc[j].y);
        }
    }
    #pragma unroll
    for (int j = 0; j < 8; j++)
        g_R[(((size_t)(b*64 + u)*NZ + Z0 + j)*KM + kc)*C + o] = acc[j];
}
__global__ void __launch_bounds__(320) k_invZ() {
    int w = threadIdx.x >> 5, o = threadIdx.x & 31;
    int u = blockIdx.x * 2 + (w / 5);
    int slot = w % 5;
    int kc = blockIdx.y, b = blockIdx.z;
    switch (slot) {
        case 0: invZ_body<0 >(b, kc, u, o); break;
        case 1: invZ_body<8 >(b, kc, u, o); break;
        case 2: invZ_body<16>(b, kc, u, o); break;
        case 3: invZ_body<24>(b, kc, u, o); break;
        default: invZ_body<32>(b, kc, u, o); break;
    }
}

// ================= inverse over y real axis (32 modes -> 64 y), xy ==========
template<int Y0>
__device__ __forceinline__ void invY_body(int b, int kx, int z, int o) {
    float2 acc[8];
    #pragma unroll
    for (int j = 0; j < 8; j++) acc[j] = make_float2(0.f, 0.f);
    #pragma unroll
    for (int ky = 0; ky < KYM; ky++) {
        float2 g = g_F[((size_t)(kx*KYM + ky)*(NB*NZ) + b*NZ + z)*C + o];
        #pragma unroll
        for (int j = 0; j < 8; j++) {
            float cc = IY.c[ky][Y0+j], ss = IY.s[ky][Y0+j];
            acc[j].x = fmaf(g.x, cc, acc[j].x);
            acc[j].x = fmaf(g.y, -ss, acc[j].x);
            acc[j].y = fmaf(g.x, ss, acc[j].y);
            acc[j].y = fmaf(g.y, cc, acc[j].y);
        }
    }
    #pragma unroll
    for (int j = 0; j < 8; j++)
        g_R[(((size_t)(b*NZ + z)*NY + Y0 + j)*KM + kx)*C + o] = acc[j];
}
__global__ void __launch_bounds__(512) k_invY() {
    int w = threadIdx.x >> 5, o = threadIdx.x & 31;
    int z = blockIdx.x * 2 + (w >> 3);
    int slot = w & 7;
    int kx = blockIdx.y, b = blockIdx.z;
    switch (slot) {
        case 0: invY_body<0 >(b, kx, z, o); break;
        case 1: invY_body<8 >(b, kx, z, o); break;
        case 2: invY_body<16>(b, kx, z, o); break;
        case 3: invY_body<24>(b, kx, z, o); break;
        case 4: invY_body<32>(b, kx, z, o); break;
        case 5: invY_body<40>(b, kx, z, o); break;
        case 6: invY_body<48>(b, kx, z, o); break;
        default: invY_body<56>(b, kx, z, o); break;
    }
}

// ================= inverse complex axis (16 modes -> 64), Re(), += ==========
template<int N0>
__device__ __forceinline__ void invAcc_body(size_t rrow, size_t obase, size_t ostride, int o) {
    float acc[8];
    #pragma unroll
    for (int j = 0; j < 8; j++) acc[j] = 0.f;
    #pragma unroll
    for (int k = 0; k < KM; k++) {
        float2 r = g_R[rrow*(KM*C) + (size_t)k*C + o];
        #pragma unroll
        for (int j = 0; j < 8; j++) {
            acc[j] = fmaf(r.x, IX.c[k][N0+j], acc[j]);
            acc[j] = fmaf(r.y, -IX.s[k][N0+j], acc[j]);
        }
    }
    #pragma unroll
    for (int j = 0; j < 8; j++)
        g_acc[obase + (size_t)(N0+j)*ostride + o] += acc[j];
}
template<int BR>
__global__ void __launch_bounds__(512) k_invAcc() {
    int w = threadIdx.x >> 5, o = threadIdx.x & 31;
    int r = w >> 3, slot = w & 7;
    int b = blockIdx.z;
    size_t rrow, obase, ostride;
    if (BR == 0) {            // xz
        int z = blockIdx.x, y = blockIdx.y*2 + r;
        rrow = ((size_t)(b*NY + y))*NZ + z;
        obase = (((size_t)b*NX*NY + y)*NZ + z)*C;
        ostride = (size_t)NY*NZ*C;
    } else if (BR == 1) {     // yz
        int z = blockIdx.x, xx = blockIdx.y*2 + r;
        rrow = ((size_t)(b*NX + xx))*NZ + z;
        obase = (((size_t)(b*NX + xx)*NY)*NZ + z)*C;
        ostride = (size_t)NZ*C;
    } else {                  // xy
        int y = blockIdx.x, z = blockIdx.y*2 + r;
        rrow = ((size_t)(b*NZ + z))*NY + y;
        obase = (((size_t)b*NX*NY + y)*NZ + z)*C;
        ostride = (size_t)NY*NZ*C;
    }
    switch (slot) {
        case 0: invAcc_body<0 >(rrow, obase, ostride, o); break;
        case 1: invAcc_body<8 >(rrow, obase, ostride, o); break;
        case 2: invAcc_body<16>(rrow, obase, ostride, o); break;
        case 3: invAcc_body<24>(rrow, obase, ostride, o); break;
        case 4: invAcc_body<32>(rrow, obase, ostride, o); break;
        case 5: invAcc_body<40>(rrow, obase, ostride, o); break;
        case 6: invAcc_body<48>(rrow, obase, ostride, o); break;
        default: invAcc_body<56>(rrow, obase, ostride, o); break;
    }
}

// ================= feedforward =================
__global__ void __launch_bounds__(256) k_ff(const float* __restrict__ w0,
                                            const float* __restrict__ b0,
                                            const float* __restrict__ w1,
                                            const float* __restrict__ b1,
                                            float* __restrict__ out) {
    __shared__ float w0t[C*64];
    __shared__ float w1t[64*C];
    __shared__ float b0s[64], b1s[C];
    __shared__ float as[8][C];
    __shared__ float h1s[8][64];
    int tid = threadIdx.x;
    for (int t = tid; t < C*64; t += 256) { int i = t / 64, h = t % 64; w0t[t] = w0[h*C + i]; }
    for (int t = tid; t < 64*C; t += 256) { int h = t / C,  o = t % C;  w1t[t] = w1[o*64 + h]; }
    if (tid < 64) b0s[tid] = b0[tid];
    if (tid < C)  b1s[tid] = b1[tid];
    __syncthreads();
    int lane = tid & 31, w = tid >> 5;
    const int TPW = 32;
    size_t t0 = ((size_t)blockIdx.x * 8 + w) * TPW;
    for (int j = 0; j < TPW; j++) {
        size_t t = t0 + j;
        as[w][lane] = g_acc[t*C + lane];
        __syncwarp();
        float h1a = b0s[lane], h1b = b0s[lane + 32];
        #pragma unroll
        for (int i = 0; i < C; i++) {
            float a = as[w][i];
            h1a += a * w0t[i*64 + lane];
            h1b += a * w0t[i*64 + lane + 32];
        }
        h1a = fmaxf(h1a, 0.f); h1b = fmaxf(h1b, 0.f);
        h1s[w][lane] = h1a; h1s[w][lane + 32] = h1b;
        __syncwarp();
        float v = b1s[lane];
        #pragma unroll
        for (int h = 0; h < 64; h++) v += h1s[w][h] * w1t[h*C + lane];
        out[t*C + lane] = v;
        __syncwarp();
    }
}

extern "C" void kernel_launch(void* const* d_in, const int* in_sizes, int n_in,
                              void* d_out, int out_size) {
    const float* x      = (const float*)d_in[0];
    const float* w      = (const float*)d_in[1];
    const float* wb     = (const float*)d_in[2];
    const float* fw_xy  = (const float*)d_in[3];
    const float* fw_yz  = (const float*)d_in[4];
    const float* fw_xz  = (const float*)d_in[5];
    const float* fw2_xy = (const float*)d_in[6];
    const float* fw2_yz = (const float*)d_in[7];
    const float* fw2_xz = (const float*)d_in[8];
    const float* ffw0   = (const float*)d_in[9];
    const float* ffb0   = (const float*)d_in[10];
    const float* ffw1   = (const float*)d_in[11];
    const float* ffb1   = (const float*)d_in[12];
    float* out = (float*)d_out;

    k_conv<<<dim3(NY, NX, NB), 640>>>(x, w, wb);

    // shared forward x-DFT (feeds xz + xy)
    k_fftx16<<<dim3(5, NY, NB), 256>>>(x);

    // ---- xz branch ----
    k_zfftQ16<<<dim3(8, KM, NB), 256>>>();
    k_mix2<8><<<dim3(256, 8), 256>>>(fw_xz, fw2_xz, NB*NY);
    k_invZ<<<dim3(32, KM, NB), 320>>>();
    k_invAcc<0><<<dim3(NZ, NY/2, NB), 512>>>();

    // ---- xy branch ----
    k_yfftQ16<0 ><<<dim3(5, KM, NB), 256>>>();
    k_yfftQ16<16><<<dim3(5, KM, NB), 256>>>();
    k_mix2<16><<<dim3(512, 5), 256>>>(fw_xy, fw2_xy, NB*NZ);
    k_invY<<<dim3(20, KM, NB), 512>>>();
    k_invAcc<2><<<dim3(NY, NZ/2, NB), 512>>>();

    // ---- yz branch ----
    k_rfftz<<<dim3(8, NX, NB), 256>>>(x);
    k_yfftP16<<<dim3(2, NX, NB), 256>>>();
    k_mix2<8><<<dim3(256, 8), 256>>>(fw_yz, fw2_yz, NB*NX);
    k_invZ<<<dim3(32, KM, NB), 320>>>();
    k_invAcc<1><<<dim3(NZ, NX/2, NB), 512>>>();

    // ---- feedforward ----
    k_ff<<<2560, 256>>>(ffw0, ffb0, ffw1, ffb1, out);
}

// round 8
// speedup vs baseline: 1.7964x; 1.7964x over previous
#include <cuda_runtime.h>
#include <cstdint>

#define NB 4
#define NX 64
#define NY 64
#define NZ 40
#define C  32
#define KM 16
#define KZM 16
#define KYM 32

// ================= compile-time trig ======
constexpr double D_PI = 3.141592653589793238462643383279502884;

constexpr double tsin_(double x) {
    double x2 = x * x, t = x, s = x;
    for (int n = 1; n <= 13; n++) { t *= -x2 / ((2.0*n) * (2.0*n + 1.0)); s += t; }
    return s;
}
constexpr double tcos_(double x) {
    double x2 = x * x, t = 1.0, s = 1.0;
    for (int n = 1; n <= 13; n++) { t *= -x2 / ((2.0*n - 1.0) * (2.0*n)); s += t; }
    return s;
}
constexpr double ang_(int m, int N) {
    int mm = m % N;
    if (mm > N / 2) mm -= N;
    return 2.0 * D_PI * mm / N;
}

struct FXT { float c[16][64]; float s[16][64]; };
constexpr FXT mkFX() {
    FXT t{};
    for (int k = 0; k < 16; k++)
        for (int n = 0; n < 64; n++) {
            double a = ang_(k * n, 64);
            t.c[k][n] = (float)tcos_(a);
            t.s[k][n] = (float)(-tsin_(a));
        }
    return t;
}
__device__ constexpr FXT FX = mkFX();

struct FZT { float c[16][40]; float s[16][40]; };
constexpr FZT mkFZ() {
    FZT t{};
    for (int k = 0; k < 16; k++) {
        int f = (k < 8) ? k : k + 5;
        for (int n = 0; n < 40; n++) {
            double a = ang_(f * n, 40);
            t.c[k][n] = (float)tcos_(a);
            t.s[k][n] = (float)(-tsin_(a));
        }
    }
    return t;
}
__device__ constexpr FZT FZ = mkFZ();

struct FYT { float c[32][64]; float s[32][64]; };
constexpr FYT mkFY() {
    FYT t{};
    for (int k = 0; k < 32; k++) {
        int f = (k < 16) ? k : k + 1;
        for (int n = 0; n < 64; n++) {
            double a = ang_(f * n, 64);
            t.c[k][n] = (float)tcos_(a);
            t.s[k][n] = (float)(-tsin_(a));
        }
    }
    return t;
}
__device__ constexpr FYT FY = mkFY();

struct IXT { float c[16][64]; float s[16][64]; };
constexpr IXT mkIX() {
    IXT t{};
    for (int k = 0; k < 16; k++)
        for (int n = 0; n < 64; n++) {
            double a = ang_(k * n, 64);
            t.c[k][n] = (float)(tcos_(a) / 64.0);
            t.s[k][n] = (float)(tsin_(a) / 64.0);
        }
    return t;
}
__device__ constexpr IXT IX = mkIX();

struct IZT { float c[16][40]; float s[16][40]; };
constexpr IZT mkIZ() {
    IZT t{};
    for (int k = 0; k < 16; k++) {
        int f = (k < 8) ? k : k + 5;
        double w = (f == 0 || f == 20) ? 1.0 : 2.0;
        for (int n = 0; n < 40; n++) {
            double a = ang_(f * n, 40);
            t.c[k][n] = (float)(tcos_(a) * w / 40.0);
            t.s[k][n] = (float)(tsin_(a) * w / 40.0);
        }
    }
    return t;
}
__device__ constexpr IZT IZ = mkIZ();

struct IYT { float c[32][64]; float s[32][64]; };
constexpr IYT mkIY() {
    IYT t{};
    for (int k = 0; k < 32; k++) {
        int f = (k < 16) ? k : k + 1;
        double w = (f == 0 || f == 32) ? 1.0 : 2.0;
        for (int n = 0; n < 64; n++) {
            double a = ang_(f * n, 64);
            t.c[k][n] = (float)(tcos_(a) * w / 64.0);
            t.s[k][n] = (float)(tsin_(a) * w / 64.0);
        }
    }
    return t;
}
__device__ constexpr IYT IY = mkIY();

// ================= scratch =================
__device__ float2 g_Qx[(size_t)NB*KM*NY*NZ*C];
__device__ float2 g_P1[(size_t)NB*NX*NY*KZM*C];
__device__ float2 g_F [(size_t)512*160*C];
__device__ float2 g_R [(size_t)NB*64*NZ*KM*C];
__device__ float  g_acc[(size_t)NB*NX*NY*NZ*C];

// ================= forward x DFT (all 16 modes) ============================
__global__ void __launch_bounds__(256) k_fftx16(const float* __restrict__ x) {
    int w = threadIdx.x >> 5, i = threadIdx.x & 31;
    int z = blockIdx.x * 8 + w;
    int y = blockIdx.y, b = blockIdx.z;
    const float* px = x + (((size_t)b*NX*NY + y)*NZ + z)*C + i;
    float2 acc[16];
    #pragma unroll
    for (int k = 0; k < 16; k++) acc[k] = make_float2(0.f, 0.f);
    #pragma unroll
    for (int xx = 0; xx < NX; xx++) {
        float v = px[(size_t)xx*NY*NZ*C];
        #pragma unroll
        for (int k = 0; k < 16; k++) {
            acc[k].x = fmaf(v, FX.c[k][xx], acc[k].x);
            acc[k].y = fmaf(v, FX.s[k][xx], acc[k].y);
        }
    }
    #pragma unroll
    for (int k = 0; k < 16; k++)
        g_Qx[((((size_t)b*KM + k)*NY + y)*NZ + z)*C + i] = acc[k];
}

// ================= forward z rDFT (16 modes) ================================
__global__ void __launch_bounds__(256) k_rfftz(const float* __restrict__ x) {
    int w = threadIdx.x >> 5, i = threadIdx.x & 31;
    int y = blockIdx.x * 8 + w;
    int xx = blockIdx.y, b = blockIdx.z;
    const float* px = x + (((size_t)(b*NX+xx)*NY + y) * NZ) * C + i;
    float2 acc[16];
    #pragma unroll
    for (int k = 0; k < 16; k++) acc[k] = make_float2(0.f, 0.f);
    #pragma unroll
    for (int z = 0; z < NZ; z++) {
        float v = px[(size_t)z*C];
        #pragma unroll
        for (int k = 0; k < 16; k++) {
            acc[k].x = fmaf(v, FZ.c[k][z], acc[k].x);
            acc[k].y = fmaf(v, FZ.s[k][z], acc[k].y);
        }
    }
    float2* q = g_P1 + (((size_t)(b*NX+xx)*NY + y) * KZM) * C + i;
    #pragma unroll
    for (int k = 0; k < 16; k++) q[(size_t)k*C] = acc[k];
}

// ================= xz: z DFT of Qx ==========================================
__global__ void __launch_bounds__(256) k_zfftQ16() {
    int w = threadIdx.x >> 5, i = threadIdx.x & 31;
    int y = blockIdx.x * 8 + w;
    int kx = blockIdx.y, b = blockIdx.z;
    const float2* q = g_Qx + (((size_t)(b*KM+kx)*NY + y) * NZ) * C + i;
    float2 acc[16];
    #pragma unroll
    for (int k = 0; k < 16; k++) acc[k] = make_float2(0.f, 0.f);
    #pragma unroll
    for (int z = 0; z < NZ; z++) {
        float2 a = q[(size_t)z*C];
        #pragma unroll
        for (int k = 0; k < 16; k++) {
            float cc = FZ.c[k][z], ss = FZ.s[k][z];
            acc[k].x = fmaf(a.x, cc, acc[k].x);
            acc[k].x = fmaf(a.y, -ss, acc[k].x);
            acc[k].y = fmaf(a.x, ss, acc[k].y);
            acc[k].y = fmaf(a.y, cc, acc[k].y);
        }
    }
    #pragma unroll
    for (int k = 0; k < 16; k++) {
        int m = kx*KZM + k;
        g_F[((size_t)m*(NB*NY) + b*NY + y)*C + i] = acc[k];
    }
}

// ================= xy: y DFT (real axis, 16 of 32 modes) ====================
template<int M0>
__global__ void __launch_bounds__(256) k_yfftQ16() {
    int w = threadIdx.x >> 5, i = threadIdx.x & 31;
    int z = blockIdx.x * 8 + w;
    int kx = blockIdx.y, b = blockIdx.z;
    const float2* q = g_Qx + (((size_t)(b*KM+kx)*NY) * NZ + z) * C + i;
    float2 acc[16];
    #pragma unroll
    for (int k = 0; k < 16; k++) acc[k] = make_float2(0.f, 0.f);
    #pragma unroll
    for (int y = 0; y < NY; y++) {
        float2 a = q[(size_t)y*NZ*C];
        #pragma unroll
        for (int k = 0; k < 16; k++) {
            float cc = FY.c[M0+k][y], ss = FY.s[M0+k][y];
            acc[k].x = fmaf(a.x, cc, acc[k].x);
            acc[k].x = fmaf(a.y, -ss, acc[k].x);
            acc[k].y = fmaf(a.x, ss, acc[k].y);
            acc[k].y = fmaf(a.y, cc, acc[k].y);
        }
    }
    #pragma unroll
    for (int k = 0; k < 16; k++) {
        int m = kx*KYM + M0 + k;
        g_F[((size_t)m*(NB*NZ) + b*NZ + z)*C + i] = acc[k];
    }
}

// ================= yz: y DFT of P1 ==========================================
__global__ void __launch_bounds__(256) k_yfftP16() {
    int w = threadIdx.x >> 5, i = threadIdx.x & 31;
    int kz = blockIdx.x * 8 + w;
    int xx = blockIdx.y, b = blockIdx.z;
    const float2* p = g_P1 + (((size_t)(b*NX+xx)*NY) * KZM + kz) * C + i;
    float2 acc[16];
    #pragma unroll
    for (int k = 0; k < 16; k++) acc[k] = make_float2(0.f, 0.f);
    #pragma unroll
    for (int y = 0; y < NY; y++) {
        float2 a = p[(size_t)y*KZM*C];
        #pragma unroll
        for (int k = 0; k < 16; k++) {
            float cc = FX.c[k][y], ss = FX.s[k][y];
            acc[k].x = fmaf(a.x, cc, acc[k].x);
            acc[k].x = fmaf(a.y, -ss, acc[k].x);
            acc[k].y = fmaf(a.x, ss, acc[k].y);
            acc[k].y = fmaf(a.y, cc, acc[k].y);
        }
    }
    #pragma unroll
    for (int k = 0; k < 16; k++) {
        int m = k*KZM + kz;
        g_F[((size_t)m*(NB*NX) + b*NX + xx)*C + i] = acc[k];
    }
}

// ================= per-mode complex 32x32 mix (grid-ized, smem) =============
__global__ void __launch_bounds__(1024) k_mixG(const float* __restrict__ fw,
                                               const float* __restrict__ fw2,
                                               int rows, int D) {
    __shared__ float2 Ws[C*C];
    __shared__ float2 Fs[32*C];
    int m = blockIdx.x, chunk = blockIdx.y;
    int tid = threadIdx.x;
    int mpx = 2 * D;
    int kx = m / mpx, km = m % mpx;
    const float* W = (km < D) ? fw : fw2;
    int kk = (km < D) ? km : km - D;
    int o = tid & 31, rr = tid >> 5;
    {
        int i = rr;
        size_t base = ((((size_t)i*C + o)*KM + kx)*D + kk) * 2;
        Ws[i*C + o] = make_float2(W[base], W[base + 1]);
    }
    size_t idx = ((size_t)m*rows + chunk*32 + rr)*C + o;
    Fs[rr*C + o] = g_F[idx];
    __syncthreads();
    float re = 0.f, im = 0.f;
    #pragma unroll
    for (int i = 0; i < C; i++) {
        float2 a = Fs[rr*C + i];
        float2 w = Ws[i*C + o];
        re += a.x*w.x - a.y*w.y;
        im += a.x*w.y + a.y*w.x;
    }
    g_F[idx] = make_float2(re, im);
}

// ================= inverse over z (16 modes -> 40 z) ========================
template<int Z0>
__device__ __forceinline__ void invZ_body(int b, int kc, int u, int o) {
    float2 acc[8];
    #pragma unroll
    for (int j = 0; j < 8; j++) acc[j] = make_float2(0.f, 0.f);
    #pragma unroll
    for (int kz = 0; kz < KZM; kz++) {
        float2 g = g_F[((size_t)(kc*KZM + kz)*(NB*64) + b*64 + u)*C + o];
        #pragma unroll
        for (int j = 0; j < 8; j++) {
            float cc = IZ.c[kz][Z0+j], ss = IZ.s[kz][Z0+j];
            acc[j].x = fmaf(g.x, cc, acc[j].x);
            acc[j].x = fmaf(g.y, -ss, acc[j].x);
            acc[j].y = fmaf(g.x, ss, acc[j].y);
            acc[j].y = fmaf(g.y, cc, acc[j].y);
        }
    }
    #pragma unroll
    for (int j = 0; j < 8; j++)
        g_R[(((size_t)(b*64 + u)*NZ + Z0 + j)*KM + kc)*C + o] = acc[j];
}
__global__ void __launch_bounds__(320) k_invZ() {
    int w = threadIdx.x >> 5, o = threadIdx.x & 31;
    int u = blockIdx.x * 2 + (w / 5);
    int slot = w % 5;
    int kc = blockIdx.y, b = blockIdx.z;
    switch (slot) {
        case 0: invZ_body<0 >(b, kc, u, o); break;
        case 1: invZ_body<8 >(b, kc, u, o); break;
        case 2: invZ_body<16>(b, kc, u, o); break;
        case 3: invZ_body<24>(b, kc, u, o); break;
        default: invZ_body<32>(b, kc, u, o); break;
    }
}

// ================= inverse over y real axis (32 modes -> 64 y), xy ==========
template<int Y0>
__device__ __forceinline__ void invY_body(int b, int kx, int z, int o) {
    float2 acc[8];
    #pragma unroll
    for (int j = 0; j < 8; j++) acc[j] = make_float2(0.f, 0.f);
    #pragma unroll
    for (int ky = 0; ky < KYM; ky++) {
        float2 g = g_F[((size_t)(kx*KYM + ky)*(NB*NZ) + b*NZ + z)*C + o];
        #pragma unroll
        for (int j = 0; j < 8; j++) {
            float cc = IY.c[ky][Y0+j], ss = IY.s[ky][Y0+j];
            acc[j].x = fmaf(g.x, cc, acc[j].x);
            acc[j].x = fmaf(g.y, -ss, acc[j].x);
            acc[j].y = fmaf(g.x, ss, acc[j].y);
            acc[j].y = fmaf(g.y, cc, acc[j].y);
        }
    }
    #pragma unroll
    for (int j = 0; j < 8; j++)
        g_R[(((size_t)(b*NZ + z)*NY + Y0 + j)*KM + kx)*C + o] = acc[j];
}
__global__ void __launch_bounds__(512) k_invY() {
    int w = threadIdx.x >> 5, o = threadIdx.x & 31;
    int z = blockIdx.x * 2 + (w >> 3);
    int slot = w & 7;
    int kx = blockIdx.y, b = blockIdx.z;
    switch (slot) {
        case 0: invY_body<0 >(b, kx, z, o); break;
        case 1: invY_body<8 >(b, kx, z, o); break;
        case 2: invY_body<16>(b, kx, z, o); break;
        case 3: invY_body<24>(b, kx, z, o); break;
        case 4: invY_body<32>(b, kx, z, o); break;
        case 5: invY_body<40>(b, kx, z, o); break;
        case 6: invY_body<48>(b, kx, z, o); break;
        default: invY_body<56>(b, kx, z, o); break;
    }
}

// ================= inverse complex axis, Re(), write or accumulate ==========
template<int N0, bool FIRST>
__device__ __forceinline__ void invAcc_body(size_t rrow, size_t obase, size_t ostride, int o) {
    float acc[8];
    #pragma unroll
    for (int j = 0; j < 8; j++) acc[j] = 0.f;
    #pragma unroll
    for (int k = 0; k < KM; k++) {
        float2 r = g_R[rrow*(KM*C) + (size_t)k*C + o];
        #pragma unroll
        for (int j = 0; j < 8; j++) {
            acc[j] = fmaf(r.x, IX.c[k][N0+j], acc[j]);
            acc[j] = fmaf(r.y, -IX.s[k][N0+j], acc[j]);
        }
    }
    #pragma unroll
    for (int j = 0; j < 8; j++) {
        if (FIRST) g_acc[obase + (size_t)(N0+j)*ostride + o] = acc[j];
        else       g_acc[obase + (size_t)(N0+j)*ostride + o] += acc[j];
    }
}
template<int BR>
__global__ void __launch_bounds__(512) k_invAcc() {
    int w = threadIdx.x >> 5, o = threadIdx.x & 31;
    int r = w >> 3, slot = w & 7;
    int b = blockIdx.z;
    size_t rrow, obase, ostride;
    if (BR == 0) {            // xz (FIRST: writes acc)
        int z = blockIdx.x, y = blockIdx.y*2 + r;
        rrow = ((size_t)(b*NY + y))*NZ + z;
        obase = (((size_t)b*NX*NY + y)*NZ + z)*C;
        ostride = (size_t)NY*NZ*C;
    } else if (BR == 1) {     // yz
        int z = blockIdx.x, xx = blockIdx.y*2 + r;
        rrow = ((size_t)(b*NX + xx))*NZ + z;
        obase = (((size_t)(b*NX + xx)*NY)*NZ + z)*C;
        ostride = (size_t)NZ*C;
    } else {                  // xy
        int y = blockIdx.x, z = blockIdx.y*2 + r;
        rrow = ((size_t)(b*NZ + z))*NY + y;
        obase = (((size_t)b*NX*NY + y)*NZ + z)*C;
        ostride = (size_t)NY*NZ*C;
    }
    constexpr bool F = (BR == 0);
    switch (slot) {
        case 0: invAcc_body<0 , F>(rrow, obase, ostride, o); break;
        case 1: invAcc_body<8 , F>(rrow, obase, ostride, o); break;
        case 2: invAcc_body<16, F>(rrow, obase, ostride, o); break;
        case 3: invAcc_body<24, F>(rrow, obase, ostride, o); break;
        case 4: invAcc_body<32, F>(rrow, obase, ostride, o); break;
        case 5: invAcc_body<40, F>(rrow, obase, ostride, o); break;
        case 6: invAcc_body<48, F>(rrow, obase, ostride, o); break;
        default: invAcc_body<56, F>(rrow, obase, ostride, o); break;
    }
}

// ============ feedforward with fused 1x1 conv: out = FF(acc + conv(x)) ======
__global__ void __launch_bounds__(256) k_ff2(const float* __restrict__ x,
                                             const float* __restrict__ wc_,
                                             const float* __restrict__ bc_,
                                             const float* __restrict__ w0,
                                             const float* __restrict__ b0,
                                             const float* __restrict__ w1,
                                             const float* __restrict__ b1,
                                             float* __restrict__ out) {
    __shared__ float wc[C*C];      // [i][o]
    __shared__ float w0t[C*64];    // [i][h]
    __shared__ float w1t[64*C];    // [h][o]
    __shared__ float bcs[C], b0s[64], b1s[C];
    __shared__ float xs[8][4][C];
    __shared__ float hsm[8][4][C];
    __shared__ float h1s[8][4][64];
    int tid = threadIdx.x;
    for (int t = tid; t < C*C;  t += 256) wc[t] = wc_[(t % C) * C + (t / C)];
    for (int t = tid; t < C*64; t += 256) { int i = t / 64, hh = t % 64; w0t[t] = w0[hh*C + i]; }
    for (int t = tid; t < 64*C; t += 256) { int hh = t / C, o = t % C;  w1t[t] = w1[o*64 + hh]; }
    if (tid < C)  bcs[tid] = bc_[tid];
    if (tid < 64) b0s[tid] = b0[tid];
    if (tid < C)  b1s[tid] = b1[tid];
    __syncthreads();
    int lane = tid & 31, w = tid >> 5;
    size_t t0 = ((size_t)blockIdx.x * 8 + w) * 32;
    for (int g = 0; g < 8; g++) {
        size_t tb = t0 + g * 4;
        float hv[4];
        #pragma unroll
        for (int r = 0; r < 4; r++) {
            xs[w][r][lane] = x[(tb + r)*C + lane];
            hv[r] = g_acc[(tb + r)*C + lane] + bcs[lane];
        }
        __syncwarp();
        #pragma unroll
        for (int i = 0; i < C; i++) {
            float wcv = wc[i*C + lane];
            #pragma unroll
            for (int r = 0; r < 4; r++) hv[r] = fmaf(xs[w][r][i], wcv, hv[r]);
        }
        #pragma unroll
        for (int r = 0; r < 4; r++) hsm[w][r][lane] = hv[r];
        __syncwarp();
        float h1a[4], h1b[4];
        #pragma unroll
        for (int r = 0; r < 4; r++) { h1a[r] = b0s[lane]; h1b[r] = b0s[lane + 32]; }
        #pragma unroll
        for (int i = 0; i < C; i++) {
            float wa = w0t[i*64 + lane], wb = w0t[i*64 + 32 + lane];
            #pragma unroll
            for (int r = 0; r < 4; r++) {
                float a = hsm[w][r][i];
                h1a[r] = fmaf(a, wa, h1a[r]);
                h1b[r] = fmaf(a, wb, h1b[r]);
            }
        }
        #pragma unroll
        for (int r = 0; r < 4; r++) {
            h1s[w][r][lane]      = fmaxf(h1a[r], 0.f);
            h1s[w][r][lane + 32] = fmaxf(h1b[r], 0.f);
        }
        __syncwarp();
        float v[4];
        #pragma unroll
        for (int r = 0; r < 4; r++) v[r] = b1s[lane];
        #pragma unroll
        for (int hh = 0; hh < 64; hh++) {
            float w1v = w1t[hh*C + lane];
            #pragma unroll
            for (int r = 0; r < 4; r++) v[r] = fmaf(h1s[w][r][hh], w1v, v[r]);
        }
        #pragma unroll
        for (int r = 0; r < 4; r++) out[(tb + r)*C + lane] = v[r];
        __syncwarp();
    }
}

extern "C" void kernel_launch(void* const* d_in, const int* in_sizes, int n_in,
                              void* d_out, int out_size) {
    const float* x      = (const float*)d_in[0];
    const float* w      = (const float*)d_in[1];
    const float* wb     = (const float*)d_in[2];
    const float* fw_xy  = (const float*)d_in[3];
    const float* fw_yz  = (const float*)d_in[4];
    const float* fw_xz  = (const float*)d_in[5];
    const float* fw2_xy = (const float*)d_in[6];
    const float* fw2_yz = (const float*)d_in[7];
    const float* fw2_xz = (const float*)d_in[8];
    const float* ffw0   = (const float*)d_in[9];
    const float* ffb0   = (const float*)d_in[10];
    const float* ffw1   = (const float*)d_in[11];
    const float* ffb1   = (const float*)d_in[12];
    float* out = (float*)d_out;

    // shared forward x-DFT (feeds xz + xy)
    k_fftx16<<<dim3(5, NY, NB), 256>>>(x);

    // ---- xz branch (initializes g_acc with '=') ----
    k_zfftQ16<<<dim3(8, KM, NB), 256>>>();
    k_mixG<<<dim3(256, 8), 1024>>>(fw_xz, fw2_xz, NB*NY, 8);
    k_invZ<<<dim3(32, KM, NB), 320>>>();
    k_invAcc<0><<<dim3(NZ, NY/2, NB), 512>>>();

    // ---- xy branch ----
    k_yfftQ16<0 ><<<dim3(5, KM, NB), 256>>>();
    k_yfftQ16<16><<<dim3(5, KM, NB), 256>>>();
    k_mixG<<<dim3(512, 5), 1024>>>(fw_xy, fw2_xy, NB*NZ, 16);
    k_invY<<<dim3(20, KM, NB), 512>>>();
    k_invAcc<2><<<dim3(NY, NZ/2, NB), 512>>>();

    // ---- yz branch ----
    k_rfftz<<<dim3(8, NX, NB), 256>>>(x);
    k_yfftP16<<<dim3(2, NX, NB), 256>>>();
    k_mixG<<<dim3(256, 8), 1024>>>(fw_yz, fw2_yz, NB*NX, 8);
    k_invZ<<<dim3(32, KM, NB), 320>>>();
    k_invAcc<1><<<dim3(NZ, NX/2, NB), 512>>>();

    // ---- feedforward (fused 1x1 conv + 2-layer MLP) ----
    k_ff2<<<2560, 256>>>(x, w, wb, ffw0, ffb0, ffw1, ffb1, out);
}

// round 9
// speedup vs baseline: 1.8954x; 1.0551x over previous
#include <cuda_runtime.h>
#include <cstdint>

#define NB 4
#define NX 64
#define NY 64
#define NZ 40
#define C  32
#define KM 16
#define KZM 16
#define KYM 32

// ================= compile-time trig ======
constexpr double D_PI = 3.141592653589793238462643383279502884;

constexpr double tsin_(double x) {
    double x2 = x * x, t = x, s = x;
    for (int n = 1; n <= 13; n++) { t *= -x2 / ((2.0*n) * (2.0*n + 1.0)); s += t; }
    return s;
}
constexpr double tcos_(double x) {
    double x2 = x * x, t = 1.0, s = 1.0;
    for (int n = 1; n <= 13; n++) { t *= -x2 / ((2.0*n - 1.0) * (2.0*n)); s += t; }
    return s;
}
constexpr double ang_(int m, int N) {
    int mm = m % N;
    if (mm > N / 2) mm -= N;
    return 2.0 * D_PI * mm / N;
}

struct FXT { float c[16][64]; float s[16][64]; };
constexpr FXT mkFX() {
    FXT t{};
    for (int k = 0; k < 16; k++)
        for (int n = 0; n < 64; n++) {
            double a = ang_(k * n, 64);
            t.c[k][n] = (float)tcos_(a);
            t.s[k][n] = (float)(-tsin_(a));
        }
    return t;
}
__device__ constexpr FXT FX = mkFX();

struct FZT { float c[16][40]; float s[16][40]; };
constexpr FZT mkFZ() {
    FZT t{};
    for (int k = 0; k < 16; k++) {
        int f = (k < 8) ? k : k + 5;
        for (int n = 0; n < 40; n++) {
            double a = ang_(f * n, 40);
            t.c[k][n] = (float)tcos_(a);
            t.s[k][n] = (float)(-tsin_(a));
        }
    }
    return t;
}
__device__ constexpr FZT FZ = mkFZ();

struct FYT { float c[32][64]; float s[32][64]; };
constexpr FYT mkFY() {
    FYT t{};
    for (int k = 0; k < 32; k++) {
        int f = (k < 16) ? k : k + 1;
        for (int n = 0; n < 64; n++) {
            double a = ang_(f * n, 64);
            t.c[k][n] = (float)tcos_(a);
            t.s[k][n] = (float)(-tsin_(a));
        }
    }
    return t;
}
__device__ constexpr FYT FY = mkFY();

struct IXT { float c[16][64]; float s[16][64]; };
constexpr IXT mkIX() {
    IXT t{};
    for (int k = 0; k < 16; k++)
        for (int n = 0; n < 64; n++) {
            double a = ang_(k * n, 64);
            t.c[k][n] = (float)(tcos_(a) / 64.0);
            t.s[k][n] = (float)(tsin_(a) / 64.0);
        }
    return t;
}
__device__ constexpr IXT IX = mkIX();

struct IZT { float c[16][40]; float s[16][40]; };
constexpr IZT mkIZ() {
    IZT t{};
    for (int k = 0; k < 16; k++) {
        int f = (k < 8) ? k : k + 5;
        double w = (f == 0 || f == 20) ? 1.0 : 2.0;
        for (int n = 0; n < 40; n++) {
            double a = ang_(f * n, 40);
            t.c[k][n] = (float)(tcos_(a) * w / 40.0);
            t.s[k][n] = (float)(tsin_(a) * w / 40.0);
        }
    }
    return t;
}
__device__ constexpr IZT IZ = mkIZ();

struct IYT { float c[32][64]; float s[32][64]; };
constexpr IYT mkIY() {
    IYT t{};
    for (int k = 0; k < 32; k++) {
        int f = (k < 16) ? k : k + 1;
        double w = (f == 0 || f == 32) ? 1.0 : 2.0;
        for (int n = 0; n < 64; n++) {
            double a = ang_(f * n, 64);
            t.c[k][n] = (float)(tcos_(a) * w / 64.0);
            t.s[k][n] = (float)(tsin_(a) * w / 64.0);
        }
    }
    return t;
}
__device__ constexpr IYT IY = mkIY();

// ================= scratch =================
__device__ float2 g_Qx[(size_t)NB*KM*NY*NZ*C];
__device__ float2 g_P1[(size_t)NB*NX*NY*KZM*C];
__device__ float2 g_F [(size_t)512*160*C];
__device__ float2 g_R [(size_t)NB*64*NZ*KM*C];
__device__ float  g_acc[(size_t)NB*NX*NY*NZ*C];

// ================= forward x DFT (all 16 modes) ============================
__global__ void __launch_bounds__(256) k_fftx16(const float* __restrict__ x) {
    int w = threadIdx.x >> 5, i = threadIdx.x & 31;
    int z = blockIdx.x * 8 + w;
    int y = blockIdx.y, b = blockIdx.z;
    const float* px = x + (((size_t)b*NX*NY + y)*NZ + z)*C + i;
    float2 acc[16];
    #pragma unroll
    for (int k = 0; k < 16; k++) acc[k] = make_float2(0.f, 0.f);
    #pragma unroll
    for (int xx = 0; xx < NX; xx++) {
        float v = px[(size_t)xx*NY*NZ*C];
        #pragma unroll
        for (int k = 0; k < 16; k++) {
            acc[k].x = fmaf(v, FX.c[k][xx], acc[k].x);
            acc[k].y = fmaf(v, FX.s[k][xx], acc[k].y);
        }
    }
    #pragma unroll
    for (int k = 0; k < 16; k++)
        g_Qx[((((size_t)b*KM + k)*NY + y)*NZ + z)*C + i] = acc[k];
}

// ================= forward z rDFT (16 modes) ================================
__global__ void __launch_bounds__(256) k_rfftz(const float* __restrict__ x) {
    int w = threadIdx.x >> 5, i = threadIdx.x & 31;
    int y = blockIdx.x * 8 + w;
    int xx = blockIdx.y, b = blockIdx.z;
    const float* px = x + (((size_t)(b*NX+xx)*NY + y) * NZ) * C + i;
    float2 acc[16];
    #pragma unroll
    for (int k = 0; k < 16; k++) acc[k] = make_float2(0.f, 0.f);
    #pragma unroll
    for (int z = 0; z < NZ; z++) {
        float v = px[(size_t)z*C];
        #pragma unroll
        for (int k = 0; k < 16; k++) {
            acc[k].x = fmaf(v, FZ.c[k][z], acc[k].x);
            acc[k].y = fmaf(v, FZ.s[k][z], acc[k].y);
        }
    }
    float2* q = g_P1 + (((size_t)(b*NX+xx)*NY + y) * KZM) * C + i;
    #pragma unroll
    for (int k = 0; k < 16; k++) q[(size_t)k*C] = acc[k];
}

// ================= xz: z DFT of Qx ==========================================
__global__ void __launch_bounds__(256) k_zfftQ16() {
    int w = threadIdx.x >> 5, i = threadIdx.x & 31;
    int y = blockIdx.x * 8 + w;
    int kx = blockIdx.y, b = blockIdx.z;
    const float2* q = g_Qx + (((size_t)(b*KM+kx)*NY + y) * NZ) * C + i;
    float2 acc[16];
    #pragma unroll
    for (int k = 0; k < 16; k++) acc[k] = make_float2(0.f, 0.f);
    #pragma unroll
    for (int z = 0; z < NZ; z++) {
        float2 a = q[(size_t)z*C];
        #pragma unroll
        for (int k = 0; k < 16; k++) {
            float cc = FZ.c[k][z], ss = FZ.s[k][z];
            acc[k].x = fmaf(a.x, cc, acc[k].x);
            acc[k].x = fmaf(a.y, -ss, acc[k].x);
            acc[k].y = fmaf(a.x, ss, acc[k].y);
            acc[k].y = fmaf(a.y, cc, acc[k].y);
        }
    }
    #pragma unroll
    for (int k = 0; k < 16; k++) {
        int m = kx*KZM + k;
        g_F[((size_t)m*(NB*NY) + b*NY + y)*C + i] = acc[k];
    }
}

// ================= xy: y DFT (real axis, 16 of 32 modes) ====================
template<int M0>
__global__ void __launch_bounds__(256) k_yfftQ16() {
    int w = threadIdx.x >> 5, i = threadIdx.x & 31;
    int z = blockIdx.x * 8 + w;
    int kx = blockIdx.y, b = blockIdx.z;
    const float2* q = g_Qx + (((size_t)(b*KM+kx)*NY) * NZ + z) * C + i;
    float2 acc[16];
    #pragma unroll
    for (int k = 0; k < 16; k++) acc[k] = make_float2(0.f, 0.f);
    #pragma unroll
    for (int y = 0; y < NY; y++) {
        float2 a = q[(size_t)y*NZ*C];
        #pragma unroll
        for (int k = 0; k < 16; k++) {
            float cc = FY.c[M0+k][y], ss = FY.s[M0+k][y];
            acc[k].x = fmaf(a.x, cc, acc[k].x);
            acc[k].x = fmaf(a.y, -ss, acc[k].x);
            acc[k].y = fmaf(a.x, ss, acc[k].y);
            acc[k].y = fmaf(a.y, cc, acc[k].y);
        }
    }
    #pragma unroll
    for (int k = 0; k < 16; k++) {
        int m = kx*KYM + M0 + k;
        g_F[((size_t)m*(NB*NZ) + b*NZ + z)*C + i] = acc[k];
    }
}

// ================= yz: y DFT of P1 ==========================================
__global__ void __launch_bounds__(256) k_yfftP16() {
    int w = threadIdx.x >> 5, i = threadIdx.x & 31;
    int kz = blockIdx.x * 8 + w;
    int xx = blockIdx.y, b = blockIdx.z;
    const float2* p = g_P1 + (((size_t)(b*NX+xx)*NY) * KZM + kz) * C + i;
    float2 acc[16];
    #pragma unroll
    for (int k = 0; k < 16; k++) acc[k] = make_float2(0.f, 0.f);
    #pragma unroll
    for (int y = 0; y < NY; y++) {
        float2 a = p[(size_t)y*KZM*C];
        #pragma unroll
        for (int k = 0; k < 16; k++) {
            float cc = FX.c[k][y], ss = FX.s[k][y];
            acc[k].x = fmaf(a.x, cc, acc[k].x);
            acc[k].x = fmaf(a.y, -ss, acc[k].x);
            acc[k].y = fmaf(a.x, ss, acc[k].y);
            acc[k].y = fmaf(a.y, cc, acc[k].y);
        }
    }
    #pragma unroll
    for (int k = 0; k < 16; k++) {
        int m = k*KZM + kz;
        g_F[((size_t)m*(NB*NX) + b*NX + xx)*C + i] = acc[k];
    }
}

// ================= per-mode complex 32x32 mix (grid-ized, smem) =============
__global__ void __launch_bounds__(1024) k_mixG(const float* __restrict__ fw,
                                               const float* __restrict__ fw2,
                                               int rows, int D) {
    __shared__ float2 Ws[C*C];
    __shared__ float2 Fs[32*C];
    int m = blockIdx.x, chunk = blockIdx.y;
    int tid = threadIdx.x;
    int mpx = 2 * D;
    int kx = m / mpx, km = m % mpx;
    const float* W = (km < D) ? fw : fw2;
    int kk = (km < D) ? km : km - D;
    int o = tid & 31, rr = tid >> 5;
    {
        int i = rr;
        size_t base = ((((size_t)i*C + o)*KM + kx)*D + kk) * 2;
        Ws[i*C + o] = make_float2(W[base], W[base + 1]);
    }
    size_t idx = ((size_t)m*rows + chunk*32 + rr)*C + o;
    Fs[rr*C + o] = g_F[idx];
    __syncthreads();
    float re = 0.f, im = 0.f;
    #pragma unroll
    for (int i = 0; i < C; i++) {
        float2 a = Fs[rr*C + i];
        float2 w = Ws[i*C + o];
        re += a.x*w.x - a.y*w.y;
        im += a.x*w.y + a.y*w.x;
    }
    g_F[idx] = make_float2(re, im);
}

// ================= inverse over z (16 modes -> 40 z) ========================
template<int Z0>
__device__ __forceinline__ void invZ_body(int b, int kc, int u, int o) {
    float2 acc[8];
    #pragma unroll
    for (int j = 0; j < 8; j++) acc[j] = make_float2(0.f, 0.f);
    #pragma unroll
    for (int kz = 0; kz < KZM; kz++) {
        float2 g = g_F[((size_t)(kc*KZM + kz)*(NB*64) + b*64 + u)*C + o];
        #pragma unroll
        for (int j = 0; j < 8; j++) {
            float cc = IZ.c[kz][Z0+j], ss = IZ.s[kz][Z0+j];
            acc[j].x = fmaf(g.x, cc, acc[j].x);
            acc[j].x = fmaf(g.y, -ss, acc[j].x);
            acc[j].y = fmaf(g.x, ss, acc[j].y);
            acc[j].y = fmaf(g.y, cc, acc[j].y);
        }
    }
    #pragma unroll
    for (int j = 0; j < 8; j++)
        g_R[(((size_t)(b*64 + u)*NZ + Z0 + j)*KM + kc)*C + o] = acc[j];
}
__global__ void __launch_bounds__(320) k_invZ() {
    int w = threadIdx.x >> 5, o = threadIdx.x & 31;
    int u = blockIdx.x * 2 + (w / 5);
    int slot = w % 5;
    int kc = blockIdx.y, b = blockIdx.z;
    switch (slot) {
        case 0: invZ_body<0 >(b, kc, u, o); break;
        case 1: invZ_body<8 >(b, kc, u, o); break;
        case 2: invZ_body<16>(b, kc, u, o); break;
        case 3: invZ_body<24>(b, kc, u, o); break;
        default: invZ_body<32>(b, kc, u, o); break;
    }
}

// ================= inverse over y real axis (32 modes -> 64 y), xy ==========
template<int Y0>
__device__ __forceinline__ void invY_body(int b, int kx, int z, int o) {
    float2 acc[8];
    #pragma unroll
    for (int j = 0; j < 8; j++) acc[j] = make_float2(0.f, 0.f);
    #pragma unroll
    for (int ky = 0; ky < KYM; ky++) {
        float2 g = g_F[((size_t)(kx*KYM + ky)*(NB*NZ) + b*NZ + z)*C + o];
        #pragma unroll
        for (int j = 0; j < 8; j++) {
            float cc = IY.c[ky][Y0+j], ss = IY.s[ky][Y0+j];
            acc[j].x = fmaf(g.x, cc, acc[j].x);
            acc[j].x = fmaf(g.y, -ss, acc[j].x);
            acc[j].y = fmaf(g.x, ss, acc[j].y);
            acc[j].y = fmaf(g.y, cc, acc[j].y);
        }
    }
    #pragma unroll
    for (int j = 0; j < 8; j++)
        g_R[(((size_t)(b*NZ + z)*NY + Y0 + j)*KM + kx)*C + o] = acc[j];
}
__global__ void __launch_bounds__(512) k_invY() {
    int w = threadIdx.x >> 5, o = threadIdx.x & 31;
    int z = blockIdx.x * 2 + (w >> 3);
    int slot = w & 7;
    int kx = blockIdx.y, b = blockIdx.z;
    switch (slot) {
        case 0: invY_body<0 >(b, kx, z, o); break;
        case 1: invY_body<8 >(b, kx, z, o); break;
        case 2: invY_body<16>(b, kx, z, o); break;
        case 3: invY_body<24>(b, kx, z, o); break;
        case 4: invY_body<32>(b, kx, z, o); break;
        case 5: invY_body<40>(b, kx, z, o); break;
        case 6: invY_body<48>(b, kx, z, o); break;
        default: invY_body<56>(b, kx, z, o); break;
    }
}

// ================= inverse complex axis, Re(), write or accumulate ==========
template<int N0, bool FIRST>
__device__ __forceinline__ void invAcc_body(size_t rrow, size_t obase, size_t ostride, int o) {
    float acc[8];
    #pragma unroll
    for (int j = 0; j < 8; j++) acc[j] = 0.f;
    #pragma unroll
    for (int k = 0; k < KM; k++) {
        float2 r = g_R[rrow*(KM*C) + (size_t)k*C + o];
        #pragma unroll
        for (int j = 0; j < 8; j++) {
            acc[j] = fmaf(r.x, IX.c[k][N0+j], acc[j]);
            acc[j] = fmaf(r.y, -IX.s[k][N0+j], acc[j]);
        }
    }
    #pragma unroll
    for (int j = 0; j < 8; j++) {
        if (FIRST) g_acc[obase + (size_t)(N0+j)*ostride + o] = acc[j];
        else       g_acc[obase + (size_t)(N0+j)*ostride + o] += acc[j];
    }
}
template<int BR>
__global__ void __launch_bounds__(512) k_invAcc() {
    int w = threadIdx.x >> 5, o = threadIdx.x & 31;
    int r = w >> 3, slot = w & 7;
    int b = blockIdx.z;
    size_t rrow, obase, ostride;
    if (BR == 0) {            // xz (FIRST: writes acc)
        int z = blockIdx.x, y = blockIdx.y*2 + r;
        rrow = ((size_t)(b*NY + y))*NZ + z;
        obase = (((size_t)b*NX*NY + y)*NZ + z)*C;
        ostride = (size_t)NY*NZ*C;
    } else if (BR == 1) {     // yz
        int z = blockIdx.x, xx = blockIdx.y*2 + r;
        rrow = ((size_t)(b*NX + xx))*NZ + z;
        obase = (((size_t)(b*NX + xx)*NY)*NZ + z)*C;
        ostride = (size_t)NZ*C;
    } else {                  // xy
        int y = blockIdx.x, z = blockIdx.y*2 + r;
        rrow = ((size_t)(b*NZ + z))*NY + y;
        obase = (((size_t)b*NX*NY + y)*NZ + z)*C;
        ostride = (size_t)NY*NZ*C;
    }
    constexpr bool F = (BR == 0);
    switch (slot) {
        case 0: invAcc_body<0 , F>(rrow, obase, ostride, o); break;
        case 1: invAcc_body<8 , F>(rrow, obase, ostride, o); break;
        case 2: invAcc_body<16, F>(rrow, obase, ostride, o); break;
        case 3: invAcc_body<24, F>(rrow, obase, ostride, o); break;
        case 4: invAcc_body<32, F>(rrow, obase, ostride, o); break;
        case 5: invAcc_body<40, F>(rrow, obase, ostride, o); break;
        case 6: invAcc_body<48, F>(rrow, obase, ostride, o); break;
        default: invAcc_body<56, F>(rrow, obase, ostride, o); break;
    }
}

// ==== feedforward + fused conv, 8-row groups, float4 smem broadcasts ========
__global__ void __launch_bounds__(256) k_ff3(const float* __restrict__ x,
                                             const float* __restrict__ wc_,
                                             const float* __restrict__ bc_,
                                             const float* __restrict__ w0,
                                             const float* __restrict__ b0,
                                             const float* __restrict__ w1,
                                             const float* __restrict__ b1,
                                             float* __restrict__ out) {
    __shared__ __align__(16) float wc[C*C];      // [i][o]
    __shared__ __align__(16) float w0t[C*64];    // [i][h]
    __shared__ __align__(16) float w1t[64*C];    // [h][o]
    __shared__ float bcs[C], b0s[64], b1s[C];
    __shared__ __align__(16) float xs[8][8][C];  // conv input, then reused as h
    __shared__ __align__(16) float h1s[8][8][64];
    int tid = threadIdx.x;
    for (int t = tid; t < C*C;  t += 256) wc[t] = wc_[(t % C) * C + (t / C)];
    for (int t = tid; t < C*64; t += 256) { int i = t / 64, hh = t % 64; w0t[t] = w0[hh*C + i]; }
    for (int t = tid; t < 64*C; t += 256) { int hh = t / C, o = t % C;  w1t[t] = w1[o*64 + hh]; }
    if (tid < C)  bcs[tid] = bc_[tid];
    if (tid < 64) b0s[tid] = b0[tid];
    if (tid < C)  b1s[tid] = b1[tid];
    __syncthreads();
    int lane = tid & 31, w = tid >> 5;
    size_t t0 = ((size_t)blockIdx.x * 8 + w) * 32;
    for (int g = 0; g < 4; g++) {
        size_t tb = t0 + g * 8;
        float hv[8];
        #pragma unroll
        for (int r = 0; r < 8; r++) {
            xs[w][r][lane] = x[(tb + r)*C + lane];
            hv[r] = g_acc[(tb + r)*C + lane] + bcs[lane];
        }
        __syncwarp();
        // conv: hv[r] += sum_i xs[r][i] * wc[i][lane]
        #pragma unroll
        for (int i4 = 0; i4 < C; i4 += 4) {
            float4 a4[8];
            #pragma unroll
            for (int r = 0; r < 8; r++)
                a4[r] = *reinterpret_cast<const float4*>(&xs[w][r][i4]);
            #pragma unroll
            for (int r = 0; r < 8; r++) {
                hv[r] = fmaf(a4[r].x, wc[(i4+0)*C + lane], hv[r]);
                hv[r] = fmaf(a4[r].y, wc[(i4+1)*C + lane], hv[r]);
                hv[r] = fmaf(a4[r].z, wc[(i4+2)*C + lane], hv[r]);
                hv[r] = fmaf(a4[r].w, wc[(i4+3)*C + lane], hv[r]);
            }
        }
        __syncwarp();   // all xs reads done before overwrite
        #pragma unroll
        for (int r = 0; r < 8; r++) xs[w][r][lane] = hv[r];
        __syncwarp();
        // ff1: h1 = relu(W0 h + b0)
        float h1a[8], h1b[8];
        #pragma unroll
        for (int r = 0; r < 8; r++) { h1a[r] = b0s[lane]; h1b[r] = b0s[lane + 32]; }
        #pragma unroll
        for (int i4 = 0; i4 < C; i4 += 4) {
            float4 a4[8];
            #pragma unroll
            for (int r = 0; r < 8; r++)
                a4[r] = *reinterpret_cast<const float4*>(&xs[w][r][i4]);
            #pragma unroll
            for (int di = 0; di < 4; di++) {
                float wa = w0t[(i4+di)*64 + lane], wb = w0t[(i4+di)*64 + 32 + lane];
                #pragma unroll
                for (int r = 0; r < 8; r++) {
                    float a = (di == 0) ? a4[r].x : (di == 1) ? a4[r].y : (di == 2) ? a4[r].z : a4[r].w;
                    h1a[r] = fmaf(a, wa, h1a[r]);
                    h1b[r] = fmaf(a, wb, h1b[r]);
                }
            }
        }
        #pragma unroll
        for (int r = 0; r < 8; r++) {
            h1s[w][r][lane]      = fmaxf(h1a[r], 0.f);
            h1s[w][r][lane + 32] = fmaxf(h1b[r], 0.f);
        }
        __syncwarp();
        // ff2: out = W1 h1 + b1
        float v[8];
        #pragma unroll
        for (int r = 0; r < 8; r++) v[r] = b1s[lane];
        #pragma unroll
        for (int h4 = 0; h4 < 64; h4 += 4) {
            float4 a4[8];
            #pragma unroll
            for (int r = 0; r < 8; r++)
                a4[r] = *reinterpret_cast<const float4*>(&h1s[w][r][h4]);
            #pragma unroll
            for (int dh = 0; dh < 4; dh++) {
                float w1v = w1t[(h4+dh)*C + lane];
                #pragma unroll
                for (int r = 0; r < 8; r++) {
                    float a = (dh == 0) ? a4[r].x : (dh == 1) ? a4[r].y : (dh == 2) ? a4[r].z : a4[r].w;
                    v[r] = fmaf(a, w1v, v[r]);
                }
            }
        }
        #pragma unroll
        for (int r = 0; r < 8; r++) out[(tb + r)*C + lane] = v[r];
        __syncwarp();
    }
}

extern "C" void kernel_launch(void* const* d_in, const int* in_sizes, int n_in,
                              void* d_out, int out_size) {
    const float* x      = (const float*)d_in[0];
    const float* w      = (const float*)d_in[1];
    const float* wb     = (const float*)d_in[2];
    const float* fw_xy  = (const float*)d_in[3];
    const float* fw_yz  = (const float*)d_in[4];
    const float* fw_xz  = (const float*)d_in[5];
    const float* fw2_xy = (const float*)d_in[6];
    const float* fw2_yz = (const float*)d_in[7];
    const float* fw2_xz = (const float*)d_in[8];
    const float* ffw0   = (const float*)d_in[9];
    const float* ffb0   = (const float*)d_in[10];
    const float* ffw1   = (const float*)d_in[11];
    const float* ffb1   = (const float*)d_in[12];
    float* out = (float*)d_out;

    // shared forward x-DFT (feeds xz + xy)
    k_fftx16<<<dim3(5, NY, NB), 256>>>(x);

    // ---- xz branch (initializes g_acc with '=') ----
    k_zfftQ16<<<dim3(8, KM, NB), 256>>>();
    k_mixG<<<dim3(256, 8), 1024>>>(fw_xz, fw2_xz, NB*NY, 8);
    k_invZ<<<dim3(32, KM, NB), 320>>>();
    k_invAcc<0><<<dim3(NZ, NY/2, NB), 512>>>();

    // ---- xy branch ----
    k_yfftQ16<0 ><<<dim3(5, KM, NB), 256>>>();
    k_yfftQ16<16><<<dim3(5, KM, NB), 256>>>();
    k_mixG<<<dim3(512, 5), 1024>>>(fw_xy, fw2_xy, NB*NZ, 16);
    k_invY<<<dim3(20, KM, NB), 512>>>();
    k_invAcc<2><<<dim3(NY, NZ/2, NB), 512>>>();

    // ---- yz branch ----
    k_rfftz<<<dim3(8, NX, NB), 256>>>(x);
    k_yfftP16<<<dim3(2, NX, NB), 256>>>();
    k_mixG<<<dim3(256, 8), 1024>>>(fw_yz, fw2_yz, NB*NX, 8);
    k_invZ<<<dim3(32, KM, NB), 320>>>();
    k_invAcc<1><<<dim3(NZ, NX/2, NB), 512>>>();

    // ---- feedforward (fused 1x1 conv + 2-layer MLP) ----
    k_ff3<<<2560, 256>>>(x, w, wb, ffw0, ffb0, ffw1, ffb1, out);
}

// round 10
// speedup vs baseline: 1.9705x; 1.0396x over previous
#include <cuda_runtime.h>
#include <cstdint>

#define NB 4
#define NX 64
#define NY 64
#define NZ 40
#define C  32
#define KM 16
#define KZM 16
#define KYM 32

typedef unsigned long long u64t;

__device__ __forceinline__ u64t ffma2(u64t a, u64t b, u64t c) {
    u64t d;
    asm("fma.rn.f32x2 %0, %1, %2, %3;" : "=l"(d) : "l"(a), "l"(b), "l"(c));
    return d;
}
__device__ __forceinline__ u64t pkf2(float2 v) {
    u64t d; asm("mov.b64 %0, {%1, %2};" : "=l"(d) : "f"(v.x), "f"(v.y)); return d;
}
__device__ __forceinline__ float2 upk(u64t v) {
    float2 r; asm("mov.b64 {%0, %1}, %2;" : "=f"(r.x), "=f"(r.y) : "l"(v)); return r;
}

// ================= compile-time trig ======
constexpr double D_PI = 3.141592653589793238462643383279502884;

constexpr double tsin_(double x) {
    double x2 = x * x, t = x, s = x;
    for (int n = 1; n <= 13; n++) { t *= -x2 / ((2.0*n) * (2.0*n + 1.0)); s += t; }
    return s;
}
constexpr double tcos_(double x) {
    double x2 = x * x, t = 1.0, s = 1.0;
    for (int n = 1; n <= 13; n++) { t *= -x2 / ((2.0*n - 1.0) * (2.0*n)); s += t; }
    return s;
}
constexpr double ang_(int m, int N) {
    int mm = m % N;
    if (mm > N / 2) mm -= N;
    return 2.0 * D_PI * mm / N;
}

struct FXT { float c[16][64]; float s[16][64]; };
constexpr FXT mkFX() {
    FXT t{};
    for (int k = 0; k < 16; k++)
        for (int n = 0; n < 64; n++) {
            double a = ang_(k * n, 64);
            t.c[k][n] = (float)tcos_(a);
            t.s[k][n] = (float)(-tsin_(a));
        }
    return t;
}
__device__ constexpr FXT FX = mkFX();

struct FZT { float c[16][40]; float s[16][40]; };
constexpr FZT mkFZ() {
    FZT t{};
    for (int k = 0; k < 16; k++) {
        int f = (k < 8) ? k : k + 5;
        for (int n = 0; n < 40; n++) {
            double a = ang_(f * n, 40);
            t.c[k][n] = (float)tcos_(a);
            t.s[k][n] = (float)(-tsin_(a));
        }
    }
    return t;
}
__device__ constexpr FZT FZ = mkFZ();

struct FYT { float c[32][64]; float s[32][64]; };
constexpr FYT mkFY() {
    FYT t{};
    for (int k = 0; k < 32; k++) {
        int f = (k < 16) ? k : k + 1;
        for (int n = 0; n < 64; n++) {
            double a = ang_(f * n, 64);
            t.c[k][n] = (float)tcos_(a);
            t.s[k][n] = (float)(-tsin_(a));
        }
    }
    return t;
}
__device__ constexpr FYT FY = mkFY();

struct IXT { float c[16][64]; float s[16][64]; };
constexpr IXT mkIX() {
    IXT t{};
    for (int k = 0; k < 16; k++)
        for (int n = 0; n < 64; n++) {
            double a = ang_(k * n, 64);
            t.c[k][n] = (float)(tcos_(a) / 64.0);
            t.s[k][n] = (float)(tsin_(a) / 64.0);
        }
    return t;
}
__device__ constexpr IXT IX = mkIX();

struct IZT { float c[16][40]; float s[16][40]; };
constexpr IZT mkIZ() {
    IZT t{};
    for (int k = 0; k < 16; k++) {
        int f = (k < 8) ? k : k + 5;
        double w = (f == 0 || f == 20) ? 1.0 : 2.0;
        for (int n = 0; n < 40; n++) {
            double a = ang_(f * n, 40);
            t.c[k][n] = (float)(tcos_(a) * w / 40.0);
            t.s[k][n] = (float)(tsin_(a) * w / 40.0);
        }
    }
    return t;
}
__device__ constexpr IZT IZ = mkIZ();

struct IYT { float c[32][64]; float s[32][64]; };
constexpr IYT mkIY() {
    IYT t{};
    for (int k = 0; k < 32; k++) {
        int f = (k < 16) ? k : k + 1;
        double w = (f == 0 || f == 32) ? 1.0 : 2.0;
        for (int n = 0; n < 64; n++) {
            double a = ang_(f * n, 64);
            t.c[k][n] = (float)(tcos_(a) * w / 64.0);
            t.s[k][n] = (float)(tsin_(a) * w / 64.0);
        }
    }
    return t;
}
__device__ constexpr IYT IY = mkIY();

// ================= scratch =================
__device__ float2 g_Qx[(size_t)NB*KM*NY*NZ*C];
__device__ float2 g_P1[(size_t)NB*NX*NY*KZM*C];
__device__ float2 g_F [(size_t)512*160*C];
__device__ float2 g_R [(size_t)NB*64*NZ*KM*C];
__device__ float  g_acc[(size_t)NB*NX*NY*NZ*C];

// ================= forward x DFT (all 16 modes) ============================
__global__ void __launch_bounds__(256) k_fftx16(const float* __restrict__ x) {
    int w = threadIdx.x >> 5, i = threadIdx.x & 31;
    int z = blockIdx.x * 8 + w;
    int y = blockIdx.y, b = blockIdx.z;
    const float* px = x + (((size_t)b*NX*NY + y)*NZ + z)*C + i;
    float2 acc[16];
    #pragma unroll
    for (int k = 0; k < 16; k++) acc[k] = make_float2(0.f, 0.f);
    #pragma unroll
    for (int xx = 0; xx < NX; xx++) {
        float v = px[(size_t)xx*NY*NZ*C];
        #pragma unroll
        for (int k = 0; k < 16; k++) {
            acc[k].x = fmaf(v, FX.c[k][xx], acc[k].x);
            acc[k].y = fmaf(v, FX.s[k][xx], acc[k].y);
        }
    }
    #pragma unroll
    for (int k = 0; k < 16; k++)
        g_Qx[((((size_t)b*KM + k)*NY + y)*NZ + z)*C + i] = acc[k];
}

// ================= forward z rDFT (16 modes) ================================
__global__ void __launch_bounds__(256) k_rfftz(const float* __restrict__ x) {
    int w = threadIdx.x >> 5, i = threadIdx.x & 31;
    int y = blockIdx.x * 8 + w;
    int xx = blockIdx.y, b = blockIdx.z;
    const float* px = x + (((size_t)(b*NX+xx)*NY + y) * NZ) * C + i;
    float2 acc[16];
    #pragma unroll
    for (int k = 0; k < 16; k++) acc[k] = make_float2(0.f, 0.f);
    #pragma unroll
    for (int z = 0; z < NZ; z++) {
        float v = px[(size_t)z*C];
        #pragma unroll
        for (int k = 0; k < 16; k++) {
            acc[k].x = fmaf(v, FZ.c[k][z], acc[k].x);
            acc[k].y = fmaf(v, FZ.s[k][z], acc[k].y);
        }
    }
    float2* q = g_P1 + (((size_t)(b*NX+xx)*NY + y) * KZM) * C + i;
    #pragma unroll
    for (int k = 0; k < 16; k++) q[(size_t)k*C] = acc[k];
}

// ================= xz: z DFT of Qx ==========================================
__global__ void __launch_bounds__(256) k_zfftQ16() {
    int w = threadIdx.x >> 5, i = threadIdx.x & 31;
    int y = blockIdx.x * 8 + w;
    int kx = blockIdx.y, b = blockIdx.z;
    const float2* q = g_Qx + (((size_t)(b*KM+kx)*NY + y) * NZ) * C + i;
    float2 acc[16];
    #pragma unroll
    for (int k = 0; k < 16; k++) acc[k] = make_float2(0.f, 0.f);
    #pragma unroll
    for (int z = 0; z < NZ; z++) {
        float2 a = q[(size_t)z*C];
        #pragma unroll
        for (int k = 0; k < 16; k++) {
            float cc = FZ.c[k][z], ss = FZ.s[k][z];
            acc[k].x = fmaf(a.x, cc, acc[k].x);
            acc[k].x = fmaf(a.y, -ss, acc[k].x);
            acc[k].y = fmaf(a.x, ss, acc[k].y);
            acc[k].y = fmaf(a.y, cc, acc[k].y);
        }
    }
    #pragma unroll
    for (int k = 0; k < 16; k++) {
        int m = kx*KZM + k;
        g_F[((size_t)m*(NB*NY) + b*NY + y)*C + i] = acc[k];
    }
}

// ================= xy: y DFT (real axis, 16 of 32 modes) ====================
template<int M0>
__global__ void __launch_bounds__(256) k_yfftQ16() {
    int w = threadIdx.x >> 5, i = threadIdx.x & 31;
    int z = blockIdx.x * 8 + w;
    int kx = blockIdx.y, b = blockIdx.z;
    const float2* q = g_Qx + (((size_t)(b*KM+kx)*NY) * NZ + z) * C + i;
    float2 acc[16];
    #pragma unroll
    for (int k = 0; k < 16; k++) acc[k] = make_float2(0.f, 0.f);
    #pragma unroll
    for (int y = 0; y < NY; y++) {
        float2 a = q[(size_t)y*NZ*C];
        #pragma unroll
        for (int k = 0; k < 16; k++) {
            float cc = FY.c[M0+k][y], ss = FY.s[M0+k][y];
            acc[k].x = fmaf(a.x, cc, acc[k].x);
            acc[k].x = fmaf(a.y, -ss, acc[k].x);
            acc[k].y = fmaf(a.x, ss, acc[k].y);
            acc[k].y = fmaf(a.y, cc, acc[k].y);
        }
    }
    #pragma unroll
    for (int k = 0; k < 16; k++) {
        int m = kx*KYM + M0 + k;
        g_F[((size_t)m*(NB*NZ) + b*NZ + z)*C + i] = acc[k];
    }
}

// ================= yz: y DFT of P1 ==========================================
__global__ void __launch_bounds__(256) k_yfftP16() {
    int w = threadIdx.x >> 5, i = threadIdx.x & 31;
    int kz = blockIdx.x * 8 + w;
    int xx = blockIdx.y, b = blockIdx.z;
    const float2* p = g_P1 + (((size_t)(b*NX+xx)*NY) * KZM + kz) * C + i;
    float2 acc[16];
    #pragma unroll
    for (int k = 0; k < 16; k++) acc[k] = make_float2(0.f, 0.f);
    #pragma unroll
    for (int y = 0; y < NY; y++) {
        float2 a = p[(size_t)y*KZM*C];
        #pragma unroll
        for (int k = 0; k < 16; k++) {
            float cc = FX.c[k][y], ss = FX.s[k][y];
            acc[k].x = fmaf(a.x, cc, acc[k].x);
            acc[k].x = fmaf(a.y, -ss, acc[k].x);
            acc[k].y = fmaf(a.x, ss, acc[k].y);
            acc[k].y = fmaf(a.y, cc, acc[k].y);
        }
    }
    #pragma unroll
    for (int k = 0; k < 16; k++) {
        int m = k*KZM + kz;
        g_F[((size_t)m*(NB*NX) + b*NX + xx)*C + i] = acc[k];
    }
}

// ================= per-mode complex 32x32 mix (grid-ized, smem) =============
__global__ void __launch_bounds__(1024) k_mixG(const float* __restrict__ fw,
                                               const float* __restrict__ fw2,
                                               int rows, int D) {
    __shared__ float2 Ws[C*C];
    __shared__ float2 Fs[32*C];
    int m = blockIdx.x, chunk = blockIdx.y;
    int tid = threadIdx.x;
    int mpx = 2 * D;
    int kx = m / mpx, km = m % mpx;
    const float* W = (km < D) ? fw : fw2;
    int kk = (km < D) ? km : km - D;
    int o = tid & 31, rr = tid >> 5;
    {
        int i = rr;
        size_t base = ((((size_t)i*C + o)*KM + kx)*D + kk) * 2;
        Ws[i*C + o] = make_float2(W[base], W[base + 1]);
    }
    size_t idx = ((size_t)m*rows + chunk*32 + rr)*C + o;
    Fs[rr*C + o] = g_F[idx];
    __syncthreads();
    float re = 0.f, im = 0.f;
    #pragma unroll
    for (int i = 0; i < C; i++) {
        float2 a = Fs[rr*C + i];
        float2 w = Ws[i*C + o];
        re += a.x*w.x - a.y*w.y;
        im += a.x*w.y + a.y*w.x;
    }
    g_F[idx] = make_float2(re, im);
}

// ================= inverse over z (16 modes -> 40 z) ========================
template<int Z0>
__device__ __forceinline__ void invZ_body(int b, int kc, int u, int o) {
    float2 acc[8];
    #pragma unroll
    for (int j = 0; j < 8; j++) acc[j] = make_float2(0.f, 0.f);
    #pragma unroll
    for (int kz = 0; kz < KZM; kz++) {
        float2 g = g_F[((size_t)(kc*KZM + kz)*(NB*64) + b*64 + u)*C + o];
        #pragma unroll
        for (int j = 0; j < 8; j++) {
            float cc = IZ.c[kz][Z0+j], ss = IZ.s[kz][Z0+j];
            acc[j].x = fmaf(g.x, cc, acc[j].x);
            acc[j].x = fmaf(g.y, -ss, acc[j].x);
            acc[j].y = fmaf(g.x, ss, acc[j].y);
            acc[j].y = fmaf(g.y, cc, acc[j].y);
        }
    }
    #pragma unroll
    for (int j = 0; j < 8; j++)
        g_R[(((size_t)(b*64 + u)*NZ + Z0 + j)*KM + kc)*C + o] = acc[j];
}
__global__ void __launch_bounds__(320) k_invZ() {
    int w = threadIdx.x >> 5, o = threadIdx.x & 31;
    int u = blockIdx.x * 2 + (w / 5);
    int slot = w % 5;
    int kc = blockIdx.y, b = blockIdx.z;
    switch (slot) {
        case 0: invZ_body<0 >(b, kc, u, o); break;
        case 1: invZ_body<8 >(b, kc, u, o); break;
        case 2: invZ_body<16>(b, kc, u, o); break;
        case 3: invZ_body<24>(b, kc, u, o); break;
        default: invZ_body<32>(b, kc, u, o); break;
    }
}

// ================= inverse over y real axis (32 modes -> 64 y), xy ==========
template<int Y0>
__device__ __forceinline__ void invY_body(int b, int kx, int z, int o) {
    float2 acc[8];
    #pragma unroll
    for (int j = 0; j < 8; j++) acc[j] = make_float2(0.f, 0.f);
    #pragma unroll
    for (int ky = 0; ky < KYM; ky++) {
        float2 g = g_F[((size_t)(kx*KYM + ky)*(NB*NZ) + b*NZ + z)*C + o];
        #pragma unroll
        for (int j = 0; j < 8; j++) {
            float cc = IY.c[ky][Y0+j], ss = IY.s[ky][Y0+j];
            acc[j].x = fmaf(g.x, cc, acc[j].x);
            acc[j].x = fmaf(g.y, -ss, acc[j].x);
            acc[j].y = fmaf(g.x, ss, acc[j].y);
            acc[j].y = fmaf(g.y, cc, acc[j].y);
        }
    }
    #pragma unroll
    for (int j = 0; j < 8; j++)
        g_R[(((size_t)(b*NZ + z)*NY + Y0 + j)*KM + kx)*C + o] = acc[j];
}
__global__ void __launch_bounds__(512) k_invY() {
    int w = threadIdx.x >> 5, o = threadIdx.x & 31;
    int z = blockIdx.x * 2 + (w >> 3);
    int slot = w & 7;
    int kx = blockIdx.y, b = blockIdx.z;
    switch (slot) {
        case 0: invY_body<0 >(b, kx, z, o); break;
        case 1: invY_body<8 >(b, kx, z, o); break;
        case 2: invY_body<16>(b, kx, z, o); break;
        case 3: invY_body<24>(b, kx, z, o); break;
        case 4: invY_body<32>(b, kx, z, o); break;
        case 5: invY_body<40>(b, kx, z, o); break;
        case 6: invY_body<48>(b, kx, z, o); break;
        default: invY_body<56>(b, kx, z, o); break;
    }
}

// ================= inverse complex axis, Re(), write or accumulate ==========
template<int N0, bool FIRST>
__device__ __forceinline__ void invAcc_body(size_t rrow, size_t obase, size_t ostride, int o) {
    float acc[8];
    #pragma unroll
    for (int j = 0; j < 8; j++) acc[j] = 0.f;
    #pragma unroll
    for (int k = 0; k < KM; k++) {
        float2 r = g_R[rrow*(KM*C) + (size_t)k*C + o];
        #pragma unroll
        for (int j = 0; j < 8; j++) {
            acc[j] = fmaf(r.x, IX.c[k][N0+j], acc[j]);
            acc[j] = fmaf(r.y, -IX.s[k][N0+j], acc[j]);
        }
    }
    #pragma unroll
    for (int j = 0; j < 8; j++) {
        if (FIRST) g_acc[obase + (size_t)(N0+j)*ostride + o] = acc[j];
        else       g_acc[obase + (size_t)(N0+j)*ostride + o] += acc[j];
    }
}
template<int BR>
__global__ void __launch_bounds__(512) k_invAcc() {
    int w = threadIdx.x >> 5, o = threadIdx.x & 31;
    int r = w >> 3, slot = w & 7;
    int b = blockIdx.z;
    size_t rrow, obase, ostride;
    if (BR == 0) {            // xz (FIRST: writes acc)
        int z = blockIdx.x, y = blockIdx.y*2 + r;
        rrow = ((size_t)(b*NY + y))*NZ + z;
        obase = (((size_t)b*NX*NY + y)*NZ + z)*C;
        ostride = (size_t)NY*NZ*C;
    } else if (BR == 1) {     // yz
        int z = blockIdx.x, xx = blockIdx.y*2 + r;
        rrow = ((size_t)(b*NX + xx))*NZ + z;
        obase = (((size_t)(b*NX + xx)*NY)*NZ + z)*C;
        ostride = (size_t)NZ*C;
    } else {                  // xy
        int y = blockIdx.x, z = blockIdx.y*2 + r;
        rrow = ((size_t)(b*NZ + z))*NY + y;
        obase = (((size_t)b*NX*NY + y)*NZ + z)*C;
        ostride = (size_t)NY*NZ*C;
    }
    constexpr bool F = (BR == 0);
    switch (slot) {
        case 0: invAcc_body<0 , F>(rrow, obase, ostride, o); break;
        case 1: invAcc_body<8 , F>(rrow, obase, ostride, o); break;
        case 2: invAcc_body<16, F>(rrow, obase, ostride, o); break;
        case 3: invAcc_body<24, F>(rrow, obase, ostride, o); break;
        case 4: invAcc_body<32, F>(rrow, obase, ostride, o); break;
        case 5: invAcc_body<40, F>(rrow, obase, ostride, o); break;
        case 6: invAcc_body<48, F>(rrow, obase, ostride, o); break;
        default: invAcc_body<56, F>(rrow, obase, ostride, o); break;
    }
}

// ==== feedforward + fused conv — packed f32x2 along reduction dim ===========
__global__ void __launch_bounds__(256) k_ff4(const float* __restrict__ x,
                                             const float* __restrict__ wc_,
                                             const float* __restrict__ bc_,
                                             const float* __restrict__ w0,
                                             const float* __restrict__ b0,
                                             const float* __restrict__ w1,
                                             const float* __restrict__ b1,
                                             float* __restrict__ out) {
    __shared__ __align__(16) u64t wcp [16*32];   // [i2][o]  (wc[o][2i2],wc[o][2i2+1])
    __shared__ __align__(16) u64t w0pa[16*32];   // [i2][lane] h=lane
    __shared__ __align__(16) u64t w0pb[16*32];   // [i2][lane] h=lane+32
    __shared__ __align__(16) u64t w1p [32*32];   // [h2][o]
    __shared__ float bcs[C], b0s[64], b1s[C];
    __shared__ __align__(16) float xs[8][8][C];
    __shared__ __align__(16) float h1s[8][8][64];
    int tid = threadIdx.x;
    const float2* wc2 = (const float2*)wc_;   // wc_[o*32+i]
    const float2* w02 = (const float2*)w0;    // w0[h*32+i]
    const float2* w12 = (const float2*)w1;    // w1[o*64+h]
    for (int t = tid; t < 16*32; t += 256) {
        int i2 = t >> 5, o = t & 31;
        wcp [t] = pkf2(wc2[o*16 + i2]);
        w0pa[t] = pkf2(w02[o*16 + i2]);          // h = o (lane)
        w0pb[t] = pkf2(w02[(o + 32)*16 + i2]);   // h = o+32
    }
    for (int t = tid; t < 32*32; t += 256) {
        int h2 = t >> 5, o = t & 31;
        w1p[t] = pkf2(w12[o*32 + h2]);
    }
    if (tid < C)  bcs[tid] = bc_[tid];
    if (tid < 64) b0s[tid] = b0[tid];
    if (tid < C)  b1s[tid] = b1[tid];
    __syncthreads();
    int lane = tid & 31, w = tid >> 5;
    size_t t0 = ((size_t)blockIdx.x * 8 + w) * 32;
    for (int g = 0; g < 4; g++) {
        size_t tb = t0 + g * 8;
        float ga[8];
        #pragma unroll
        for (int r = 0; r < 8; r++) {
            xs[w][r][lane] = x[(tb + r)*C + lane];
            ga[r] = g_acc[(tb + r)*C + lane];
        }
        __syncwarp();
        // ---- conv: packed partial sums over even/odd i ----
        u64t pc[8];
        #pragma unroll
        for (int r = 0; r < 8; r++) pc[r] = 0ull;
        #pragma unroll
        for (int i2 = 0; i2 < 16; i2 += 2) {
            u64t wv0 = wcp[i2*32 + lane], wv1 = wcp[(i2+1)*32 + lane];
            #pragma unroll
            for (int r = 0; r < 8; r++) {
                ulonglong2 a2 = *reinterpret_cast<const ulonglong2*>(&xs[w][r][i2*2]);
                pc[r] = ffma2(a2.x, wv0, pc[r]);
                pc[r] = ffma2(a2.y, wv1, pc[r]);
            }
        }
        float hv[8];
        #pragma unroll
        for (int r = 0; r < 8; r++) {
            float2 p = upk(pc[r]);
            hv[r] = ga[r] + bcs[lane] + p.x + p.y;
        }
        __syncwarp();   // all xs reads done before overwrite
        #pragma unroll
        for (int r = 0; r < 8; r++) xs[w][r][lane] = hv[r];
        __syncwarp();
        // ---- ff1: h1 = relu(W0 h + b0), packed over i ----
        u64t pa[8], pb[8];
        #pragma unroll
        for (int r = 0; r < 8; r++) { pa[r] = 0ull; pb[r] = 0ull; }
        #pragma unroll
        for (int i2 = 0; i2 < 16; i2 += 2) {
            u64t wa0 = w0pa[i2*32 + lane], wa1 = w0pa[(i2+1)*32 + lane];
            u64t wb0 = w0pb[i2*32 + lane], wb1 = w0pb[(i2+1)*32 + lane];
            #pragma unroll
            for (int r = 0; r < 8; r++) {
                ulonglong2 a2 = *reinterpret_cast<const ulonglong2*>(&xs[w][r][i2*2]);
                pa[r] = ffma2(a2.x, wa0, pa[r]);
                pa[r] = ffma2(a2.y, wa1, pa[r]);
                pb[r] = ffma2(a2.x, wb0, pb[r]);
                pb[r] = ffma2(a2.y, wb1, pb[r]);
            }
        }
        #pragma unroll
        for (int r = 0; r < 8; r++) {
            float2 qa = upk(pa[r]), qb = upk(pb[r]);
            h1s[w][r][lane]      = fmaxf(b0s[lane]      + qa.x + qa.y, 0.f);
            h1s[w][r][lane + 32] = fmaxf(b0s[lane + 32] + qb.x + qb.y, 0.f);
        }
        __syncwarp();
        // ---- ff2: out = W1 h1 + b1, packed over h ----
        u64t pv[8];
        #pragma unroll
        for (int r = 0; r < 8; r++) pv[r] = 0ull;
        #pragma unroll
        for (int h2 = 0; h2 < 32; h2 += 2) {
            u64t wv0 = w1p[h2*32 + lane], wv1 = w1p[(h2+1)*32 + lane];
            #pragma unroll
            for (int r = 0; r < 8; r++) {
                ulonglong2 a2 = *reinterpret_cast<const ulonglong2*>(&h1s[w][r][h2*2]);
                pv[r] = ffma2(a2.x, wv0, pv[r]);
                pv[r] = ffma2(a2.y, wv1, pv[r]);
            }
        }
        #pragma unroll
        for (int r = 0; r < 8; r++) {
            float2 p = upk(pv[r]);
            out[(tb + r)*C + lane] = b1s[lane] + p.x + p.y;
        }
        __syncwarp();
    }
}

extern "C" void kernel_launch(void* const* d_in, const int* in_sizes, int n_in,
                              void* d_out, int out_size) {
    const float* x      = (const float*)d_in[0];
    const float* w      = (const float*)d_in[1];
    const float* wb     = (const float*)d_in[2];
    const float* fw_xy  = (const float*)d_in[3];
    const float* fw_yz  = (const float*)d_in[4];
    const float* fw_xz  = (const float*)d_in[5];
    const float* fw2_xy = (const float*)d_in[6];
    const float* fw2_yz = (const float*)d_in[7];
    const float* fw2_xz = (const float*)d_in[8];
    const float* ffw0   = (const float*)d_in[9];
    const float* ffb0   = (const float*)d_in[10];
    const float* ffw1   = (const float*)d_in[11];
    const float* ffb1   = (const float*)d_in[12];
    float* out = (float*)d_out;

    // shared forward x-DFT (feeds xz + xy)
    k_fftx16<<<dim3(5, NY, NB), 256>>>(x);

    // ---- xz branch (initializes g_acc with '=') ----
    k_zfftQ16<<<dim3(8, KM, NB), 256>>>();
    k_mixG<<<dim3(256, 8), 1024>>>(fw_xz, fw2_xz, NB*NY, 8);
    k_invZ<<<dim3(32, KM, NB), 320>>>();
    k_invAcc<0><<<dim3(NZ, NY/2, NB), 512>>>();

    // ---- xy branch ----
    k_yfftQ16<0 ><<<dim3(5, KM, NB), 256>>>();
    k_yfftQ16<16><<<dim3(5, KM, NB), 256>>>();
    k_mixG<<<dim3(512, 5), 1024>>>(fw_xy, fw2_xy, NB*NZ, 16);
    k_invY<<<dim3(20, KM, NB), 512>>>();
    k_invAcc<2><<<dim3(NY, NZ/2, NB), 512>>>();

    // ---- yz branch ----
    k_rfftz<<<dim3(8, NX, NB), 256>>>(x);
    k_yfftP16<<<dim3(2, NX, NB), 256>>>();
    k_mixG<<<dim3(256, 8), 1024>>>(fw_yz, fw2_yz, NB*NX, 8);
    k_invZ<<<dim3(32, KM, NB), 320>>>();
    k_invAcc<1><<<dim3(NZ, NX/2, NB), 512>>>();

    // ---- feedforward (fused 1x1 conv + 2-layer MLP, f32x2) ----
    k_ff4<<<2560, 256>>>(x, w, wb, ffw0, ffb0, ffw1, ffb1, out);
}

// round 11
// speedup vs baseline: 2.0142x; 1.0222x over previous
#include <cuda_runtime.h>
#include <cstdint>

#define NB 4
#define NX 64
#define NY 64
#define NZ 40
#define C  32
#define KM 16
#define KZM 16
#define KYM 32

typedef unsigned long long u64t;

__device__ __forceinline__ u64t ffma2(u64t a, u64t b, u64t c) {
    u64t d;
    asm("fma.rn.f32x2 %0, %1, %2, %3;" : "=l"(d) : "l"(a), "l"(b), "l"(c));
    return d;
}
__device__ __forceinline__ u64t pkf2(float2 v) {
    u64t d; asm("mov.b64 %0, {%1, %2};" : "=l"(d) : "f"(v.x), "f"(v.y)); return d;
}
__device__ __forceinline__ float2 upk(u64t v) {
    float2 r; asm("mov.b64 {%0, %1}, %2;" : "=f"(r.x), "=f"(r.y) : "l"(v)); return r;
}

// ================= compile-time trig ======
constexpr double D_PI = 3.141592653589793238462643383279502884;

constexpr double tsin_(double x) {
    double x2 = x * x, t = x, s = x;
    for (int n = 1; n <= 13; n++) { t *= -x2 / ((2.0*n) * (2.0*n + 1.0)); s += t; }
    return s;
}
constexpr double tcos_(double x) {
    double x2 = x * x, t = 1.0, s = 1.0;
    for (int n = 1; n <= 13; n++) { t *= -x2 / ((2.0*n - 1.0) * (2.0*n)); s += t; }
    return s;
}
constexpr double ang_(int m, int N) {
    int mm = m % N;
    if (mm > N / 2) mm -= N;
    return 2.0 * D_PI * mm / N;
}

struct FXT { float c[16][64]; float s[16][64]; };
constexpr FXT mkFX() {
    FXT t{};
    for (int k = 0; k < 16; k++)
        for (int n = 0; n < 64; n++) {
            double a = ang_(k * n, 64);
            t.c[k][n] = (float)tcos_(a);
            t.s[k][n] = (float)(-tsin_(a));
        }
    return t;
}
__device__ constexpr FXT FX = mkFX();

struct FZT { float c[16][40]; float s[16][40]; };
constexpr FZT mkFZ() {
    FZT t{};
    for (int k = 0; k < 16; k++) {
        int f = (k < 8) ? k : k + 5;
        for (int n = 0; n < 40; n++) {
            double a = ang_(f * n, 40);
            t.c[k][n] = (float)tcos_(a);
            t.s[k][n] = (float)(-tsin_(a));
        }
    }
    return t;
}
__device__ constexpr FZT FZ = mkFZ();

struct FYT { float c[32][64]; float s[32][64]; };
constexpr FYT mkFY() {
    FYT t{};
    for (int k = 0; k < 32; k++) {
        int f = (k < 16) ? k : k + 1;
        for (int n = 0; n < 64; n++) {
            double a = ang_(f * n, 64);
            t.c[k][n] = (float)tcos_(a);
            t.s[k][n] = (float)(-tsin_(a));
        }
    }
    return t;
}
__device__ constexpr FYT FY = mkFY();

struct IXT { float c[16][64]; float s[16][64]; };
constexpr IXT mkIX() {
    IXT t{};
    for (int k = 0; k < 16; k++)
        for (int n = 0; n < 64; n++) {
            double a = ang_(k * n, 64);
            t.c[k][n] = (float)(tcos_(a) / 64.0);
            t.s[k][n] = (float)(tsin_(a) / 64.0);
        }
    return t;
}
__device__ constexpr IXT IX = mkIX();

struct IZT { float c[16][40]; float s[16][40]; };
constexpr IZT mkIZ() {
    IZT t{};
    for (int k = 0; k < 16; k++) {
        int f = (k < 8) ? k : k + 5;
        double w = (f == 0 || f == 20) ? 1.0 : 2.0;
        for (int n = 0; n < 40; n++) {
            double a = ang_(f * n, 40);
            t.c[k][n] = (float)(tcos_(a) * w / 40.0);
            t.s[k][n] = (float)(tsin_(a) * w / 40.0);
        }
    }
    return t;
}
__device__ constexpr IZT IZ = mkIZ();

struct IYT { float c[32][64]; float s[32][64]; };
constexpr IYT mkIY() {
    IYT t{};
    for (int k = 0; k < 32; k++) {
        int f = (k < 16) ? k : k + 1;
        double w = (f == 0 || f == 32) ? 1.0 : 2.0;
        for (int n = 0; n < 64; n++) {
            double a = ang_(f * n, 64);
            t.c[k][n] = (float)(tcos_(a) * w / 64.0);
            t.s[k][n] = (float)(tsin_(a) * w / 64.0);
        }
    }
    return t;
}
__device__ constexpr IYT IY = mkIY();

// ================= scratch =================
__device__ float2 g_Qx[(size_t)NB*KM*NY*NZ*C];
__device__ float2 g_P1[(size_t)NB*NX*NY*KZM*C];
__device__ float2 g_F [(size_t)512*160*C];
__device__ float2 g_R [(size_t)NB*64*NZ*KM*C];    // xz / yz coefficient rows
__device__ float2 g_R2[(size_t)NB*64*NZ*KM*C];    // xy coefficient rows
__device__ float  g_acc[(size_t)NB*NX*NY*NZ*C];

// ================= forward x DFT (all 16 modes) ============================
__global__ void __launch_bounds__(256) k_fftx16(const float* __restrict__ x) {
    int w = threadIdx.x >> 5, i = threadIdx.x & 31;
    int z = blockIdx.x * 8 + w;
    int y = blockIdx.y, b = blockIdx.z;
    const float* px = x + (((size_t)b*NX*NY + y)*NZ + z)*C + i;
    float2 acc[16];
    #pragma unroll
    for (int k = 0; k < 16; k++) acc[k] = make_float2(0.f, 0.f);
    #pragma unroll
    for (int xx = 0; xx < NX; xx++) {
        float v = px[(size_t)xx*NY*NZ*C];
        #pragma unroll
        for (int k = 0; k < 16; k++) {
            acc[k].x = fmaf(v, FX.c[k][xx], acc[k].x);
            acc[k].y = fmaf(v, FX.s[k][xx], acc[k].y);
        }
    }
    #pragma unroll
    for (int k = 0; k < 16; k++)
        g_Qx[((((size_t)b*KM + k)*NY + y)*NZ + z)*C + i] = acc[k];
}

// ================= forward z rDFT (16 modes) ================================
__global__ void __launch_bounds__(256) k_rfftz(const float* __restrict__ x) {
    int w = threadIdx.x >> 5, i = threadIdx.x & 31;
    int y = blockIdx.x * 8 + w;
    int xx = blockIdx.y, b = blockIdx.z;
    const float* px = x + (((size_t)(b*NX+xx)*NY + y) * NZ) * C + i;
    float2 acc[16];
    #pragma unroll
    for (int k = 0; k < 16; k++) acc[k] = make_float2(0.f, 0.f);
    #pragma unroll
    for (int z = 0; z < NZ; z++) {
        float v = px[(size_t)z*C];
        #pragma unroll
        for (int k = 0; k < 16; k++) {
            acc[k].x = fmaf(v, FZ.c[k][z], acc[k].x);
            acc[k].y = fmaf(v, FZ.s[k][z], acc[k].y);
        }
    }
    float2* q = g_P1 + (((size_t)(b*NX+xx)*NY + y) * KZM) * C + i;
    #pragma unroll
    for (int k = 0; k < 16; k++) q[(size_t)k*C] = acc[k];
}

// ================= xz: z DFT of Qx ==========================================
__global__ void __launch_bounds__(256) k_zfftQ16() {
    int w = threadIdx.x >> 5, i = threadIdx.x & 31;
    int y = blockIdx.x * 8 + w;
    int kx = blockIdx.y, b = blockIdx.z;
    const float2* q = g_Qx + (((size_t)(b*KM+kx)*NY + y) * NZ) * C + i;
    float2 acc[16];
    #pragma unroll
    for (int k = 0; k < 16; k++) acc[k] = make_float2(0.f, 0.f);
    #pragma unroll
    for (int z = 0; z < NZ; z++) {
        float2 a = q[(size_t)z*C];
        #pragma unroll
        for (int k = 0; k < 16; k++) {
            float cc = FZ.c[k][z], ss = FZ.s[k][z];
            acc[k].x = fmaf(a.x, cc, acc[k].x);
            acc[k].x = fmaf(a.y, -ss, acc[k].x);
            acc[k].y = fmaf(a.x, ss, acc[k].y);
            acc[k].y = fmaf(a.y, cc, acc[k].y);
        }
    }
    #pragma unroll
    for (int k = 0; k < 16; k++) {
        int m = kx*KZM + k;
        g_F[((size_t)m*(NB*NY) + b*NY + y)*C + i] = acc[k];
    }
}

// ================= xy: y DFT (real axis, all 32 modes) ======================
__global__ void __launch_bounds__(256) k_yfftQ32() {
    int w = threadIdx.x >> 5, i = threadIdx.x & 31;
    int z = blockIdx.x * 8 + w;
    int kx = blockIdx.y, b = blockIdx.z;
    const float2* q = g_Qx + (((size_t)(b*KM+kx)*NY) * NZ + z) * C + i;
    float2 acc[32];
    #pragma unroll
    for (int k = 0; k < 32; k++) acc[k] = make_float2(0.f, 0.f);
    #pragma unroll
    for (int y = 0; y < NY; y++) {
        float2 a = q[(size_t)y*NZ*C];
        #pragma unroll
        for (int k = 0; k < 32; k++) {
            float cc = FY.c[k][y], ss = FY.s[k][y];
            acc[k].x = fmaf(a.x, cc, acc[k].x);
            acc[k].x = fmaf(a.y, -ss, acc[k].x);
            acc[k].y = fmaf(a.x, ss, acc[k].y);
            acc[k].y = fmaf(a.y, cc, acc[k].y);
        }
    }
    #pragma unroll
    for (int k = 0; k < 32; k++) {
        int m = kx*KYM + k;
        g_F[((size_t)m*(NB*NZ) + b*NZ + z)*C + i] = acc[k];
    }
}

// ================= yz: y DFT of P1 ==========================================
__global__ void __launch_bounds__(256) k_yfftP16() {
    int w = threadIdx.x >> 5, i = threadIdx.x & 31;
    int kz = blockIdx.x * 8 + w;
    int xx = blockIdx.y, b = blockIdx.z;
    const float2* p = g_P1 + (((size_t)(b*NX+xx)*NY) * KZM + kz) * C + i;
    float2 acc[16];
    #pragma unroll
    for (int k = 0; k < 16; k++) acc[k] = make_float2(0.f, 0.f);
    #pragma unroll
    for (int y = 0; y < NY; y++) {
        float2 a = p[(size_t)y*KZM*C];
        #pragma unroll
        for (int k = 0; k < 16; k++) {
            float cc = FX.c[k][y], ss = FX.s[k][y];
            acc[k].x = fmaf(a.x, cc, acc[k].x);
            acc[k].x = fmaf(a.y, -ss, acc[k].x);
            acc[k].y = fmaf(a.x, ss, acc[k].y);
            acc[k].y = fmaf(a.y, cc, acc[k].y);
        }
    }
    #pragma unroll
    for (int k = 0; k < 16; k++) {
        int m = k*KZM + kz;
        g_F[((size_t)m*(NB*NX) + b*NX + xx)*C + i] = acc[k];
    }
}

// ================= per-mode complex 32x32 mix (grid-ized, smem) =============
__global__ void __launch_bounds__(1024) k_mixG(const float* __restrict__ fw,
                                               const float* __restrict__ fw2,
                                               int rows, int D) {
    __shared__ float2 Ws[C*C];
    __shared__ float2 Fs[32*C];
    int m = blockIdx.x, chunk = blockIdx.y;
    int tid = threadIdx.x;
    int mpx = 2 * D;
    int kx = m / mpx, km = m % mpx;
    const float* W = (km < D) ? fw : fw2;
    int kk = (km < D) ? km : km - D;
    int o = tid & 31, rr = tid >> 5;
    {
        int i = rr;
        size_t base = ((((size_t)i*C + o)*KM + kx)*D + kk) * 2;
        Ws[i*C + o] = make_float2(W[base], W[base + 1]);
    }
    size_t idx = ((size_t)m*rows + chunk*32 + rr)*C + o;
    Fs[rr*C + o] = g_F[idx];
    __syncthreads();
    float re = 0.f, im = 0.f;
    #pragma unroll
    for (int i = 0; i < C; i++) {
        float2 a = Fs[rr*C + i];
        float2 w = Ws[i*C + o];
        re += a.x*w.x - a.y*w.y;
        im += a.x*w.y + a.y*w.x;
    }
    g_F[idx] = make_float2(re, im);
}

// ================= inverse over z (16 modes -> 40 z) ========================
template<int Z0>
__device__ __forceinline__ void invZ_body(int b, int kc, int u, int o) {
    float2 acc[8];
    #pragma unroll
    for (int j = 0; j < 8; j++) acc[j] = make_float2(0.f, 0.f);
    #pragma unroll
    for (int kz = 0; kz < KZM; kz++) {
        float2 g = g_F[((size_t)(kc*KZM + kz)*(NB*64) + b*64 + u)*C + o];
        #pragma unroll
        for (int j = 0; j < 8; j++) {
            float cc = IZ.c[kz][Z0+j], ss = IZ.s[kz][Z0+j];
            acc[j].x = fmaf(g.x, cc, acc[j].x);
            acc[j].x = fmaf(g.y, -ss, acc[j].x);
            acc[j].y = fmaf(g.x, ss, acc[j].y);
            acc[j].y = fmaf(g.y, cc, acc[j].y);
        }
    }
    #pragma unroll
    for (int j = 0; j < 8; j++)
        g_R[(((size_t)(b*64 + u)*NZ + Z0 + j)*KM + kc)*C + o] = acc[j];
}
__global__ void __launch_bounds__(320) k_invZ() {
    int w = threadIdx.x >> 5, o = threadIdx.x & 31;
    int u = blockIdx.x * 2 + (w / 5);
    int slot = w % 5;
    int kc = blockIdx.y, b = blockIdx.z;
    switch (slot) {
        case 0: invZ_body<0 >(b, kc, u, o); break;
        case 1: invZ_body<8 >(b, kc, u, o); break;
        case 2: invZ_body<16>(b, kc, u, o); break;
        case 3: invZ_body<24>(b, kc, u, o); break;
        default: invZ_body<32>(b, kc, u, o); break;
    }
}

// ================= inverse over y real axis (32 modes -> 64 y), xy ==========
template<int Y0>
__device__ __forceinline__ void invY_body(int b, int kx, int z, int o) {
    float2 acc[8];
    #pragma unroll
    for (int j = 0; j < 8; j++) acc[j] = make_float2(0.f, 0.f);
    #pragma unroll
    for (int ky = 0; ky < KYM; ky++) {
        float2 g = g_F[((size_t)(kx*KYM + ky)*(NB*NZ) + b*NZ + z)*C + o];
        #pragma unroll
        for (int j = 0; j < 8; j++) {
            float cc = IY.c[ky][Y0+j], ss = IY.s[ky][Y0+j];
            acc[j].x = fmaf(g.x, cc, acc[j].x);
            acc[j].x = fmaf(g.y, -ss, acc[j].x);
            acc[j].y = fmaf(g.x, ss, acc[j].y);
            acc[j].y = fmaf(g.y, cc, acc[j].y);
        }
    }
    #pragma unroll
    for (int j = 0; j < 8; j++)
        g_R2[(((size_t)(b*NZ + z)*NY + Y0 + j)*KM + kx)*C + o] = acc[j];
}
__global__ void __launch_bounds__(512) k_invY() {
    int w = threadIdx.x >> 5, o = threadIdx.x & 31;
    int z = blockIdx.x * 2 + (w >> 3);
    int slot = w & 7;
    int kx = blockIdx.y, b = blockIdx.z;
    switch (slot) {
        case 0: invY_body<0 >(b, kx, z, o); break;
        case 1: invY_body<8 >(b, kx, z, o); break;
        case 2: invY_body<16>(b, kx, z, o); break;
        case 3: invY_body<24>(b, kx, z, o); break;
        case 4: invY_body<32>(b, kx, z, o); break;
        case 5: invY_body<40>(b, kx, z, o); break;
        case 6: invY_body<48>(b, kx, z, o); break;
        default: invY_body<56>(b, kx, z, o); break;
    }
}

// ====== fused inverse-x for xz + xy: acc = sum_k (R_A[k]+R_B[k])·IX[k][x] ===
template<int N0>
__device__ __forceinline__ void invAccXX_body(size_t rrowA, size_t rrowB,
                                              size_t obase, int o) {
    float2 s[KM];
    #pragma unroll
    for (int k = 0; k < KM; k++) {
        float2 a = g_R [rrowA*(KM*C) + (size_t)k*C + o];
        float2 b = g_R2[rrowB*(KM*C) + (size_t)k*C + o];
        s[k] = make_float2(a.x + b.x, a.y + b.y);
    }
    float acc[8];
    #pragma unroll
    for (int j = 0; j < 8; j++) acc[j] = 0.f;
    #pragma unroll
    for (int k = 0; k < KM; k++) {
        #pragma unroll
        for (int j = 0; j < 8; j++) {
            acc[j] = fmaf(s[k].x, IX.c[k][N0+j], acc[j]);
            acc[j] = fmaf(s[k].y, -IX.s[k][N0+j], acc[j]);
        }
    }
    #pragma unroll
    for (int j = 0; j < 8; j++)
        g_acc[obase + (size_t)(N0+j)*(NY*NZ*C) + o] = acc[j];
}
__global__ void __launch_bounds__(512) k_invAccXX() {
    int w = threadIdx.x >> 5, o = threadIdx.x & 31;
    int r = w >> 3, slot = w & 7;
    int b = blockIdx.z;
    int z = blockIdx.x, y = blockIdx.y*2 + r;
    size_t rrowA = ((size_t)(b*NY + y))*NZ + z;      // xz: keyed (b,y,z)
    size_t rrowB = ((size_t)(b*NZ + z))*NY + y;      // xy: keyed (b,z,y)
    size_t obase = (((size_t)b*NX*NY + y)*NZ + z)*C;
    switch (slot) {
        case 0: invAccXX_body<0 >(rrowA, rrowB, obase, o); break;
        case 1: invAccXX_body<8 >(rrowA, rrowB, obase, o); break;
        case 2: invAccXX_body<16>(rrowA, rrowB, obase, o); break;
        case 3: invAccXX_body<24>(rrowA, rrowB, obase, o); break;
        case 4: invAccXX_body<32>(rrowA, rrowB, obase, o); break;
        case 5: invAccXX_body<40>(rrowA, rrowB, obase, o); break;
        case 6: invAccXX_body<48>(rrowA, rrowB, obase, o); break;
        default: invAccXX_body<56>(rrowA, rrowB, obase, o); break;
    }
}

// ================= yz inverse over y (16 modes -> 64), Re(), += =============
template<int N0>
__device__ __forceinline__ void invAccYZ_body(size_t rrow, size_t obase, int o) {
    float acc[8];
    #pragma unroll
    for (int j = 0; j < 8; j++) acc[j] = 0.f;
    #pragma unroll
    for (int k = 0; k < KM; k++) {
        float2 r = g_R[rrow*(KM*C) + (size_t)k*C + o];
        #pragma unroll
        for (int j = 0; j < 8; j++) {
            acc[j] = fmaf(r.x, IX.c[k][N0+j], acc[j]);
            acc[j] = fmaf(r.y, -IX.s[k][N0+j], acc[j]);
        }
    }
    #pragma unroll
    for (int j = 0; j < 8; j++)
        g_acc[obase + (size_t)(N0+j)*(NZ*C) + o] += acc[j];
}
__global__ void __launch_bounds__(512) k_invAccYZ() {
    int w = threadIdx.x >> 5, o = threadIdx.x & 31;
    int r = w >> 3, slot = w & 7;
    int b = blockIdx.z;
    int z = blockIdx.x, xx = blockIdx.y*2 + r;
    size_t rrow = ((size_t)(b*NX + xx))*NZ + z;
    size_t obase = (((size_t)(b*NX + xx)*NY)*NZ + z)*C;
    switch (slot) {
        case 0: invAccYZ_body<0 >(rrow, obase, o); break;
        case 1: invAccYZ_body<8 >(rrow, obase, o); break;
        case 2: invAccYZ_body<16>(rrow, obase, o); break;
        case 3: invAccYZ_body<24>(rrow, obase, o); break;
        case 4: invAccYZ_body<32>(rrow, obase, o); break;
        case 5: invAccYZ_body<40>(rrow, obase, o); break;
        case 6: invAccYZ_body<48>(rrow, obase, o); break;
        default: invAccYZ_body<56>(rrow, obase, o); break;
    }
}

// ==== feedforward + fused conv — packed f32x2 along reduction dim ===========
__global__ void __launch_bounds__(256) k_ff4(const float* __restrict__ x,
                                             const float* __restrict__ wc_,
                                             const float* __restrict__ bc_,
                                             const float* __restrict__ w0,
                                             const float* __restrict__ b0,
                                             const float* __restrict__ w1,
                                             const float* __restrict__ b1,
                                             float* __restrict__ out) {
    __shared__ __align__(16) u64t wcp [16*32];
    __shared__ __align__(16) u64t w0pa[16*32];
    __shared__ __align__(16) u64t w0pb[16*32];
    __shared__ __align__(16) u64t w1p [32*32];
    __shared__ float bcs[C], b0s[64], b1s[C];
    __shared__ __align__(16) float xs[8][8][C];
    __shared__ __align__(16) float h1s[8][8][64];
    int tid = threadIdx.x;
    const float2* wc2 = (const float2*)wc_;
    const float2* w02 = (const float2*)w0;
    const float2* w12 = (const float2*)w1;
    for (int t = tid; t < 16*32; t += 256) {
        int i2 = t >> 5, o = t & 31;
        wcp [t] = pkf2(wc2[o*16 + i2]);
        w0pa[t] = pkf2(w02[o*16 + i2]);
        w0pb[t] = pkf2(w02[(o + 32)*16 + i2]);
    }
    for (int t = tid; t < 32*32; t += 256) {
        int h2 = t >> 5, o = t & 31;
        w1p[t] = pkf2(w12[o*32 + h2]);
    }
    if (tid < C)  bcs[tid] = bc_[tid];
    if (tid < 64) b0s[tid] = b0[tid];
    if (tid < C)  b1s[tid] = b1[tid];
    __syncthreads();
    int lane = tid & 31, w = tid >> 5;
    size_t t0 = ((size_t)blockIdx.x * 8 + w) * 32;
    for (int g = 0; g < 4; g++) {
        size_t tb = t0 + g * 8;
        float ga[8];
        #pragma unroll
        for (int r = 0; r < 8; r++) {
            xs[w][r][lane] = x[(tb + r)*C + lane];
            ga[r] = g_acc[(tb + r)*C + lane];
        }
        __syncwarp();
        u64t pc[8];
        #pragma unroll
        for (int r = 0; r < 8; r++) pc[r] = 0ull;
        #pragma unroll
        for (int i2 = 0; i2 < 16; i2 += 2) {
            u64t wv0 = wcp[i2*32 + lane], wv1 = wcp[(i2+1)*32 + lane];
            #pragma unroll
            for (int r = 0; r < 8; r++) {
                ulonglong2 a2 = *reinterpret_cast<const ulonglong2*>(&xs[w][r][i2*2]);
                pc[r] = ffma2(a2.x, wv0, pc[r]);
                pc[r] = ffma2(a2.y, wv1, pc[r]);
            }
        }
        float hv[8];
        #pragma unroll
        for (int r = 0; r < 8; r++) {
            float2 p = upk(pc[r]);
            hv[r] = ga[r] + bcs[lane] + p.x + p.y;
        }
        __syncwarp();
        #pragma unroll
        for (int r = 0; r < 8; r++) xs[w][r][lane] = hv[r];
        __syncwarp();
        u64t pa[8], pb[8];
        #pragma unroll
        for (int r = 0; r < 8; r++) { pa[r] = 0ull; pb[r] = 0ull; }
        #pragma unroll
        for (int i2 = 0; i2 < 16; i2 += 2) {
            u64t wa0 = w0pa[i2*32 + lane], wa1 = w0pa[(i2+1)*32 + lane];
            u64t wb0 = w0pb[i2*32 + lane], wb1 = w0pb[(i2+1)*32 + lane];
            #pragma unroll
            for (int r = 0; r < 8; r++) {
                ulonglong2 a2 = *reinterpret_cast<const ulonglong2*>(&xs[w][r][i2*2]);
                pa[r] = ffma2(a2.x, wa0, pa[r]);
                pa[r] = ffma2(a2.y, wa1, pa[r]);
                pb[r] = ffma2(a2.x, wb0, pb[r]);
                pb[r] = ffma2(a2.y, wb1, pb[r]);
            }
        }
        #pragma unroll
        for (int r = 0; r < 8; r++) {
            float2 qa = upk(pa[r]), qb = upk(pb[r]);
            h1s[w][r][lane]      = fmaxf(b0s[lane]      + qa.x + qa.y, 0.f);
            h1s[w][r][lane + 32] = fmaxf(b0s[lane + 32] + qb.x + qb.y, 0.f);
        }
        __syncwarp();
        u64t pv[8];
        #pragma unroll
        for (int r = 0; r < 8; r++) pv[r] = 0ull;
        #pragma unroll
        for (int h2 = 0; h2 < 32; h2 += 2) {
            u64t wv0 = w1p[h2*32 + lane], wv1 = w1p[(h2+1)*32 + lane];
            #pragma unroll
            for (int r = 0; r < 8; r++) {
                ulonglong2 a2 = *reinterpret_cast<const ulonglong2*>(&h1s[w][r][h2*2]);
                pv[r] = ffma2(a2.x, wv0, pv[r]);
                pv[r] = ffma2(a2.y, wv1, pv[r]);
            }
        }
        #pragma unroll
        for (int r = 0; r < 8; r++) {
            float2 p = upk(pv[r]);
            out[(tb + r)*C + lane] = b1s[lane] + p.x + p.y;
        }
        __syncwarp();
    }
}

extern "C" void kernel_launch(void* const* d_in, const int* in_sizes, int n_in,
                              void* d_out, int out_size) {
    const float* x      = (const float*)d_in[0];
    const float* w      = (const float*)d_in[1];
    const float* wb     = (const float*)d_in[2];
    const float* fw_xy  = (const float*)d_in[3];
    const float* fw_yz  = (const float*)d_in[4];
    const float* fw_xz  = (const float*)d_in[5];
    const float* fw2_xy = (const float*)d_in[6];
    const float* fw2_yz = (const float*)d_in[7];
    const float* fw2_xz = (const float*)d_in[8];
    const float* ffw0   = (const float*)d_in[9];
    const float* ffb0   = (const float*)d_in[10];
    const float* ffw1   = (const float*)d_in[11];
    const float* ffb1   = (const float*)d_in[12];
    float* out = (float*)d_out;

    // shared forward x-DFT (feeds xz + xy)
    k_fftx16<<<dim3(5, NY, NB), 256>>>(x);

    // ---- xz branch → R_A ----
    k_zfftQ16<<<dim3(8, KM, NB), 256>>>();
    k_mixG<<<dim3(256, 8), 1024>>>(fw_xz, fw2_xz, NB*NY, 8);
    k_invZ<<<dim3(32, KM, NB), 320>>>();

    // ---- xy branch → R_B ----
    k_yfftQ32<<<dim3(5, KM, NB), 256>>>();
    k_mixG<<<dim3(512, 5), 1024>>>(fw_xy, fw2_xy, NB*NZ, 16);
    k_invY<<<dim3(20, KM, NB), 512>>>();

    // ---- fused x-expansion of xz+xy (writes acc with '=') ----
    k_invAccXX<<<dim3(NZ, NY/2, NB), 512>>>();

    // ---- yz branch → R_A (reused), then += ----
    k_rfftz<<<dim3(8, NX, NB), 256>>>(x);
    k_yfftP16<<<dim3(2, NX, NB), 256>>>();
    k_mixG<<<dim3(256, 8), 1024>>>(fw_yz, fw2_yz, NB*NX, 8);
    k_invZ<<<dim3(32, KM, NB), 320>>>();
    k_invAccYZ<<<dim3(NZ, NX/2, NB), 512>>>();

    // ---- feedforward (fused 1x1 conv + 2-layer MLP, f32x2) ----
    k_ff4<<<2560, 256>>>(x, w, wb, ffw0, ffb0, ffw1, ffb1, out);
}

// round 14
// speedup vs baseline: 2.0270x; 1.0063x over previous
#include <cuda_runtime.h>
#include <cstdint>

#define NB 4
#define NX 64
#define NY 64
#define NZ 40
#define C  32
#define KM 16
#define KZM 16
#define KYM 32

typedef unsigned long long u64t;

__device__ __forceinline__ u64t ffma2(u64t a, u64t b, u64t c) {
    u64t d;
    asm("fma.rn.f32x2 %0, %1, %2, %3;" : "=l"(d) : "l"(a), "l"(b), "l"(c));
    return d;
}
__device__ __forceinline__ u64t pkf2(float2 v) {
    u64t d; asm("mov.b64 %0, {%1, %2};" : "=l"(d) : "f"(v.x), "f"(v.y)); return d;
}
__device__ __forceinline__ float2 upk(u64t v) {
    float2 r; asm("mov.b64 {%0, %1}, %2;" : "=f"(r.x), "=f"(r.y) : "l"(v)); return r;
}

// ================= compile-time trig ======
constexpr double D_PI = 3.141592653589793238462643383279502884;

constexpr double tsin_(double x) {
    double x2 = x * x, t = x, s = x;
    for (int n = 1; n <= 13; n++) { t *= -x2 / ((2.0*n) * (2.0*n + 1.0)); s += t; }
    return s;
}
constexpr double tcos_(double x) {
    double x2 = x * x, t = 1.0, s = 1.0;
    for (int n = 1; n <= 13; n++) { t *= -x2 / ((2.0*n - 1.0) * (2.0*n)); s += t; }
    return s;
}
constexpr double ang_(int m, int N) {
    int mm = m % N;
    if (mm > N / 2) mm -= N;
    return 2.0 * D_PI * mm / N;
}

struct FXT { float c[16][64]; float s[16][64]; };
constexpr FXT mkFX() {
    FXT t{};
    for (int k = 0; k < 16; k++)
        for (int n = 0; n < 64; n++) {
            double a = ang_(k * n, 64);
            t.c[k][n] = (float)tcos_(a);
            t.s[k][n] = (float)(-tsin_(a));
        }
    return t;
}
__device__ constexpr FXT FX = mkFX();

struct FZT { float c[16][40]; float s[16][40]; };
constexpr FZT mkFZ() {
    FZT t{};
    for (int k = 0; k < 16; k++) {
        int f = (k < 8) ? k : k + 5;
        for (int n = 0; n < 40; n++) {
            double a = ang_(f * n, 40);
            t.c[k][n] = (float)tcos_(a);
            t.s[k][n] = (float)(-tsin_(a));
        }
    }
    return t;
}
__device__ constexpr FZT FZ = mkFZ();

struct FYT { float c[32][64]; float s[32][64]; };
constexpr FYT mkFY() {
    FYT t{};
    for (int k = 0; k < 32; k++) {
        int f = (k < 16) ? k : k + 1;
        for (int n = 0; n < 64; n++) {
            double a = ang_(f * n, 64);
            t.c[k][n] = (float)tcos_(a);
            t.s[k][n] = (float)(-tsin_(a));
        }
    }
    return t;
}
__device__ constexpr FYT FY = mkFY();

struct IXT { float c[16][64]; float s[16][64]; };
constexpr IXT mkIX() {
    IXT t{};
    for (int k = 0; k < 16; k++)
        for (int n = 0; n < 64; n++) {
            double a = ang_(k * n, 64);
            t.c[k][n] = (float)(tcos_(a) / 64.0);
            t.s[k][n] = (float)(tsin_(a) / 64.0);
        }
    return t;
}
__device__ constexpr IXT IX = mkIX();

struct IZT { float c[16][40]; float s[16][40]; };
constexpr IZT mkIZ() {
    IZT t{};
    for (int k = 0; k < 16; k++) {
        int f = (k < 8) ? k : k + 5;
        double w = (f == 0 || f == 20) ? 1.0 : 2.0;
        for (int n = 0; n < 40; n++) {
            double a = ang_(f * n, 40);
            t.c[k][n] = (float)(tcos_(a) * w / 40.0);
            t.s[k][n] = (float)(tsin_(a) * w / 40.0);
        }
    }
    return t;
}
__device__ constexpr IZT IZ = mkIZ();

struct IYT { float c[32][64]; float s[32][64]; };
constexpr IYT mkIY() {
    IYT t{};
    for (int k = 0; k < 32; k++) {
        int f = (k < 16) ? k : k + 1;
        double w = (f == 0 || f == 32) ? 1.0 : 2.0;
        for (int n = 0; n < 64; n++) {
            double a = ang_(f * n, 64);
            t.c[k][n] = (float)(tcos_(a) * w / 64.0);
            t.s[k][n] = (float)(tsin_(a) * w / 64.0);
        }
    }
    return t;
}
__device__ constexpr IYT IY = mkIY();

// ================= scratch =================
__device__ float2 g_Qx[(size_t)NB*KM*NY*NZ*C];
__device__ float2 g_P1[(size_t)NB*NX*NY*KZM*C];
__device__ float2 g_F [(size_t)256*256*C];        // xz modes
__device__ float2 g_Fxy[(size_t)512*160*C];       // xy modes
__device__ float2 g_Fyz[(size_t)256*256*C];       // yz modes
__device__ float2 g_R [(size_t)NB*64*NZ*KM*C];    // xz coefficient rows
__device__ float2 g_R2[(size_t)NB*64*NZ*KM*C];    // xy coefficient rows
__device__ float2 g_R3[(size_t)NB*64*NZ*KM*C];    // yz coefficient rows
__device__ float  g_acc[(size_t)NB*NX*NY*NZ*C];

// ================= forward x DFT (all 16 modes) ============================
__global__ void __launch_bounds__(256) k_fftx16(const float* __restrict__ x) {
    int w = threadIdx.x >> 5, i = threadIdx.x & 31;
    int z = blockIdx.x * 8 + w;
    int y = blockIdx.y, b = blockIdx.z;
    const float* px = x + (((size_t)b*NX*NY + y)*NZ + z)*C + i;
    float2 acc[16];
    #pragma unroll
    for (int k = 0; k < 16; k++) acc[k] = make_float2(0.f, 0.f);
    #pragma unroll
    for (int xx = 0; xx < NX; xx++) {
        float v = px[(size_t)xx*NY*NZ*C];
        #pragma unroll
        for (int k = 0; k < 16; k++) {
            acc[k].x = fmaf(v, FX.c[k][xx], acc[k].x);
            acc[k].y = fmaf(v, FX.s[k][xx], acc[k].y);
        }
    }
    #pragma unroll
    for (int k = 0; k < 16; k++)
        g_Qx[((((size_t)b*KM + k)*NY + y)*NZ + z)*C + i] = acc[k];
}

// ================= forward z rDFT (16 modes) ================================
__global__ void __launch_bounds__(256) k_rfftz(const float* __restrict__ x) {
    int w = threadIdx.x >> 5, i = threadIdx.x & 31;
    int y = blockIdx.x * 8 + w;
    int xx = blockIdx.y, b = blockIdx.z;
    const float* px = x + (((size_t)(b*NX+xx)*NY + y) * NZ) * C + i;
    float2 acc[16];
    #pragma unroll
    for (int k = 0; k < 16; k++) acc[k] = make_float2(0.f, 0.f);
    #pragma unroll
    for (int z = 0; z < NZ; z++) {
        float v = px[(size_t)z*C];
        #pragma unroll
        for (int k = 0; k < 16; k++) {
            acc[k].x = fmaf(v, FZ.c[k][z], acc[k].x);
            acc[k].y = fmaf(v, FZ.s[k][z], acc[k].y);
        }
    }
    float2* q = g_P1 + (((size_t)(b*NX+xx)*NY + y) * KZM) * C + i;
    #pragma unroll
    for (int k = 0; k < 16; k++) q[(size_t)k*C] = acc[k];
}

// ================= xz: z DFT of Qx ==========================================
__global__ void __launch_bounds__(256) k_zfftQ16() {
    int w = threadIdx.x >> 5, i = threadIdx.x & 31;
    int y = blockIdx.x * 8 + w;
    int kx = blockIdx.y, b = blockIdx.z;
    const float2* q = g_Qx + (((size_t)(b*KM+kx)*NY + y) * NZ) * C + i;
    float2 acc[16];
    #pragma unroll
    for (int k = 0; k < 16; k++) acc[k] = make_float2(0.f, 0.f);
    #pragma unroll
    for (int z = 0; z < NZ; z++) {
        float2 a = q[(size_t)z*C];
        #pragma unroll
        for (int k = 0; k < 16; k++) {
            float cc = FZ.c[k][z], ss = FZ.s[k][z];
            acc[k].x = fmaf(a.x, cc, acc[k].x);
            acc[k].x = fmaf(a.y, -ss, acc[k].x);
            acc[k].y = fmaf(a.x, ss, acc[k].y);
            acc[k].y = fmaf(a.y, cc, acc[k].y);
        }
    }
    #pragma unroll
    for (int k = 0; k < 16; k++) {
        int m = kx*KZM + k;
        g_F[((size_t)m*(NB*NY) + b*NY + y)*C + i] = acc[k];
    }
}

// ================= xy: y DFT (real axis, all 32 modes) ======================
__global__ void __launch_bounds__(256) k_yfftQ32() {
    int w = threadIdx.x >> 5, i = threadIdx.x & 31;
    int z = blockIdx.x * 8 + w;
    int kx = blockIdx.y, b = blockIdx.z;
    const float2* q = g_Qx + (((size_t)(b*KM+kx)*NY) * NZ + z) * C + i;
    float2 acc[32];
    #pragma unroll
    for (int k = 0; k < 32; k++) acc[k] = make_float2(0.f, 0.f);
    #pragma unroll
    for (int y = 0; y < NY; y++) {
        float2 a = q[(size_t)y*NZ*C];
        #pragma unroll
        for (int k = 0; k < 32; k++) {
            float cc = FY.c[k][y], ss = FY.s[k][y];
            acc[k].x = fmaf(a.x, cc, acc[k].x);
            acc[k].x = fmaf(a.y, -ss, acc[k].x);
            acc[k].y = fmaf(a.x, ss, acc[k].y);
            acc[k].y = fmaf(a.y, cc, acc[k].y);
        }
    }
    #pragma unroll
    for (int k = 0; k < 32; k++) {
        int m = kx*KYM + k;
        g_Fxy[((size_t)m*(NB*NZ) + b*NZ + z)*C + i] = acc[k];
    }
}

// ================= yz: y DFT of P1 ==========================================
__global__ void __launch_bounds__(256) k_yfftP16() {
    int w = threadIdx.x >> 5, i = threadIdx.x & 31;
    int kz = blockIdx.x * 8 + w;
    int xx = blockIdx.y, b = blockIdx.z;
    const float2* p = g_P1 + (((size_t)(b*NX+xx)*NY) * KZM + kz) * C + i;
    float2 acc[16];
    #pragma unroll
    for (int k = 0; k < 16; k++) acc[k] = make_float2(0.f, 0.f);
    #pragma unroll
    for (int y = 0; y < NY; y++) {
        float2 a = p[(size_t)y*KZM*C];
        #pragma unroll
        for (int k = 0; k < 16; k++) {
            float cc = FX.c[k][y], ss = FX.s[k][y];
            acc[k].x = fmaf(a.x, cc, acc[k].x);
            acc[k].x = fmaf(a.y, -ss, acc[k].x);
            acc[k].y = fmaf(a.x, ss, acc[k].y);
            acc[k].y = fmaf(a.y, cc, acc[k].y);
        }
    }
    #pragma unroll
    for (int k = 0; k < 16; k++) {
        int m = k*KZM + kz;
        g_Fyz[((size_t)m*(NB*NX) + b*NX + xx)*C + i] = acc[k];
    }
}

// ====== combined per-mode mix for xz (modes 0..255) + yz (256..511), D=8 ====
__global__ void __launch_bounds__(1024) k_mixZZ(const float* __restrict__ fw_xz,
                                                const float* __restrict__ fw2_xz,
                                                const float* __restrict__ fw_yz,
                                                const float* __restrict__ fw2_yz) {
    __shared__ float2 Ws[C*C];
    __shared__ float2 Fs[32*C];
    int mm = blockIdx.x, chunk = blockIdx.y;
    int branch = mm >> 8;
    int m = mm & 255;
    float2* Fb = branch ? g_Fyz : g_F;
    const float* fw  = branch ? fw_yz  : fw_xz;
    const float* fw2 = branch ? fw2_yz : fw2_xz;
    int tid = threadIdx.x;
    const int D = 8;
    int kx = m / (2*D), km = m % (2*D);
    const float* W = (km < D) ? fw : fw2;
    int kk = (km < D) ? km : km - D;
    int o = tid & 31, rr = tid >> 5;
    {
        int i = rr;
        size_t base = ((((size_t)i*C + o)*KM + kx)*D + kk) * 2;
        Ws[i*C + o] = make_float2(W[base], W[base + 1]);
    }
    size_t idx = ((size_t)m*256 + chunk*32 + rr)*C + o;
    Fs[rr*C + o] = Fb[idx];
    __syncthreads();
    float re = 0.f, im = 0.f;
    #pragma unroll
    for (int i = 0; i < C; i++) {
        float2 a = Fs[rr*C + i];
        float2 w = Ws[i*C + o];
        re += a.x*w.x - a.y*w.y;
        im += a.x*w.y + a.y*w.x;
    }
    Fb[idx] = make_float2(re, im);
}

// ================= xy per-mode mix (D=16) ===================================
__global__ void __launch_bounds__(1024) k_mixXY(const float* __restrict__ fw,
                                                const float* __restrict__ fw2) {
    __shared__ float2 Ws[C*C];
    __shared__ float2 Fs[32*C];
    int m = blockIdx.x, chunk = blockIdx.y;
    int tid = threadIdx.x;
    const int D = 16;
    int kx = m / (2*D), km = m % (2*D);
    const float* W = (km < D) ? fw : fw2;
    int kk = (km < D) ? km : km - D;
    int o = tid & 31, rr = tid >> 5;
    {
        int i = rr;
        size_t base = ((((size_t)i*C + o)*KM + kx)*D + kk) * 2;
        Ws[i*C + o] = make_float2(W[base], W[base + 1]);
    }
    size_t idx = ((size_t)m*160 + chunk*32 + rr)*C + o;
    Fs[rr*C + o] = g_Fxy[idx];
    __syncthreads();
    float re = 0.f, im = 0.f;
    #pragma unroll
    for (int i = 0; i < C; i++) {
        float2 a = Fs[rr*C + i];
        float2 w = Ws[i*C + o];
        re += a.x*w.x - a.y*w.y;
        im += a.x*w.y + a.y*w.x;
    }
    g_Fxy[idx] = make_float2(re, im);
}

// ====== combined inverse over z for xz (bz<NB) and yz (bz>=NB) ==============
template<int Z0>
__device__ __forceinline__ void invZ_body(const float2* __restrict__ Fb,
                                          float2* __restrict__ Rout,
                                          int b, int kc, int u, int o) {
    float2 acc[8];
    #pragma unroll
    for (int j = 0; j < 8; j++) acc[j] = make_float2(0.f, 0.f);
    #pragma unroll
    for (int kz = 0; kz < KZM; kz++) {
        float2 g = Fb[((size_t)(kc*KZM + kz)*(NB*64) + b*64 + u)*C + o];
        #pragma unroll
        for (int j = 0; j < 8; j++) {
            float cc = IZ.c[kz][Z0+j], ss = IZ.s[kz][Z0+j];
            acc[j].x = fmaf(g.x, cc, acc[j].x);
            acc[j].x = fmaf(g.y, -ss, acc[j].x);
            acc[j].y = fmaf(g.x, ss, acc[j].y);
            acc[j].y = fmaf(g.y, cc, acc[j].y);
        }
    }
    #pragma unroll
    for (int j = 0; j < 8; j++)
        Rout[(((size_t)(b*64 + u)*NZ + Z0 + j)*KM + kc)*C + o] = acc[j];
}
__global__ void __launch_bounds__(320) k_invZ2() {
    int w = threadIdx.x >> 5, o = threadIdx.x & 31;
    int u = blockIdx.x * 2 + (w / 5);
    int slot = w % 5;
    int kc = blockIdx.y;
    int bz = blockIdx.z;
    int branch = (bz >= NB);
    int b = bz & (NB - 1);
    const float2* Fb = branch ? g_Fyz : g_F;
    float2* Rout = branch ? g_R3 : g_R;
    switch (slot) {
        case 0: invZ_body<0 >(Fb, Rout, b, kc, u, o); break;
        case 1: invZ_body<8 >(Fb, Rout, b, kc, u, o); break;
        case 2: invZ_body<16>(Fb, Rout, b, kc, u, o); break;
        case 3: invZ_body<24>(Fb, Rout, b, kc, u, o); break;
        default: invZ_body<32>(Fb, Rout, b, kc, u, o); break;
    }
}

// ================= inverse over y real axis (32 modes -> 64 y), xy ==========
template<int Y0>
__device__ __forceinline__ void invY_body(int b, int kx, int z, int o) {
    float2 acc[8];
    #pragma unroll
    for (int j = 0; j < 8; j++) acc[j] = make_float2(0.f, 0.f);
    #pragma unroll
    for (int ky = 0; ky < KYM; ky++) {
        float2 g = g_Fxy[((size_t)(kx*KYM + ky)*(NB*NZ) + b*NZ + z)*C + o];
        #pragma unroll
        for (int j = 0; j < 8; j++) {
            float cc = IY.c[ky][Y0+j], ss = IY.s[ky][Y0+j];
            acc[j].x = fmaf(g.x, cc, acc[j].x);
            acc[j].x = fmaf(g.y, -ss, acc[j].x);
            acc[j].y = fmaf(g.x, ss, acc[j].y);
            acc[j].y = fmaf(g.y, cc, acc[j].y);
        }
    }
    #pragma unroll
    for (int j = 0; j < 8; j++)
        g_R2[(((size_t)(b*NZ + z)*NY + Y0 + j)*KM + kx)*C + o] = acc[j];
}
__global__ void __launch_bounds__(512) k_invY() {
    int w = threadIdx.x >> 5, o = threadIdx.x & 31;
    int z = blockIdx.x * 2 + (w >> 3);
    int slot = w & 7;
    int kx = blockIdx.y, b = blockIdx.z;
    switch (slot) {
        case 0: invY_body<0 >(b, kx, z, o); break;
        case 1: invY_body<8 >(b, kx, z, o); break;
        case 2: invY_body<16>(b, kx, z, o); break;
        case 3: invY_body<24>(b, kx, z, o); break;
        case 4: invY_body<32>(b, kx, z, o); break;
        case 5: invY_body<40>(b, kx, z, o); break;
        case 6: invY_body<48>(b, kx, z, o); break;
        default: invY_body<56>(b, kx, z, o); break;
    }
}

// ====== fused inverse-x for xz + xy: acc = sum_k (R_A[k]+R_B[k])·IX[k][x] ===
template<int N0>
__device__ __forceinline__ void invAccXX_body(size_t rrowA, size_t rrowB,
                                              size_t obase, int o) {
    float2 s[KM];
    #pragma unroll
    for (int k = 0; k < KM; k++) {
        float2 a = g_R [rrowA*(KM*C) + (size_t)k*C + o];
        float2 b = g_R2[rrowB*(KM*C) + (size_t)k*C + o];
        s[k] = make_float2(a.x + b.x, a.y + b.y);
    }
    float acc[8];
    #pragma unroll
    for (int j = 0; j < 8; j++) acc[j] = 0.f;
    #pragma unroll
    for (int k = 0; k < KM; k++) {
        #pragma unroll
        for (int j = 0; j < 8; j++) {
            acc[j] = fmaf(s[k].x, IX.c[k][N0+j], acc[j]);
            acc[j] = fmaf(s[k].y, -IX.s[k][N0+j], acc[j]);
        }
    }
    #pragma unroll
    for (int j = 0; j < 8; j++)
        g_acc[obase + (size_t)(N0+j)*(NY*NZ*C) + o] = acc[j];
}
__global__ void __launch_bounds__(512) k_invAccXX() {
    int w = threadIdx.x >> 5, o = threadIdx.x & 31;
    int r = w >> 3, slot = w & 7;
    int b = blockIdx.z;
    int z = blockIdx.x, y = blockIdx.y*2 + r;
    size_t rrowA = ((size_t)(b*NY + y))*NZ + z;
    size_t rrowB = ((size_t)(b*NZ + z))*NY + y;
    size_t obase = (((size_t)b*NX*NY + y)*NZ + z)*C;
    switch (slot) {
        case 0: invAccXX_body<0 >(rrowA, rrowB, obase, o); break;
        case 1: invAccXX_body<8 >(rrowA, rrowB, obase, o); break;
        case 2: invAccXX_body<16>(rrowA, rrowB, obase, o); break;
        case 3: invAccXX_body<24>(rrowA, rrowB, obase, o); break;
        case 4: invAccXX_body<32>(rrowA, rrowB, obase, o); break;
        case 5: invAccXX_body<40>(rrowA, rrowB, obase, o); break;
        case 6: invAccXX_body<48>(rrowA, rrowB, obase, o); break;
        default: invAccXX_body<56>(rrowA, rrowB, obase, o); break;
    }
}

// ================= yz inverse over y (16 modes -> 64), Re(), += =============
template<int N0>
__device__ __forceinline__ void invAccYZ_body(size_t rrow, size_t obase, int o) {
    float acc[8];
    #pragma unroll
    for (int j = 0; j < 8; j++) acc[j] = 0.f;
    #pragma unroll
    for (int k = 0; k < KM; k++) {
        float2 r = g_R3[rrow*(KM*C) + (size_t)k*C + o];
        #pragma unroll
        for (int j = 0; j < 8; j++) {
            acc[j] = fmaf(r.x, IX.c[k][N0+j], acc[j]);
            acc[j] = fmaf(r.y, -IX.s[k][N0+j], acc[j]);
        }
    }
    #pragma unroll
    for (int j = 0; j < 8; j++)
        g_acc[obase + (size_t)(N0+j)*(NZ*C) + o] += acc[j];
}
__global__ void __launch_bounds__(512) k_invAccYZ() {
    int w = threadIdx.x >> 5, o = threadIdx.x & 31;
    int r = w >> 3, slot = w & 7;
    int b = blockIdx.z;
    int z = blockIdx.x, xx = blockIdx.y*2 + r;
    size_t rrow = ((size_t)(b*NX + xx))*NZ + z;
    size_t obase = (((size_t)(b*NX + xx)*NY)*NZ + z)*C;
    switch (slot) {
        case 0: invAccYZ_body<0 >(rrow, obase, o); break;
        case 1: invAccYZ_body<8 >(rrow, obase, o); break;
        case 2: invAccYZ_body<16>(rrow, obase, o); break;
        case 3: invAccYZ_body<24>(rrow, obase, o); break;
        case 4: invAccYZ_body<32>(rrow, obase, o); break;
        case 5: invAccYZ_body<40>(rrow, obase, o); break;
        case 6: invAccYZ_body<48>(rrow, obase, o); break;
        default: invAccYZ_body<56>(rrow, obase, o); break;
    }
}

// ==== feedforward + fused conv — packed f32x2 along reduction dim ===========
__global__ void __launch_bounds__(256) k_ff4(const float* __restrict__ x,
                                             const float* __restrict__ wc_,
                                             const float* __restrict__ bc_,
                                             const float* __restrict__ w0,
                                             const float* __restrict__ b0,
                                             const float* __restrict__ w1,
                                             const float* __restrict__ b1,
                                             float* __restrict__ out) {
    __shared__ __align__(16) u64t wcp [16*32];
    __shared__ __align__(16) u64t w0pa[16*32];
    __shared__ __align__(16) u64t w0pb[16*32];
    __shared__ __align__(16) u64t w1p [32*32];
    __shared__ float bcs[C], b0s[64], b1s[C];
    __shared__ __align__(16) float xs[8][8][C];
    __shared__ __align__(16) float h1s[8][8][64];
    int tid = threadIdx.x;
    const float2* wc2 = (const float2*)wc_;
    const float2* w02 = (const float2*)w0;
    const float2* w12 = (const float2*)w1;
    for (int t = tid; t < 16*32; t += 256) {
        int i2 = t >> 5, o = t & 31;
        wcp [t] = pkf2(wc2[o*16 + i2]);
        w0pa[t] = pkf2(w02[o*16 + i2]);
        w0pb[t] = pkf2(w02[(o + 32)*16 + i2]);
    }
    for (int t = tid; t < 32*32; t += 256) {
        int h2 = t >> 5, o = t & 31;
        w1p[t] = pkf2(w12[o*32 + h2]);
    }
    if (tid < C)  bcs[tid] = bc_[tid];
    if (tid < 64) b0s[tid] = b0[tid];
    if (tid < C)  b1s[tid] = b1[tid];
    __syncthreads();
    int lane = tid & 31, w = tid >> 5;
    size_t t0 = ((size_t)blockIdx.x * 8 + w) * 32;
    for (int g = 0; g < 4; g++) {
        size_t tb = t0 + g * 8;
        float ga[8];
        #pragma unroll
        for (int r = 0; r < 8; r++) {
            xs[w][r][lane] = x[(tb + r)*C + lane];
            ga[r] = g_acc[(tb + r)*C + lane];
        }
        __syncwarp();
        u64t pc[8];
        #pragma unroll
        for (int r = 0; r < 8; r++) pc[r] = 0ull;
        #pragma unroll
        for (int i2 = 0; i2 < 16; i2 += 2) {
            u64t wv0 = wcp[i2*32 + lane], wv1 = wcp[(i2+1)*32 + lane];
            #pragma unroll
            for (int r = 0; r < 8; r++) {
                ulonglong2 a2 = *reinterpret_cast<const ulonglong2*>(&xs[w][r][i2*2]);
                pc[r] = ffma2(a2.x, wv0, pc[r]);
                pc[r] = ffma2(a2.y, wv1, pc[r]);
            }
        }
        float hv[8];
        #pragma unroll
        for (int r = 0; r < 8; r++) {
            float2 p = upk(pc[r]);
            hv[r] = ga[r] + bcs[lane] + p.x + p.y;
        }
        __syncwarp();
        #pragma unroll
        for (int r = 0; r < 8; r++) xs[w][r][lane] = hv[r];
        __syncwarp();
        u64t pa[8], pb[8];
        #pragma unroll
        for (int r = 0; r < 8; r++) { pa[r] = 0ull; pb[r] = 0ull; }
        #pragma unroll
        for (int i2 = 0; i2 < 16; i2 += 2) {
            u64t wa0 = w0pa[i2*32 + lane], wa1 = w0pa[(i2+1)*32 + lane];
            u64t wb0 = w0pb[i2*32 + lane], wb1 = w0pb[(i2+1)*32 + lane];
            #pragma unroll
            for (int r = 0; r < 8; r++) {
                ulonglong2 a2 = *reinterpret_cast<const ulonglong2*>(&xs[w][r][i2*2]);
                pa[r] = ffma2(a2.x, wa0, pa[r]);
                pa[r] = ffma2(a2.y, wa1, pa[r]);
                pb[r] = ffma2(a2.x, wb0, pb[r]);
                pb[r] = ffma2(a2.y, wb1, pb[r]);
            }
        }
        #pragma unroll
        for (int r = 0; r < 8; r++) {
            float2 qa = upk(pa[r]), qb = upk(pb[r]);
            h1s[w][r][lane]      = fmaxf(b0s[lane]      + qa.x + qa.y, 0.f);
            h1s[w][r][lane + 32] = fmaxf(b0s[lane + 32] + qb.x + qb.y, 0.f);
        }
        __syncwarp();
        u64t pv[8];
        #pragma unroll
        for (int r = 0; r < 8; r++) pv[r] = 0ull;
        #pragma unroll
        for (int h2 = 0; h2 < 32; h2 += 2) {
            u64t wv0 = w1p[h2*32 + lane], wv1 = w1p[(h2+1)*32 + lane];
            #pragma unroll
            for (int r = 0; r < 8; r++) {
                ulonglong2 a2 = *reinterpret_cast<const ulonglong2*>(&h1s[w][r][h2*2]);
                pv[r] = ffma2(a2.x, wv0, pv[r]);
                pv[r] = ffma2(a2.y, wv1, pv[r]);
            }
        }
        #pragma unroll
        for (int r = 0; r < 8; r++) {
            float2 p = upk(pv[r]);
            out[(tb + r)*C + lane] = b1s[lane] + p.x + p.y;
        }
        __syncwarp();
    }
}

extern "C" void kernel_launch(void* const* d_in, const int* in_sizes, int n_in,
                              void* d_out, int out_size) {
    const float* x      = (const float*)d_in[0];
    const float* w      = (const float*)d_in[1];
    const float* wb     = (const float*)d_in[2];
    const float* fw_xy  = (const float*)d_in[3];
    const float* fw_yz  = (const float*)d_in[4];
    const float* fw_xz  = (const float*)d_in[5];
    const float* fw2_xy = (const float*)d_in[6];
    const float* fw2_yz = (const float*)d_in[7];
    const float* fw2_xz = (const float*)d_in[8];
    const float* ffw0   = (const float*)d_in[9];
    const float* ffb0   = (const float*)d_in[10];
    const float* ffw1   = (const float*)d_in[11];
    const float* ffb1   = (const float*)d_in[12];
    float* out = (float*)d_out;

    // ---- forwards ----
    k_fftx16 <<<dim3(5, NY, NB), 256>>>(x);
    k_rfftz  <<<dim3(8, NX, NB), 256>>>(x);
    k_zfftQ16<<<dim3(8, KM, NB), 256>>>();
    k_yfftQ32<<<dim3(5, KM, NB), 256>>>();
    k_yfftP16<<<dim3(2, NX, NB), 256>>>();

    // ---- mixes ----
    k_mixZZ<<<dim3(512, 8), 1024>>>(fw_xz, fw2_xz, fw_yz, fw2_yz);
    k_mixXY<<<dim3(512, 5), 1024>>>(fw_xy, fw2_xy);

    // ---- inverses ----
    k_invZ2<<<dim3(32, KM, 2*NB), 320>>>();
    k_invY <<<dim3(20, KM, NB), 512>>>();
    k_invAccXX<<<dim3(NZ, NY/2, NB), 512>>>();
    k_invAccYZ<<<dim3(NZ, NX/2, NB), 512>>>();

    // ---- feedforward (fused 1x1 conv + 2-layer MLP, f32x2) ----
    k_ff4<<<2560, 256>>>(x, w, wb, ffw0, ffb0, ffw1, ffb1, out);
}

// round 15
// speedup vs baseline: 2.0379x; 1.0054x over previous
#include <cuda_runtime.h>
#include <cstdint>

#define NB 4
#define NX 64
#define NY 64
#define NZ 40
#define C  32
#define KM 16
#define KZM 16
#define KYM 32

typedef unsigned long long u64t;

__device__ __forceinline__ u64t ffma2(u64t a, u64t b, u64t c) {
    u64t d;
    asm("fma.rn.f32x2 %0, %1, %2, %3;" : "=l"(d) : "l"(a), "l"(b), "l"(c));
    return d;
}
__device__ __forceinline__ u64t pkf2(float2 v) {
    u64t d; asm("mov.b64 %0, {%1, %2};" : "=l"(d) : "f"(v.x), "f"(v.y)); return d;
}
__device__ __forceinline__ float2 upk(u64t v) {
    float2 r; asm("mov.b64 {%0, %1}, %2;" : "=f"(r.x), "=f"(r.y) : "l"(v)); return r;
}

// ================= compile-time trig ======
constexpr double D_PI = 3.141592653589793238462643383279502884;

constexpr double tsin_(double x) {
    double x2 = x * x, t = x, s = x;
    for (int n = 1; n <= 13; n++) { t *= -x2 / ((2.0*n) * (2.0*n + 1.0)); s += t; }
    return s;
}
constexpr double tcos_(double x) {
    double x2 = x * x, t = 1.0, s = 1.0;
    for (int n = 1; n <= 13; n++) { t *= -x2 / ((2.0*n - 1.0) * (2.0*n)); s += t; }
    return s;
}
constexpr double ang_(int m, int N) {
    int mm = m % N;
    if (mm > N / 2) mm -= N;
    return 2.0 * D_PI * mm / N;
}

struct FXT { float c[16][64]; float s[16][64]; };
constexpr FXT mkFX() {
    FXT t{};
    for (int k = 0; k < 16; k++)
        for (int n = 0; n < 64; n++) {
            double a = ang_(k * n, 64);
            t.c[k][n] = (float)tcos_(a);
            t.s[k][n] = (float)(-tsin_(a));
        }
    return t;
}
__device__ constexpr FXT FX = mkFX();

struct FZT { float c[16][40]; float s[16][40]; };
constexpr FZT mkFZ() {
    FZT t{};
    for (int k = 0; k < 16; k++) {
        int f = (k < 8) ? k : k + 5;
        for (int n = 0; n < 40; n++) {
            double a = ang_(f * n, 40);
            t.c[k][n] = (float)tcos_(a);
            t.s[k][n] = (float)(-tsin_(a));
        }
    }
    return t;
}
__device__ constexpr FZT FZ = mkFZ();

struct FYT { float c[32][64]; float s[32][64]; };
constexpr FYT mkFY() {
    FYT t{};
    for (int k = 0; k < 32; k++) {
        int f = (k < 16) ? k : k + 1;
        for (int n = 0; n < 64; n++) {
            double a = ang_(f * n, 64);
            t.c[k][n] = (float)tcos_(a);
            t.s[k][n] = (float)(-tsin_(a));
        }
    }
    return t;
}
__device__ constexpr FYT FY = mkFY();

struct IXT { float c[16][64]; float s[16][64]; };
constexpr IXT mkIX() {
    IXT t{};
    for (int k = 0; k < 16; k++)
        for (int n = 0; n < 64; n++) {
            double a = ang_(k * n, 64);
            t.c[k][n] = (float)(tcos_(a) / 64.0);
            t.s[k][n] = (float)(tsin_(a) / 64.0);
        }
    return t;
}
__device__ constexpr IXT IX = mkIX();

struct IZT { float c[16][40]; float s[16][40]; };
constexpr IZT mkIZ() {
    IZT t{};
    for (int k = 0; k < 16; k++) {
        int f = (k < 8) ? k : k + 5;
        double w = (f == 0 || f == 20) ? 1.0 : 2.0;
        for (int n = 0; n < 40; n++) {
            double a = ang_(f * n, 40);
            t.c[k][n] = (float)(tcos_(a) * w / 40.0);
            t.s[k][n] = (float)(tsin_(a) * w / 40.0);
        }
    }
    return t;
}
__device__ constexpr IZT IZ = mkIZ();

struct IYT { float c[32][64]; float s[32][64]; };
constexpr IYT mkIY() {
    IYT t{};
    for (int k = 0; k < 32; k++) {
        int f = (k < 16) ? k : k + 1;
        double w = (f == 0 || f == 32) ? 1.0 : 2.0;
        for (int n = 0; n < 64; n++) {
            double a = ang_(f * n, 64);
            t.c[k][n] = (float)(tcos_(a) * w / 64.0);
            t.s[k][n] = (float)(tsin_(a) * w / 64.0);
        }
    }
    return t;
}
__device__ constexpr IYT IY = mkIY();

// ================= scratch =================
__device__ float2 g_Qx[(size_t)NB*KM*NY*NZ*C];
__device__ float2 g_P1[(size_t)NB*NX*NY*KZM*C];
__device__ float2 g_F [(size_t)256*256*C];        // xz modes
__device__ float2 g_Fxy[(size_t)512*160*C];       // xy modes
__device__ float2 g_Fyz[(size_t)256*256*C];       // yz modes
__device__ float2 g_R [(size_t)NB*64*NZ*KM*C];    // xz coefficient rows
__device__ float2 g_R2[(size_t)NB*64*NZ*KM*C];    // xy coefficient rows
__device__ float2 g_R3[(size_t)NB*64*NZ*KM*C];    // yz coefficient rows
__device__ float  g_acc[(size_t)NB*NX*NY*NZ*C];

// ================= forward x DFT (all 16 modes) ============================
__global__ void __launch_bounds__(256) k_fftx16(const float* __restrict__ x) {
    int w = threadIdx.x >> 5, i = threadIdx.x & 31;
    int z = blockIdx.x * 8 + w;
    int y = blockIdx.y, b = blockIdx.z;
    const float* px = x + (((size_t)b*NX*NY + y)*NZ + z)*C + i;
    float2 acc[16];
    #pragma unroll
    for (int k = 0; k < 16; k++) acc[k] = make_float2(0.f, 0.f);
    #pragma unroll
    for (int xx = 0; xx < NX; xx++) {
        float v = px[(size_t)xx*NY*NZ*C];
        #pragma unroll
        for (int k = 0; k < 16; k++) {
            acc[k].x = fmaf(v, FX.c[k][xx], acc[k].x);
            acc[k].y = fmaf(v, FX.s[k][xx], acc[k].y);
        }
    }
    #pragma unroll
    for (int k = 0; k < 16; k++)
        g_Qx[((((size_t)b*KM + k)*NY + y)*NZ + z)*C + i] = acc[k];
}

// ================= forward z rDFT (16 modes) ================================
__global__ void __launch_bounds__(256) k_rfftz(const float* __restrict__ x) {
    int w = threadIdx.x >> 5, i = threadIdx.x & 31;
    int y = blockIdx.x * 8 + w;
    int xx = blockIdx.y, b = blockIdx.z;
    const float* px = x + (((size_t)(b*NX+xx)*NY + y) * NZ) * C + i;
    float2 acc[16];
    #pragma unroll
    for (int k = 0; k < 16; k++) acc[k] = make_float2(0.f, 0.f);
    #pragma unroll
    for (int z = 0; z < NZ; z++) {
        float v = px[(size_t)z*C];
        #pragma unroll
        for (int k = 0; k < 16; k++) {
            acc[k].x = fmaf(v, FZ.c[k][z], acc[k].x);
            acc[k].y = fmaf(v, FZ.s[k][z], acc[k].y);
        }
    }
    float2* q = g_P1 + (((size_t)(b*NX+xx)*NY + y) * KZM) * C + i;
    #pragma unroll
    for (int k = 0; k < 16; k++) q[(size_t)k*C] = acc[k];
}

// ================= xz: z DFT of Qx ==========================================
__global__ void __launch_bounds__(256) k_zfftQ16() {
    int w = threadIdx.x >> 5, i = threadIdx.x & 31;
    int y = blockIdx.x * 8 + w;
    int kx = blockIdx.y, b = blockIdx.z;
    const float2* q = g_Qx + (((size_t)(b*KM+kx)*NY + y) * NZ) * C + i;
    float2 acc[16];
    #pragma unroll
    for (int k = 0; k < 16; k++) acc[k] = make_float2(0.f, 0.f);
    #pragma unroll
    for (int z = 0; z < NZ; z++) {
        float2 a = q[(size_t)z*C];
        #pragma unroll
        for (int k = 0; k < 16; k++) {
            float cc = FZ.c[k][z], ss = FZ.s[k][z];
            acc[k].x = fmaf(a.x, cc, acc[k].x);
            acc[k].x = fmaf(a.y, -ss, acc[k].x);
            acc[k].y = fmaf(a.x, ss, acc[k].y);
            acc[k].y = fmaf(a.y, cc, acc[k].y);
        }
    }
    #pragma unroll
    for (int k = 0; k < 16; k++) {
        int m = kx*KZM + k;
        g_F[((size_t)m*(NB*NY) + b*NY + y)*C + i] = acc[k];
    }
}

// ======= xy: y DFT (real axis), 16 modes per block-half, one launch =========
__global__ void __launch_bounds__(256) k_yfftQ16h() {
    int w = threadIdx.x >> 5, i = threadIdx.x & 31;
    int z = blockIdx.x * 8 + w;
    int kx = blockIdx.y;
    int bz = blockIdx.z;
    int M0 = (bz >= NB) ? 16 : 0;
    int b = bz & (NB - 1);
    const float2* q = g_Qx + (((size_t)(b*KM+kx)*NY) * NZ + z) * C + i;
    float2 acc[16];
    #pragma unroll
    for (int k = 0; k < 16; k++) acc[k] = make_float2(0.f, 0.f);
    #pragma unroll
    for (int y = 0; y < NY; y++) {
        float2 a = q[(size_t)y*NZ*C];
        if (M0 == 0) {
            #pragma unroll
            for (int k = 0; k < 16; k++) {
                float cc = FY.c[k][y], ss = FY.s[k][y];
                acc[k].x = fmaf(a.x, cc, acc[k].x);
                acc[k].x = fmaf(a.y, -ss, acc[k].x);
                acc[k].y = fmaf(a.x, ss, acc[k].y);
                acc[k].y = fmaf(a.y, cc, acc[k].y);
            }
        } else {
            #pragma unroll
            for (int k = 0; k < 16; k++) {
                float cc = FY.c[16+k][y], ss = FY.s[16+k][y];
                acc[k].x = fmaf(a.x, cc, acc[k].x);
                acc[k].x = fmaf(a.y, -ss, acc[k].x);
                acc[k].y = fmaf(a.x, ss, acc[k].y);
                acc[k].y = fmaf(a.y, cc, acc[k].y);
            }
        }
    }
    #pragma unroll
    for (int k = 0; k < 16; k++) {
        int m = kx*KYM + M0 + k;
        g_Fxy[((size_t)m*(NB*NZ) + b*NZ + z)*C + i] = acc[k];
    }
}

// ================= yz: y DFT of P1 ==========================================
__global__ void __launch_bounds__(256) k_yfftP16() {
    int w = threadIdx.x >> 5, i = threadIdx.x & 31;
    int kz = blockIdx.x * 8 + w;
    int xx = blockIdx.y, b = blockIdx.z;
    const float2* p = g_P1 + (((size_t)(b*NX+xx)*NY) * KZM + kz) * C + i;
    float2 acc[16];
    #pragma unroll
    for (int k = 0; k < 16; k++) acc[k] = make_float2(0.f, 0.f);
    #pragma unroll
    for (int y = 0; y < NY; y++) {
        float2 a = p[(size_t)y*KZM*C];
        #pragma unroll
        for (int k = 0; k < 16; k++) {
            float cc = FX.c[k][y], ss = FX.s[k][y];
            acc[k].x = fmaf(a.x, cc, acc[k].x);
            acc[k].x = fmaf(a.y, -ss, acc[k].x);
            acc[k].y = fmaf(a.x, ss, acc[k].y);
            acc[k].y = fmaf(a.y, cc, acc[k].y);
        }
    }
    #pragma unroll
    for (int k = 0; k < 16; k++) {
        int m = k*KZM + kz;
        g_Fyz[((size_t)m*(NB*NX) + b*NX + xx)*C + i] = acc[k];
    }
}

// ====== combined per-mode mix for xz (modes 0..255) + yz (256..511), D=8 ====
__global__ void __launch_bounds__(1024) k_mixZZ(const float* __restrict__ fw_xz,
                                                const float* __restrict__ fw2_xz,
                                                const float* __restrict__ fw_yz,
                                                const float* __restrict__ fw2_yz) {
    __shared__ float2 Ws[C*C];
    __shared__ float2 Fs[32*C];
    int mm = blockIdx.x, chunk = blockIdx.y;
    int branch = mm >> 8;
    int m = mm & 255;
    float2* Fb = branch ? g_Fyz : g_F;
    const float* fw  = branch ? fw_yz  : fw_xz;
    const float* fw2 = branch ? fw2_yz : fw2_xz;
    int tid = threadIdx.x;
    const int D = 8;
    int kx = m / (2*D), km = m % (2*D);
    const float* W = (km < D) ? fw : fw2;
    int kk = (km < D) ? km : km - D;
    int o = tid & 31, rr = tid >> 5;
    {
        int i = rr;
        size_t base = ((((size_t)i*C + o)*KM + kx)*D + kk) * 2;
        Ws[i*C + o] = make_float2(W[base], W[base + 1]);
    }
    size_t idx = ((size_t)m*256 + chunk*32 + rr)*C + o;
    Fs[rr*C + o] = Fb[idx];
    __syncthreads();
    float re = 0.f, im = 0.f;
    #pragma unroll
    for (int i = 0; i < C; i++) {
        float2 a = Fs[rr*C + i];
        float2 w = Ws[i*C + o];
        re += a.x*w.x - a.y*w.y;
        im += a.x*w.y + a.y*w.x;
    }
    Fb[idx] = make_float2(re, im);
}

// ================= xy per-mode mix (D=16) ===================================
__global__ void __launch_bounds__(1024) k_mixXY(const float* __restrict__ fw,
                                                const float* __restrict__ fw2) {
    __shared__ float2 Ws[C*C];
    __shared__ float2 Fs[32*C];
    int m = blockIdx.x, chunk = blockIdx.y;
    int tid = threadIdx.x;
    const int D = 16;
    int kx = m / (2*D), km = m % (2*D);
    const float* W = (km < D) ? fw : fw2;
    int kk = (km < D) ? km : km - D;
    int o = tid & 31, rr = tid >> 5;
    {
        int i = rr;
        size_t base = ((((size_t)i*C + o)*KM + kx)*D + kk) * 2;
        Ws[i*C + o] = make_float2(W[base], W[base + 1]);
    }
    size_t idx = ((size_t)m*160 + chunk*32 + rr)*C + o;
    Fs[rr*C + o] = g_Fxy[idx];
    __syncthreads();
    float re = 0.f, im = 0.f;
    #pragma unroll
    for (int i = 0; i < C; i++) {
        float2 a = Fs[rr*C + i];
        float2 w = Ws[i*C + o];
        re += a.x*w.x - a.y*w.y;
        im += a.x*w.y + a.y*w.x;
    }
    g_Fxy[idx] = make_float2(re, im);
}

// ====== combined inverse over z for xz (bz<NB) and yz (bz>=NB) ==============
template<int Z0>
__device__ __forceinline__ void invZ_body(const float2* __restrict__ Fb,
                                          float2* __restrict__ Rout,
                                          int b, int kc, int u, int o) {
    float2 acc[8];
    #pragma unroll
    for (int j = 0; j < 8; j++) acc[j] = make_float2(0.f, 0.f);
    #pragma unroll
    for (int kz = 0; kz < KZM; kz++) {
        float2 g = Fb[((size_t)(kc*KZM + kz)*(NB*64) + b*64 + u)*C + o];
        #pragma unroll
        for (int j = 0; j < 8; j++) {
            float cc = IZ.c[kz][Z0+j], ss = IZ.s[kz][Z0+j];
            acc[j].x = fmaf(g.x, cc, acc[j].x);
            acc[j].x = fmaf(g.y, -ss, acc[j].x);
            acc[j].y = fmaf(g.x, ss, acc[j].y);
            acc[j].y = fmaf(g.y, cc, acc[j].y);
        }
    }
    #pragma unroll
    for (int j = 0; j < 8; j++)
        Rout[(((size_t)(b*64 + u)*NZ + Z0 + j)*KM + kc)*C + o] = acc[j];
}
__global__ void __launch_bounds__(320) k_invZ2() {
    int w = threadIdx.x >> 5, o = threadIdx.x & 31;
    int u = blockIdx.x * 2 + (w / 5);
    int slot = w % 5;
    int kc = blockIdx.y;
    int bz = blockIdx.z;
    int branch = (bz >= NB);
    int b = bz & (NB - 1);
    const float2* Fb = branch ? g_Fyz : g_F;
    float2* Rout = branch ? g_R3 : g_R;
    switch (slot) {
        case 0: invZ_body<0 >(Fb, Rout, b, kc, u, o); break;
        case 1: invZ_body<8 >(Fb, Rout, b, kc, u, o); break;
        case 2: invZ_body<16>(Fb, Rout, b, kc, u, o); break;
        case 3: invZ_body<24>(Fb, Rout, b, kc, u, o); break;
        default: invZ_body<32>(Fb, Rout, b, kc, u, o); break;
    }
}

// ================= inverse over y real axis (32 modes -> 64 y), xy ==========
template<int Y0>
__device__ __forceinline__ void invY_body(int b, int kx, int z, int o) {
    float2 acc[8];
    #pragma unroll
    for (int j = 0; j < 8; j++) acc[j] = make_float2(0.f, 0.f);
    #pragma unroll
    for (int ky = 0; ky < KYM; ky++) {
        float2 g = g_Fxy[((size_t)(kx*KYM + ky)*(NB*NZ) + b*NZ + z)*C + o];
        #pragma unroll
        for (int j = 0; j < 8; j++) {
            float cc = IY.c[ky][Y0+j], ss = IY.s[ky][Y0+j];
            acc[j].x = fmaf(g.x, cc, acc[j].x);
            acc[j].x = fmaf(g.y, -ss, acc[j].x);
            acc[j].y = fmaf(g.x, ss, acc[j].y);
            acc[j].y = fmaf(g.y, cc, acc[j].y);
        }
    }
    #pragma unroll
    for (int j = 0; j < 8; j++)
        g_R2[(((size_t)(b*NZ + z)*NY + Y0 + j)*KM + kx)*C + o] = acc[j];
}
__global__ void __launch_bounds__(512) k_invY() {
    int w = threadIdx.x >> 5, o = threadIdx.x & 31;
    int z = blockIdx.x * 2 + (w >> 3);
    int slot = w & 7;
    int kx = blockIdx.y, b = blockIdx.z;
    switch (slot) {
        case 0: invY_body<0 >(b, kx, z, o); break;
        case 1: invY_body<8 >(b, kx, z, o); break;
        case 2: invY_body<16>(b, kx, z, o); break;
        case 3: invY_body<24>(b, kx, z, o); break;
        case 4: invY_body<32>(b, kx, z, o); break;
        case 5: invY_body<40>(b, kx, z, o); break;
        case 6: invY_body<48>(b, kx, z, o); break;
        default: invY_body<56>(b, kx, z, o); break;
    }
}

// ====== fused inverse-x for xz + xy: acc = sum_k (R_A[k]+R_B[k])·IX[k][x] ===
template<int N0>
__device__ __forceinline__ void invAccXX_body(size_t rrowA, size_t rrowB,
                                              size_t obase, int o) {
    float2 s[KM];
    #pragma unroll
    for (int k = 0; k < KM; k++) {
        float2 a = g_R [rrowA*(KM*C) + (size_t)k*C + o];
        float2 b = g_R2[rrowB*(KM*C) + (size_t)k*C + o];
        s[k] = make_float2(a.x + b.x, a.y + b.y);
    }
    float acc[8];
    #pragma unroll
    for (int j = 0; j < 8; j++) acc[j] = 0.f;
    #pragma unroll
    for (int k = 0; k < KM; k++) {
        #pragma unroll
        for (int j = 0; j < 8; j++) {
            acc[j] = fmaf(s[k].x, IX.c[k][N0+j], acc[j]);
            acc[j] = fmaf(s[k].y, -IX.s[k][N0+j], acc[j]);
        }
    }
    #pragma unroll
    for (int j = 0; j < 8; j++)
        g_acc[obase + (size_t)(N0+j)*(NY*NZ*C) + o] = acc[j];
}
__global__ void __launch_bounds__(512) k_invAccXX() {
    int w = threadIdx.x >> 5, o = threadIdx.x & 31;
    int r = w >> 3, slot = w & 7;
    int b = blockIdx.z;
    int z = blockIdx.x, y = blockIdx.y*2 + r;
    size_t rrowA = ((size_t)(b*NY + y))*NZ + z;
    size_t rrowB = ((size_t)(b*NZ + z))*NY + y;
    size_t obase = (((size_t)b*NX*NY + y)*NZ + z)*C;
    switch (slot) {
        case 0: invAccXX_body<0 >(rrowA, rrowB, obase, o); break;
        case 1: invAccXX_body<8 >(rrowA, rrowB, obase, o); break;
        case 2: invAccXX_body<16>(rrowA, rrowB, obase, o); break;
        case 3: invAccXX_body<24>(rrowA, rrowB, obase, o); break;
        case 4: invAccXX_body<32>(rrowA, rrowB, obase, o); break;
        case 5: invAccXX_body<40>(rrowA, rrowB, obase, o); break;
        case 6: invAccXX_body<48>(rrowA, rrowB, obase, o); break;
        default: invAccXX_body<56>(rrowA, rrowB, obase, o); break;
    }
}

// ================= yz inverse over y (16 modes -> 64), Re(), += =============
template<int N0>
__device__ __forceinline__ void invAccYZ_body(size_t rrow, size_t obase, int o) {
    float acc[8];
    #pragma unroll
    for (int j = 0; j < 8; j++) acc[j] = 0.f;
    #pragma unroll
    for (int k = 0; k < KM; k++) {
        float2 r = g_R3[rrow*(KM*C) + (size_t)k*C + o];
        #pragma unroll
        for (int j = 0; j < 8; j++) {
            acc[j] = fmaf(r.x, IX.c[k][N0+j], acc[j]);
            acc[j] = fmaf(r.y, -IX.s[k][N0+j], acc[j]);
        }
    }
    #pragma unroll
    for (int j = 0; j < 8; j++)
        g_acc[obase + (size_t)(N0+j)*(NZ*C) + o] += acc[j];
}
__global__ void __launch_bounds__(512) k_invAccYZ() {
    int w = threadIdx.x >> 5, o = threadIdx.x & 31;
    int r = w >> 3, slot = w & 7;
    int b = blockIdx.z;
    int z = blockIdx.x, xx = blockIdx.y*2 + r;
    size_t rrow = ((size_t)(b*NX + xx))*NZ + z;
    size_t obase = (((size_t)(b*NX + xx)*NY)*NZ + z)*C;
    switch (slot) {
        case 0: invAccYZ_body<0 >(rrow, obase, o); break;
        case 1: invAccYZ_body<8 >(rrow, obase, o); break;
        case 2: invAccYZ_body<16>(rrow, obase, o); break;
        case 3: invAccYZ_body<24>(rrow, obase, o); break;
        case 4: invAccYZ_body<32>(rrow, obase, o); break;
        case 5: invAccYZ_body<40>(rrow, obase, o); break;
        case 6: invAccYZ_body<48>(rrow, obase, o); break;
        default: invAccYZ_body<56>(rrow, obase, o); break;
    }
}

// ==== feedforward + fused conv — packed f32x2 along reduction dim ===========
__global__ void __launch_bounds__(256) k_ff4(const float* __restrict__ x,
                                             const float* __restrict__ wc_,
                                             const float* __restrict__ bc_,
                                             const float* __restrict__ w0,
                                             const float* __restrict__ b0,
                                             const float* __restrict__ w1,
                                             const float* __restrict__ b1,
                                             float* __restrict__ out) {
    __shared__ __align__(16) u64t wcp [16*32];
    __shared__ __align__(16) u64t w0pa[16*32];
    __shared__ __align__(16) u64t w0pb[16*32];
    __shared__ __align__(16) u64t w1p [32*32];
    __shared__ float bcs[C], b0s[64], b1s[C];
    __shared__ __align__(16) float xs[8][8][C];
    __shared__ __align__(16) float h1s[8][8][64];
    int tid = threadIdx.x;
    const float2* wc2 = (const float2*)wc_;
    const float2* w02 = (const float2*)w0;
    const float2* w12 = (const float2*)w1;
    for (int t = tid; t < 16*32; t += 256) {
        int i2 = t >> 5, o = t & 31;
        wcp [t] = pkf2(wc2[o*16 + i2]);
        w0pa[t] = pkf2(w02[o*16 + i2]);
        w0pb[t] = pkf2(w02[(o + 32)*16 + i2]);
    }
    for (int t = tid; t < 32*32; t += 256) {
        int h2 = t >> 5, o = t & 31;
        w1p[t] = pkf2(w12[o*32 + h2]);
    }
    if (tid < C)  bcs[tid] = bc_[tid];
    if (tid < 64) b0s[tid] = b0[tid];
    if (tid < C)  b1s[tid] = b1[tid];
    __syncthreads();
    int lane = tid & 31, w = tid >> 5;
    size_t t0 = ((size_t)blockIdx.x * 8 + w) * 32;
    for (int g = 0; g < 4; g++) {
        size_t tb = t0 + g * 8;
        float ga[8];
        #pragma unroll
        for (int r = 0; r < 8; r++) {
            xs[w][r][lane] = x[(tb + r)*C + lane];
            ga[r] = g_acc[(tb + r)*C + lane];
        }
        __syncwarp();
        u64t pc[8];
        #pragma unroll
        for (int r = 0; r < 8; r++) pc[r] = 0ull;
        #pragma unroll
        for (int i2 = 0; i2 < 16; i2 += 2) {
            u64t wv0 = wcp[i2*32 + lane], wv1 = wcp[(i2+1)*32 + lane];
            #pragma unroll
            for (int r = 0; r < 8; r++) {
                ulonglong2 a2 = *reinterpret_cast<const ulonglong2*>(&xs[w][r][i2*2]);
                pc[r] = ffma2(a2.x, wv0, pc[r]);
                pc[r] = ffma2(a2.y, wv1, pc[r]);
            }
        }
        float hv[8];
        #pragma unroll
        for (int r = 0; r < 8; r++) {
            float2 p = upk(pc[r]);
            hv[r] = ga[r] + bcs[lane] + p.x + p.y;
        }
        __syncwarp();
        #pragma unroll
        for (int r = 0; r < 8; r++) xs[w][r][lane] = hv[r];
        __syncwarp();
        u64t pa[8], pb[8];
        #pragma unroll
        for (int r = 0; r < 8; r++) { pa[r] = 0ull; pb[r] = 0ull; }
        #pragma unroll
        for (int i2 = 0; i2 < 16; i2 += 2) {
            u64t wa0 = w0pa[i2*32 + lane], wa1 = w0pa[(i2+1)*32 + lane];
            u64t wb0 = w0pb[i2*32 + lane], wb1 = w0pb[(i2+1)*32 + lane];
            #pragma unroll
            for (int r = 0; r < 8; r++) {
                ulonglong2 a2 = *reinterpret_cast<const ulonglong2*>(&xs[w][r][i2*2]);
                pa[r] = ffma2(a2.x, wa0, pa[r]);
                pa[r] = ffma2(a2.y, wa1, pa[r]);
                pb[r] = ffma2(a2.x, wb0, pb[r]);
                pb[r] = ffma2(a2.y, wb1, pb[r]);
            }
        }
        #pragma unroll
        for (int r = 0; r < 8; r++) {
            float2 qa = upk(pa[r]), qb = upk(pb[r]);
            h1s[w][r][lane]      = fmaxf(b0s[lane]      + qa.x + qa.y, 0.f);
            h1s[w][r][lane + 32] = fmaxf(b0s[lane + 32] + qb.x + qb.y, 0.f);
        }
        __syncwarp();
        u64t pv[8];
        #pragma unroll
        for (int r = 0; r < 8; r++) pv[r] = 0ull;
        #pragma unroll
        for (int h2 = 0; h2 < 32; h2 += 2) {
            u64t wv0 = w1p[h2*32 + lane], wv1 = w1p[(h2+1)*32 + lane];
            #pragma unroll
            for (int r = 0; r < 8; r++) {
                ulonglong2 a2 = *reinterpret_cast<const ulonglong2*>(&h1s[w][r][h2*2]);
                pv[r] = ffma2(a2.x, wv0, pv[r]);
                pv[r] = ffma2(a2.y, wv1, pv[r]);
            }
        }
        #pragma unroll
        for (int r = 0; r < 8; r++) {
            float2 p = upk(pv[r]);
            out[(tb + r)*C + lane] = b1s[lane] + p.x + p.y;
        }
        __syncwarp();
    }
}

extern "C" void kernel_launch(void* const* d_in, const int* in_sizes, int n_in,
                              void* d_out, int out_size) {
    const float* x      = (const float*)d_in[0];
    const float* w      = (const float*)d_in[1];
    const float* wb     = (const float*)d_in[2];
    const float* fw_xy  = (const float*)d_in[3];
    const float* fw_yz  = (const float*)d_in[4];
    const float* fw_xz  = (const float*)d_in[5];
    const float* fw2_xy = (const float*)d_in[6];
    const float* fw2_yz = (const float*)d_in[7];
    const float* fw2_xz = (const float*)d_in[8];
    const float* ffw0   = (const float*)d_in[9];
    const float* ffb0   = (const float*)d_in[10];
    const float* ffw1   = (const float*)d_in[11];
    const float* ffb1   = (const float*)d_in[12];
    float* out = (float*)d_out;

    // ---- forwards ----
    k_fftx16  <<<dim3(5, NY, NB), 256>>>(x);
    k_rfftz   <<<dim3(8, NX, NB), 256>>>(x);
    k_zfftQ16 <<<dim3(8, KM, NB), 256>>>();
    k_yfftQ16h<<<dim3(5, KM, 2*NB), 256>>>();
    k_yfftP16 <<<dim3(2, NX, NB), 256>>>();

    // ---- mixes ----
    k_mixZZ<<<dim3(512, 8), 1024>>>(fw_xz, fw2_xz, fw_yz, fw2_yz);
    k_mixXY<<<dim3(512, 5), 1024>>>(fw_xy, fw2_xy);

    // ---- inverses ----
    k_invZ2<<<dim3(32, KM, 2*NB), 320>>>();
    k_invY <<<dim3(20, KM, NB), 512>>>();
    k_invAccXX<<<dim3(NZ, NY/2, NB), 512>>>();
    k_invAccYZ<<<dim3(NZ, NX/2, NB), 512>>>();

    // ---- feedforward (fused 1x1 conv + 2-layer MLP, f32x2) ----
    k_ff4<<<2560, 256>>>(x, w, wb, ffw0, ffb0, ffw1, ffb1, out);
}

// round 16
// speedup vs baseline: 2.0483x; 1.0051x over previous
#include <cuda_runtime.h>
#include <cstdint>

#define NB 4
#define NX 64
#define NY 64
#define NZ 40
#define C  32
#define KM 16
#define KZM 16
#define KYM 32

typedef unsigned long long u64t;

__device__ __forceinline__ u64t ffma2(u64t a, u64t b, u64t c) {
    u64t d;
    asm("fma.rn.f32x2 %0, %1, %2, %3;" : "=l"(d) : "l"(a), "l"(b), "l"(c));
    return d;
}
__device__ __forceinline__ u64t pkf2(float2 v) {
    u64t d; asm("mov.b64 %0, {%1, %2};" : "=l"(d) : "f"(v.x), "f"(v.y)); return d;
}
__device__ __forceinline__ float2 upk(u64t v) {
    float2 r; asm("mov.b64 {%0, %1}, %2;" : "=f"(r.x), "=f"(r.y) : "l"(v)); return r;
}

// ================= compile-time trig ======
constexpr double D_PI = 3.141592653589793238462643383279502884;

constexpr double tsin_(double x) {
    double x2 = x * x, t = x, s = x;
    for (int n = 1; n <= 13; n++) { t *= -x2 / ((2.0*n) * (2.0*n + 1.0)); s += t; }
    return s;
}
constexpr double tcos_(double x) {
    double x2 = x * x, t = 1.0, s = 1.0;
    for (int n = 1; n <= 13; n++) { t *= -x2 / ((2.0*n - 1.0) * (2.0*n)); s += t; }
    return s;
}
constexpr double ang_(int m, int N) {
    int mm = m % N;
    if (mm > N / 2) mm -= N;
    return 2.0 * D_PI * mm / N;
}

struct FXT { float c[16][64]; float s[16][64]; };
constexpr FXT mkFX() {
    FXT t{};
    for (int k = 0; k < 16; k++)
        for (int n = 0; n < 64; n++) {
            double a = ang_(k * n, 64);
            t.c[k][n] = (float)tcos_(a);
            t.s[k][n] = (float)(-tsin_(a));
        }
    return t;
}
__device__ constexpr FXT FX = mkFX();

struct FZT { float c[16][40]; float s[16][40]; };
constexpr FZT mkFZ() {
    FZT t{};
    for (int k = 0; k < 16; k++) {
        int f = (k < 8) ? k : k + 5;
        for (int n = 0; n < 40; n++) {
            double a = ang_(f * n, 40);
            t.c[k][n] = (float)tcos_(a);
            t.s[k][n] = (float)(-tsin_(a));
        }
    }
    return t;
}
__device__ constexpr FZT FZ = mkFZ();

struct FYT { float c[32][64]; float s[32][64]; };
constexpr FYT mkFY() {
    FYT t{};
    for (int k = 0; k < 32; k++) {
        int f = (k < 16) ? k : k + 1;
        for (int n = 0; n < 64; n++) {
            double a = ang_(f * n, 64);
            t.c[k][n] = (float)tcos_(a);
            t.s[k][n] = (float)(-tsin_(a));
        }
    }
    return t;
}
__device__ constexpr FYT FY = mkFY();

struct IXT { float c[16][64]; float s[16][64]; };
constexpr IXT mkIX() {
    IXT t{};
    for (int k = 0; k < 16; k++)
        for (int n = 0; n < 64; n++) {
            double a = ang_(k * n, 64);
            t.c[k][n] = (float)(tcos_(a) / 64.0);
            t.s[k][n] = (float)(tsin_(a) / 64.0);
        }
    return t;
}
__device__ constexpr IXT IX = mkIX();

struct IZT { float c[16][40]; float s[16][40]; };
constexpr IZT mkIZ() {
    IZT t{};
    for (int k = 0; k < 16; k++) {
        int f = (k < 8) ? k : k + 5;
        double w = (f == 0 || f == 20) ? 1.0 : 2.0;
        for (int n = 0; n < 40; n++) {
            double a = ang_(f * n, 40);
            t.c[k][n] = (float)(tcos_(a) * w / 40.0);
            t.s[k][n] = (float)(tsin_(a) * w / 40.0);
        }
    }
    return t;
}
__device__ constexpr IZT IZ = mkIZ();

struct IYT { float c[32][64]; float s[32][64]; };
constexpr IYT mkIY() {
    IYT t{};
    for (int k = 0; k < 32; k++) {
        int f = (k < 16) ? k : k + 1;
        double w = (f == 0 || f == 32) ? 1.0 : 2.0;
        for (int n = 0; n < 64; n++) {
            double a = ang_(f * n, 64);
            t.c[k][n] = (float)(tcos_(a) * w / 64.0);
            t.s[k][n] = (float)(tsin_(a) * w / 64.0);
        }
    }
    return t;
}
__device__ constexpr IYT IY = mkIY();

// ================= scratch =================
__device__ float2 g_Qx[(size_t)NB*KM*NY*NZ*C];
__device__ float2 g_P1[(size_t)NB*NX*NY*KZM*C];
__device__ float2 g_F [(size_t)256*256*C];        // xz modes
__device__ float2 g_Fxy[(size_t)512*160*C];       // xy modes
__device__ float2 g_Fyz[(size_t)256*256*C];       // yz modes
__device__ float2 g_R [(size_t)NB*64*NZ*KM*C];    // xz coefficient rows
__device__ float2 g_R2[(size_t)NB*64*NZ*KM*C];    // xy coefficient rows
__device__ float2 g_R3[(size_t)NB*64*NZ*KM*C];    // yz coefficient rows
__device__ float  g_acc[(size_t)NB*NX*NY*NZ*C];

// ================= forward x DFT (all 16 modes) ============================
__global__ void __launch_bounds__(256) k_fftx16(const float* __restrict__ x) {
    int w = threadIdx.x >> 5, i = threadIdx.x & 31;
    int z = blockIdx.x * 8 + w;
    int y = blockIdx.y, b = blockIdx.z;
    const float* px = x + (((size_t)b*NX*NY + y)*NZ + z)*C + i;
    float2 acc[16];
    #pragma unroll
    for (int k = 0; k < 16; k++) acc[k] = make_float2(0.f, 0.f);
    #pragma unroll
    for (int xx = 0; xx < NX; xx++) {
        float v = px[(size_t)xx*NY*NZ*C];
        #pragma unroll
        for (int k = 0; k < 16; k++) {
            acc[k].x = fmaf(v, FX.c[k][xx], acc[k].x);
            acc[k].y = fmaf(v, FX.s[k][xx], acc[k].y);
        }
    }
    #pragma unroll
    for (int k = 0; k < 16; k++)
        g_Qx[((((size_t)b*KM + k)*NY + y)*NZ + z)*C + i] = acc[k];
}

// ================= forward z rDFT (16 modes) ================================
__global__ void __launch_bounds__(256) k_rfftz(const float* __restrict__ x) {
    int w = threadIdx.x >> 5, i = threadIdx.x & 31;
    int y = blockIdx.x * 8 + w;
    int xx = blockIdx.y, b = blockIdx.z;
    const float* px = x + (((size_t)(b*NX+xx)*NY + y) * NZ) * C + i;
    float2 acc[16];
    #pragma unroll
    for (int k = 0; k < 16; k++) acc[k] = make_float2(0.f, 0.f);
    #pragma unroll
    for (int z = 0; z < NZ; z++) {
        float v = px[(size_t)z*C];
        #pragma unroll
        for (int k = 0; k < 16; k++) {
            acc[k].x = fmaf(v, FZ.c[k][z], acc[k].x);
            acc[k].y = fmaf(v, FZ.s[k][z], acc[k].y);
        }
    }
    float2* q = g_P1 + (((size_t)(b*NX+xx)*NY + y) * KZM) * C + i;
    #pragma unroll
    for (int k = 0; k < 16; k++) q[(size_t)k*C] = acc[k];
}

// ================= xz: z DFT of Qx ==========================================
__global__ void __launch_bounds__(256) k_zfftQ16() {
    int w = threadIdx.x >> 5, i = threadIdx.x & 31;
    int y = blockIdx.x * 8 + w;
    int kx = blockIdx.y, b = blockIdx.z;
    const float2* q = g_Qx + (((size_t)(b*KM+kx)*NY + y) * NZ) * C + i;
    float2 acc[16];
    #pragma unroll
    for (int k = 0; k < 16; k++) acc[k] = make_float2(0.f, 0.f);
    #pragma unroll
    for (int z = 0; z < NZ; z++) {
        float2 a = q[(size_t)z*C];
        #pragma unroll
        for (int k = 0; k < 16; k++) {
            float cc = FZ.c[k][z], ss = FZ.s[k][z];
            acc[k].x = fmaf(a.x, cc, acc[k].x);
            acc[k].x = fmaf(a.y, -ss, acc[k].x);
            acc[k].y = fmaf(a.x, ss, acc[k].y);
            acc[k].y = fmaf(a.y, cc, acc[k].y);
        }
    }
    #pragma unroll
    for (int k = 0; k < 16; k++) {
        int m = kx*KZM + k;
        g_F[((size_t)m*(NB*NY) + b*NY + y)*C + i] = acc[k];
    }
}

// ======= xy: y DFT (real axis), 16 modes per block-half, one launch =========
__global__ void __launch_bounds__(256) k_yfftQ16h() {
    int w = threadIdx.x >> 5, i = threadIdx.x & 31;
    int z = blockIdx.x * 8 + w;
    int kx = blockIdx.y;
    int bz = blockIdx.z;
    int M0 = (bz >= NB) ? 16 : 0;
    int b = bz & (NB - 1);
    const float2* q = g_Qx + (((size_t)(b*KM+kx)*NY) * NZ + z) * C + i;
    float2 acc[16];
    #pragma unroll
    for (int k = 0; k < 16; k++) acc[k] = make_float2(0.f, 0.f);
    #pragma unroll
    for (int y = 0; y < NY; y++) {
        float2 a = q[(size_t)y*NZ*C];
        if (M0 == 0) {
            #pragma unroll
            for (int k = 0; k < 16; k++) {
                float cc = FY.c[k][y], ss = FY.s[k][y];
                acc[k].x = fmaf(a.x, cc, acc[k].x);
                acc[k].x = fmaf(a.y, -ss, acc[k].x);
                acc[k].y = fmaf(a.x, ss, acc[k].y);
                acc[k].y = fmaf(a.y, cc, acc[k].y);
            }
        } else {
            #pragma unroll
            for (int k = 0; k < 16; k++) {
                float cc = FY.c[16+k][y], ss = FY.s[16+k][y];
                acc[k].x = fmaf(a.x, cc, acc[k].x);
                acc[k].x = fmaf(a.y, -ss, acc[k].x);
                acc[k].y = fmaf(a.x, ss, acc[k].y);
                acc[k].y = fmaf(a.y, cc, acc[k].y);
            }
        }
    }
    #pragma unroll
    for (int k = 0; k < 16; k++) {
        int m = kx*KYM + M0 + k;
        g_Fxy[((size_t)m*(NB*NZ) + b*NZ + z)*C + i] = acc[k];
    }
}

// ================= yz: y DFT of P1 ==========================================
__global__ void __launch_bounds__(256) k_yfftP16() {
    int w = threadIdx.x >> 5, i = threadIdx.x & 31;
    int kz = blockIdx.x * 8 + w;
    int xx = blockIdx.y, b = blockIdx.z;
    const float2* p = g_P1 + (((size_t)(b*NX+xx)*NY) * KZM + kz) * C + i;
    float2 acc[16];
    #pragma unroll
    for (int k = 0; k < 16; k++) acc[k] = make_float2(0.f, 0.f);
    #pragma unroll
    for (int y = 0; y < NY; y++) {
        float2 a = p[(size_t)y*KZM*C];
        #pragma unroll
        for (int k = 0; k < 16; k++) {
            float cc = FX.c[k][y], ss = FX.s[k][y];
            acc[k].x = fmaf(a.x, cc, acc[k].x);
            acc[k].x = fmaf(a.y, -ss, acc[k].x);
            acc[k].y = fmaf(a.x, ss, acc[k].y);
            acc[k].y = fmaf(a.y, cc, acc[k].y);
        }
    }
    #pragma unroll
    for (int k = 0; k < 16; k++) {
        int m = k*KZM + kz;
        g_Fyz[((size_t)m*(NB*NX) + b*NX + xx)*C + i] = acc[k];
    }
}

// ====== planar f32x2 mix body: 4 packed bilinear accumulators ===============
__device__ __forceinline__ void mix_body(const float* __restrict__ W,
                                         int kx, int D, int kk,
                                         float2* __restrict__ Fb,
                                         int rows, int row0) {
    __shared__ __align__(16) float WsRe[32*34];
    __shared__ __align__(16) float WsIm[32*34];
    __shared__ __align__(16) float FsRe[32*32];
    __shared__ __align__(16) float FsIm[32*32];
    int tid = threadIdx.x;
    int o = tid & 31, rr = tid >> 5;
    {
        // load weights transposed: Ws[o][i], o = rr slot index here
        int oo = tid >> 5, ii = tid & 31;
        size_t base = ((((size_t)ii*C + oo)*KM + kx)*D + kk) * 2;
        WsRe[oo*34 + ii] = W[base];
        WsIm[oo*34 + ii] = W[base + 1];
        // load F row planar
        float2 a = Fb[(size_t)(row0 + oo)*C + ii];   // oo = row slot, ii = channel
        FsRe[oo*32 + ii] = a.x;
        FsIm[oo*32 + ii] = a.y;
    }
    __syncthreads();
    u64t sRR = 0ull, sII = 0ull, sRI = 0ull, sIR = 0ull;
    #pragma unroll
    for (int i2 = 0; i2 < 16; i2++) {
        u64t aRe = *(const u64t*)&FsRe[rr*32 + 2*i2];
        u64t aIm = *(const u64t*)&FsIm[rr*32 + 2*i2];
        u64t wRe = *(const u64t*)&WsRe[o*34 + 2*i2];
        u64t wIm = *(const u64t*)&WsIm[o*34 + 2*i2];
        sRR = ffma2(aRe, wRe, sRR);
        sII = ffma2(aIm, wIm, sII);
        sRI = ffma2(aRe, wIm, sRI);
        sIR = ffma2(aIm, wRe, sIR);
    }
    float2 prr = upk(sRR), pii = upk(sII), pri = upk(sRI), pir = upk(sIR);
    float re = (prr.x + prr.y) - (pii.x + pii.y);
    float im = (pri.x + pri.y) + (pir.x + pir.y);
    Fb[(size_t)(row0 + rr)*C + o] = make_float2(re, im);
}

// ====== combined per-mode mix for xz (modes 0..255) + yz (256..511), D=8 ====
__global__ void __launch_bounds__(1024) k_mixZZ(const float* __restrict__ fw_xz,
                                                const float* __restrict__ fw2_xz,
                                                const float* __restrict__ fw_yz,
                                                const float* __restrict__ fw2_yz) {
    int mm = blockIdx.x, chunk = blockIdx.y;
    int branch = mm >> 8;
    int m = mm & 255;
    float2* Fb = (branch ? g_Fyz : g_F) + (size_t)m*256*C;
    const float* fw  = branch ? fw_yz  : fw_xz;
    const float* fw2 = branch ? fw2_yz : fw2_xz;
    const int D = 8;
    int kx = m / (2*D), km = m % (2*D);
    const float* W = (km < D) ? fw : fw2;
    int kk = (km < D) ? km : km - D;
    mix_body(W, kx, D, kk, Fb, 256, chunk*32);
}

// ================= xy per-mode mix (D=16) ===================================
__global__ void __launch_bounds__(1024) k_mixXY(const float* __restrict__ fw,
                                                const float* __restrict__ fw2) {
    int m = blockIdx.x, chunk = blockIdx.y;
    const int D = 16;
    int kx = m / (2*D), km = m % (2*D);
    const float* W = (km < D) ? fw : fw2;
    int kk = (km < D) ? km : km - D;
    mix_body(W, kx, D, kk, g_Fxy + (size_t)m*160*C, 160, chunk*32);
}

// ====== combined inverse over z for xz (bz<NB) and yz (bz>=NB) ==============
template<int Z0>
__device__ __forceinline__ void invZ_body(const float2* __restrict__ Fb,
                                          float2* __restrict__ Rout,
                                          int b, int kc, int u, int o) {
    float2 acc[8];
    #pragma unroll
    for (int j = 0; j < 8; j++) acc[j] = make_float2(0.f, 0.f);
    #pragma unroll
    for (int kz = 0; kz < KZM; kz++) {
        float2 g = Fb[((size_t)(kc*KZM + kz)*(NB*64) + b*64 + u)*C + o];
        #pragma unroll
        for (int j = 0; j < 8; j++) {
            float cc = IZ.c[kz][Z0+j], ss = IZ.s[kz][Z0+j];
            acc[j].x = fmaf(g.x, cc, acc[j].x);
            acc[j].x = fmaf(g.y, -ss, acc[j].x);
            acc[j].y = fmaf(g.x, ss, acc[j].y);
            acc[j].y = fmaf(g.y, cc, acc[j].y);
        }
    }
    #pragma unroll
    for (int j = 0; j < 8; j++)
        Rout[(((size_t)(b*64 + u)*NZ + Z0 + j)*KM + kc)*C + o] = acc[j];
}
__global__ void __launch_bounds__(320) k_invZ2() {
    int w = threadIdx.x >> 5, o = threadIdx.x & 31;
    int u = blockIdx.x * 2 + (w / 5);
    int slot = w % 5;
    int kc = blockIdx.y;
    int bz = blockIdx.z;
    int branch = (bz >= NB);
    int b = bz & (NB - 1);
    const float2* Fb = branch ? g_Fyz : g_F;
    float2* Rout = branch ? g_R3 : g_R;
    switch (slot) {
        case 0: invZ_body<0 >(Fb, Rout, b, kc, u, o); break;
        case 1: invZ_body<8 >(Fb, Rout, b, kc, u, o); break;
        case 2: invZ_body<16>(Fb, Rout, b, kc, u, o); break;
        case 3: invZ_body<24>(Fb, Rout, b, kc, u, o); break;
        default: invZ_body<32>(Fb, Rout, b, kc, u, o); break;
    }
}

// ================= inverse over y real axis (32 modes -> 64 y), xy ==========
template<int Y0>
__device__ __forceinline__ void invY_body(int b, int kx, int z, int o) {
    float2 acc[8];
    #pragma unroll
    for (int j = 0; j < 8; j++) acc[j] = make_float2(0.f, 0.f);
    #pragma unroll
    for (int ky = 0; ky < KYM; ky++) {
        float2 g = g_Fxy[((size_t)(kx*KYM + ky)*(NB*NZ) + b*NZ + z)*C + o];
        #pragma unroll
        for (int j = 0; j < 8; j++) {
            float cc = IY.c[ky][Y0+j], ss = IY.s[ky][Y0+j];
            acc[j].x = fmaf(g.x, cc, acc[j].x);
            acc[j].x = fmaf(g.y, -ss, acc[j].x);
            acc[j].y = fmaf(g.x, ss, acc[j].y);
            acc[j].y = fmaf(g.y, cc, acc[j].y);
        }
    }
    #pragma unroll
    for (int j = 0; j < 8; j++)
        g_R2[(((size_t)(b*NZ + z)*NY + Y0 + j)*KM + kx)*C + o] = acc[j];
}
__global__ void __launch_bounds__(512) k_invY() {
    int w = threadIdx.x >> 5, o = threadIdx.x & 31;
    int z = blockIdx.x * 2 + (w >> 3);
    int slot = w & 7;
    int kx = blockIdx.y, b = blockIdx.z;
    switch (slot) {
        case 0: invY_body<0 >(b, kx, z, o); break;
        case 1: invY_body<8 >(b, kx, z, o); break;
        case 2: invY_body<16>(b, kx, z, o); break;
        case 3: invY_body<24>(b, kx, z, o); break;
        case 4: invY_body<32>(b, kx, z, o); break;
        case 5: invY_body<40>(b, kx, z, o); break;
        case 6: invY_body<48>(b, kx, z, o); break;
        default: invY_body<56>(b, kx, z, o); break;
    }
}

// ====== fused inverse-x for xz + xy: acc = sum_k (R_A[k]+R_B[k])·IX[k][x] ===
template<int N0>
__device__ __forceinline__ void invAccXX_body(size_t rrowA, size_t rrowB,
                                              size_t obase, int o) {
    float2 s[KM];
    #pragma unroll
    for (int k = 0; k < KM; k++) {
        float2 a = g_R [rrowA*(KM*C) + (size_t)k*C + o];
        float2 b = g_R2[rrowB*(KM*C) + (size_t)k*C + o];
        s[k] = make_float2(a.x + b.x, a.y + b.y);
    }
    float acc[8];
    #pragma unroll
    for (int j = 0; j < 8; j++) acc[j] = 0.f;
    #pragma unroll
    for (int k = 0; k < KM; k++) {
        #pragma unroll
        for (int j = 0; j < 8; j++) {
            acc[j] = fmaf(s[k].x, IX.c[k][N0+j], acc[j]);
            acc[j] = fmaf(s[k].y, -IX.s[k][N0+j], acc[j]);
        }
    }
    #pragma unroll
    for (int j = 0; j < 8; j++)
        g_acc[obase + (size_t)(N0+j)*(NY*NZ*C) + o] = acc[j];
}
__global__ void __launch_bounds__(512) k_invAccXX() {
    int w = threadIdx.x >> 5, o = threadIdx.x & 31;
    int r = w >> 3, slot = w & 7;
    int b = blockIdx.z;
    int z = blockIdx.x, y = blockIdx.y*2 + r;
    size_t rrowA = ((size_t)(b*NY + y))*NZ + z;
    size_t rrowB = ((size_t)(b*NZ + z))*NY + y;
    size_t obase = (((size_t)b*NX*NY + y)*NZ + z)*C;
    switch (slot) {
        case 0: invAccXX_body<0 >(rrowA, rrowB, obase, o); break;
        case 1: invAccXX_body<8 >(rrowA, rrowB, obase, o); break;
        case 2: invAccXX_body<16>(rrowA, rrowB, obase, o); break;
        case 3: invAccXX_body<24>(rrowA, rrowB, obase, o); break;
        case 4: invAccXX_body<32>(rrowA, rrowB, obase, o); break;
        case 5: invAccXX_body<40>(rrowA, rrowB, obase, o); break;
        case 6: invAccXX_body<48>(rrowA, rrowB, obase, o); break;
        default: invAccXX_body<56>(rrowA, rrowB, obase, o); break;
    }
}

// ================= yz inverse over y (16 modes -> 64), Re(), += =============
template<int N0>
__device__ __forceinline__ void invAccYZ_body(size_t rrow, size_t obase, int o) {
    float acc[8];
    #pragma unroll
    for (int j = 0; j < 8; j++) acc[j] = 0.f;
    #pragma unroll
    for (int k = 0; k < KM; k++) {
        float2 r = g_R3[rrow*(KM*C) + (size_t)k*C + o];
        #pragma unroll
        for (int j = 0; j < 8; j++) {
            acc[j] = fmaf(r.x, IX.c[k][N0+j], acc[j]);
            acc[j] = fmaf(r.y, -IX.s[k][N0+j], acc[j]);
        }
    }
    #pragma unroll
    for (int j = 0; j < 8; j++)
        g_acc[obase + (size_t)(N0+j)*(NZ*C) + o] += acc[j];
}
__global__ void __launch_bounds__(512) k_invAccYZ() {
    int w = threadIdx.x >> 5, o = threadIdx.x & 31;
    int r = w >> 3, slot = w & 7;
    int b = blockIdx.z;
    int z = blockIdx.x, xx = blockIdx.y*2 + r;
    size_t rrow = ((size_t)(b*NX + xx))*NZ + z;
    size_t obase = (((size_t)(b*NX + xx)*NY)*NZ + z)*C;
    switch (slot) {
        case 0: invAccYZ_body<0 >(rrow, obase, o); break;
        case 1: invAccYZ_body<8 >(rrow, obase, o); break;
        case 2: invAccYZ_body<16>(rrow, obase, o); break;
        case 3: invAccYZ_body<24>(rrow, obase, o); break;
        case 4: invAccYZ_body<32>(rrow, obase, o); break;
        case 5: invAccYZ_body<40>(rrow, obase, o); break;
        case 6: invAccYZ_body<48>(rrow, obase, o); break;
        default: invAccYZ_body<56>(rrow, obase, o); break;
    }
}

// ==== feedforward + fused conv — packed f32x2 along reduction dim ===========
__global__ void __launch_bounds__(256) k_ff4(const float* __restrict__ x,
                                             const float* __restrict__ wc_,
                                             const float* __restrict__ bc_,
                                             const float* __restrict__ w0,
                                             const float* __restrict__ b0,
                                             const float* __restrict__ w1,
                                             const float* __restrict__ b1,
                                             float* __restrict__ out) {
    __shared__ __align__(16) u64t wcp [16*32];
    __shared__ __align__(16) u64t w0pa[16*32];
    __shared__ __align__(16) u64t w0pb[16*32];
    __shared__ __align__(16) u64t w1p [32*32];
    __shared__ float bcs[C], b0s[64], b1s[C];
    __shared__ __align__(16) float xs[8][8][C];
    __shared__ __align__(16) float h1s[8][8][64];
    int tid = threadIdx.x;
    const float2* wc2 = (const float2*)wc_;
    const float2* w02 = (const float2*)w0;
    const float2* w12 = (const float2*)w1;
    for (int t = tid; t < 16*32; t += 256) {
        int i2 = t >> 5, o = t & 31;
        wcp [t] = pkf2(wc2[o*16 + i2]);
        w0pa[t] = pkf2(w02[o*16 + i2]);
        w0pb[t] = pkf2(w02[(o + 32)*16 + i2]);
    }
    for (int t = tid; t < 32*32; t += 256) {
        int h2 = t >> 5, o = t & 31;
        w1p[t] = pkf2(w12[o*32 + h2]);
    }
    if (tid < C)  bcs[tid] = bc_[tid];
    if (tid < 64) b0s[tid] = b0[tid];
    if (tid < C)  b1s[tid] = b1[tid];
    __syncthreads();
    int lane = tid & 31, w = tid >> 5;
    size_t t0 = ((size_t)blockIdx.x * 8 + w) * 32;
    for (int g = 0; g < 4; g++) {
        size_t tb = t0 + g * 8;
        float ga[8];
        #pragma unroll
        for (int r = 0; r < 8; r++) {
            xs[w][r][lane] = x[(tb + r)*C + lane];
            ga[r] = g_acc[(tb + r)*C + lane];
        }
        __syncwarp();
        u64t pc[8];
        #pragma unroll
        for (int r = 0; r < 8; r++) pc[r] = 0ull;
        #pragma unroll
        for (int i2 = 0; i2 < 16; i2 += 2) {
            u64t wv0 = wcp[i2*32 + lane], wv1 = wcp[(i2+1)*32 + lane];
            #pragma unroll
            for (int r = 0; r < 8; r++) {
                ulonglong2 a2 = *reinterpret_cast<const ulonglong2*>(&xs[w][r][i2*2]);
                pc[r] = ffma2(a2.x, wv0, pc[r]);
                pc[r] = ffma2(a2.y, wv1, pc[r]);
            }
        }
        float hv[8];
        #pragma unroll
        for (int r = 0; r < 8; r++) {
            float2 p = upk(pc[r]);
            hv[r] = ga[r] + bcs[lane] + p.x + p.y;
        }
        __syncwarp();
        #pragma unroll
        for (int r = 0; r < 8; r++) xs[w][r][lane] = hv[r];
        __syncwarp();
        u64t pa[8], pb[8];
        #pragma unroll
        for (int r = 0; r < 8; r++) { pa[r] = 0ull; pb[r] = 0ull; }
        #pragma unroll
        for (int i2 = 0; i2 < 16; i2 += 2) {
            u64t wa0 = w0pa[i2*32 + lane], wa1 = w0pa[(i2+1)*32 + lane];
            u64t wb0 = w0pb[i2*32 + lane], wb1 = w0pb[(i2+1)*32 + lane];
            #pragma unroll
            for (int r = 0; r < 8; r++) {
                ulonglong2 a2 = *reinterpret_cast<const ulonglong2*>(&xs[w][r][i2*2]);
                pa[r] = ffma2(a2.x, wa0, pa[r]);
                pa[r] = ffma2(a2.y, wa1, pa[r]);
                pb[r] = ffma2(a2.x, wb0, pb[r]);
                pb[r] = ffma2(a2.y, wb1, pb[r]);
            }
        }
        #pragma unroll
        for (int r = 0; r < 8; r++) {
            float2 qa = upk(pa[r]), qb = upk(pb[r]);
            h1s[w][r][lane]      = fmaxf(b0s[lane]      + qa.x + qa.y, 0.f);
            h1s[w][r][lane + 32] = fmaxf(b0s[lane + 32] + qb.x + qb.y, 0.f);
        }
        __syncwarp();
        u64t pv[8];
        #pragma unroll
        for (int r = 0; r < 8; r++) pv[r] = 0ull;
        #pragma unroll
        for (int h2 = 0; h2 < 32; h2 += 2) {
            u64t wv0 = w1p[h2*32 + lane], wv1 = w1p[(h2+1)*32 + lane];
            #pragma unroll
            for (int r = 0; r < 8; r++) {
                ulonglong2 a2 = *reinterpret_cast<const ulonglong2*>(&h1s[w][r][h2*2]);
                pv[r] = ffma2(a2.x, wv0, pv[r]);
                pv[r] = ffma2(a2.y, wv1, pv[r]);
            }
        }
        #pragma unroll
        for (int r = 0; r < 8; r++) {
            float2 p = upk(pv[r]);
            out[(tb + r)*C + lane] = b1s[lane] + p.x + p.y;
        }
        __syncwarp();
    }
}

extern "C" void kernel_launch(void* const* d_in, const int* in_sizes, int n_in,
                              void* d_out, int out_size) {
    const float* x      = (const float*)d_in[0];
    const float* w      = (const float*)d_in[1];
    const float* wb     = (const float*)d_in[2];
    const float* fw_xy  = (const float*)d_in[3];
    const float* fw_yz  = (const float*)d_in[4];
    const float* fw_xz  = (const float*)d_in[5];
    const float* fw2_xy = (const float*)d_in[6];
    const float* fw2_yz = (const float*)d_in[7];
    const float* fw2_xz = (const float*)d_in[8];
    const float* ffw0   = (const float*)d_in[9];
    const float* ffb0   = (const float*)d_in[10];
    const float* ffw1   = (const float*)d_in[11];
    const float* ffb1   = (const float*)d_in[12];
    float* out = (float*)d_out;

    // ---- forwards ----
    k_fftx16  <<<dim3(5, NY, NB), 256>>>(x);
    k_rfftz   <<<dim3(8, NX, NB), 256>>>(x);
    k_zfftQ16 <<<dim3(8, KM, NB), 256>>>();
    k_yfftQ16h<<<dim3(5, KM, 2*NB), 256>>>();
    k_yfftP16 <<<dim3(2, NX, NB), 256>>>();

    // ---- mixes ----
    k_mixZZ<<<dim3(512, 8), 1024>>>(fw_xz, fw2_xz, fw_yz, fw2_yz);
    k_mixXY<<<dim3(512, 5), 1024>>>(fw_xy, fw2_xy);

    // ---- inverses ----
    k_invZ2<<<dim3(32, KM, 2*NB), 320>>>();
    k_invY <<<dim3(20, KM, NB), 512>>>();
    k_invAccXX<<<dim3(NZ, NY/2, NB), 512>>>();
    k_invAccYZ<<<dim3(NZ, NX/2, NB), 512>>>();

    // ---- feedforward (fused 1x1 conv + 2-layer MLP, f32x2) ----
    k_ff4<<<2560, 256>>>(x, w, wb, ffw0, ffb0, ffw1, ffb1, out);
}